// round 3
// baseline (speedup 1.0000x reference)
#include <cuda_runtime.h>
#include <math.h>
#include <stdint.h>

#define NN   50000
#define NE   262144
#define NOCP 32768
#define EA   (NE - NOCP)      // 229376
#define NG   64
#define HD   128

// ---------------- scratch (device globals; allocation-free kernel_launch) ----
__device__ float g_S   [NN * HD];
__device__ float g_Mm  [NN * HD];
__device__ float g_aggF[NN * HD];
__device__ float g_aggO[NN * HD];
__device__ float g_D   [NN * HD];
__device__ float g_P   [(size_t)NN * 512];
__device__ float g_Q   [(size_t)NN * 512];
__device__ float g_A1  [(size_t)EA * 512];
__device__ float g_A2  [(size_t)EA * 256];
__device__ float g_sel [EA];
__device__ float g_ex  [EA];
__device__ int   g_seg [EA];
__device__ int   g_lbl [EA];
__device__ float g_Wc  [256 * 128];
__device__ float g_bc  [128];
__device__ int   g_mx  [NG];
__device__ float g_sum [NG];
__device__ int   g_pm  [NG];
__device__ int   g_added[NG];

// ---------------- init ------------------------------------------------------
__global__ void k_init() {
    size_t i = (size_t)blockIdx.x * blockDim.x + threadIdx.x;
    if (i < (size_t)NN * HD) { g_aggF[i] = 0.f; g_aggO[i] = 0.f; }
    if (blockIdx.x == 0 && threadIdx.x < NG) {
        g_mx[threadIdx.x]    = (int)0xFF800000;
        g_sum[threadIdx.x]   = 0.f;
        g_pm[threadIdx.x]    = 0;
        g_added[threadIdx.x] = EA;
    }
}

// ---------------- Wc = Wr3 @ Wp1, bc = br3 @ Wp1 + bp1 -----------------------
__global__ void k_wc(const float* __restrict__ Wr3, const float* __restrict__ br3,
                     const float* __restrict__ Wp1, const float* __restrict__ bp1) {
    int t = blockIdx.x * blockDim.x + threadIdx.x;
    if (t >= 256 * 128) return;
    int k = t >> 7, c = t & 127;
    float s = 0.f;
    #pragma unroll 8
    for (int m = 0; m < 128; m++) s += Wr3[k * 128 + m] * Wp1[m * 128 + c];
    g_Wc[t] = s;
    if (t < 128) {
        float b = bp1[t];
        #pragma unroll 8
        for (int m = 0; m < 128; m++) b += br3[m] * Wp1[m * 128 + t];
        g_bc[t] = b;
    }
}

// ---------------- per-edge segment / label precompute ------------------------
__global__ void k_seg(const int* __restrict__ ei, const int* __restrict__ bv,
                      const int* __restrict__ y) {
    int e = blockIdx.x * blockDim.x + threadIdx.x;
    if (e >= EA) return;
    int s = __ldg(&ei[NOCP + e]);
    int g = __ldg(&bv[s]);
    g_seg[e] = g;
    g_lbl[e] = __ldg(&y[g]);
}

// =============================================================================
//                 TF32x3 tensor-core GEMM (mma.sync m16n8k8)
// C = op(A@B + bias); 128x128 block tile, K-step 16, 256 thr, 8 warps (64x32).
// Split: a = a_hi + a_lo (hi = fp32 truncated to tf32); acc += hi*hi+hi*lo+lo*hi.
// Requires K%16==0, N%128==0 (grid.x = N/128); M arbitrary (guarded).
// =============================================================================
#define MMA_TF32(d, a, b)                                                     \
    asm volatile(                                                             \
        "mma.sync.aligned.m16n8k8.row.col.f32.tf32.tf32.f32 "                 \
        "{%0,%1,%2,%3}, {%4,%5,%6,%7}, {%8,%9}, {%0,%1,%2,%3};\n"             \
        : "+f"((d)[0]), "+f"((d)[1]), "+f"((d)[2]), "+f"((d)[3])              \
        : "r"((a)[0]), "r"((a)[1]), "r"((a)[2]), "r"((a)[3]),                 \
          "r"((b)[0]), "r"((b)[1]))

__device__ __forceinline__ void split_tf32(float v, float& h, float& l) {
    h = __uint_as_float(__float_as_uint(v) & 0xFFFFE000u);
    l = v - h;
}

#define APAD 20
#define BPAD 136

template <bool ELU, bool HASBIAS>
__global__ void __launch_bounds__(256)
tgemm(const float* __restrict__ A, const float* __restrict__ B,
      const float* __restrict__ bias, float* __restrict__ C,
      int M, int N, int K) {
    __shared__ float Ah[128][APAD], Al[128][APAD];
    __shared__ float Bh[16][BPAD],  Bl[16][BPAD];

    const int tid = threadIdx.x;
    const int bm = blockIdx.y * 128;
    const int bn = blockIdx.x * 128;

    const int wid = tid >> 5, lane = tid & 31;
    const int gid = lane >> 2, tg = lane & 3;
    const int wm = (wid >> 2) * 64, wn = (wid & 3) * 32;

    // loader geometry
    const int arow = tid >> 1,  acq = (tid & 1) * 8;     // A: row, col-quad base
    const int brow = tid >> 4,  bcq = (tid & 15) * 8;    // B: k-row, col-quad base

    float4 pa0, pa1, pb0, pb1;
    auto loadG = [&](int k0) {
        int gr = bm + arow;
        if (gr < M) {
            pa0 = *(const float4*)&A[(size_t)gr * K + k0 + acq];
            pa1 = *(const float4*)&A[(size_t)gr * K + k0 + acq + 4];
        } else {
            pa0 = make_float4(0.f,0.f,0.f,0.f); pa1 = pa0;
        }
        pb0 = *(const float4*)&B[(size_t)(k0 + brow) * N + bn + bcq];
        pb1 = *(const float4*)&B[(size_t)(k0 + brow) * N + bn + bcq + 4];
    };
    auto storeS = [&]() {
        float h, l;
        split_tf32(pa0.x, h, l); Ah[arow][acq+0] = h; Al[arow][acq+0] = l;
        split_tf32(pa0.y, h, l); Ah[arow][acq+1] = h; Al[arow][acq+1] = l;
        split_tf32(pa0.z, h, l); Ah[arow][acq+2] = h; Al[arow][acq+2] = l;
        split_tf32(pa0.w, h, l); Ah[arow][acq+3] = h; Al[arow][acq+3] = l;
        split_tf32(pa1.x, h, l); Ah[arow][acq+4] = h; Al[arow][acq+4] = l;
        split_tf32(pa1.y, h, l); Ah[arow][acq+5] = h; Al[arow][acq+5] = l;
        split_tf32(pa1.z, h, l); Ah[arow][acq+6] = h; Al[arow][acq+6] = l;
        split_tf32(pa1.w, h, l); Ah[arow][acq+7] = h; Al[arow][acq+7] = l;
        split_tf32(pb0.x, h, l); Bh[brow][bcq+0] = h; Bl[brow][bcq+0] = l;
        split_tf32(pb0.y, h, l); Bh[brow][bcq+1] = h; Bl[brow][bcq+1] = l;
        split_tf32(pb0.z, h, l); Bh[brow][bcq+2] = h; Bl[brow][bcq+2] = l;
        split_tf32(pb0.w, h, l); Bh[brow][bcq+3] = h; Bl[brow][bcq+3] = l;
        split_tf32(pb1.x, h, l); Bh[brow][bcq+4] = h; Bl[brow][bcq+4] = l;
        split_tf32(pb1.y, h, l); Bh[brow][bcq+5] = h; Bl[brow][bcq+5] = l;
        split_tf32(pb1.z, h, l); Bh[brow][bcq+6] = h; Bl[brow][bcq+6] = l;
        split_tf32(pb1.w, h, l); Bh[brow][bcq+7] = h; Bl[brow][bcq+7] = l;
    };

    float acc[4][4][4];
    #pragma unroll
    for (int i = 0; i < 4; i++)
        #pragma unroll
        for (int j = 0; j < 4; j++)
            #pragma unroll
            for (int r = 0; r < 4; r++) acc[i][j][r] = 0.f;

    loadG(0); storeS(); __syncthreads();

    const int ntiles = K >> 4;
    for (int t = 0; t < ntiles; t++) {
        if (t + 1 < ntiles) loadG((t + 1) << 4);

        #pragma unroll
        for (int ks = 0; ks < 2; ks++) {
            uint32_t ahf[4][4], alf[4][4], bhf[4][2], blf[4][2];
            #pragma unroll
            for (int mt = 0; mt < 4; mt++) {
                int r0 = wm + mt * 16 + gid;
                int c0 = ks * 8 + tg;
                ahf[mt][0] = __float_as_uint(Ah[r0    ][c0    ]);
                ahf[mt][1] = __float_as_uint(Ah[r0 + 8][c0    ]);
                ahf[mt][2] = __float_as_uint(Ah[r0    ][c0 + 4]);
                ahf[mt][3] = __float_as_uint(Ah[r0 + 8][c0 + 4]);
                alf[mt][0] = __float_as_uint(Al[r0    ][c0    ]);
                alf[mt][1] = __float_as_uint(Al[r0 + 8][c0    ]);
                alf[mt][2] = __float_as_uint(Al[r0    ][c0 + 4]);
                alf[mt][3] = __float_as_uint(Al[r0 + 8][c0 + 4]);
            }
            #pragma unroll
            for (int nt = 0; nt < 4; nt++) {
                int c = wn + nt * 8 + gid;
                bhf[nt][0] = __float_as_uint(Bh[ks * 8 + tg    ][c]);
                bhf[nt][1] = __float_as_uint(Bh[ks * 8 + tg + 4][c]);
                blf[nt][0] = __float_as_uint(Bl[ks * 8 + tg    ][c]);
                blf[nt][1] = __float_as_uint(Bl[ks * 8 + tg + 4][c]);
            }
            #pragma unroll
            for (int mt = 0; mt < 4; mt++)
                #pragma unroll
                for (int nt = 0; nt < 4; nt++) {
                    MMA_TF32(acc[mt][nt], ahf[mt], bhf[nt]);
                    MMA_TF32(acc[mt][nt], ahf[mt], blf[nt]);
                    MMA_TF32(acc[mt][nt], alf[mt], bhf[nt]);
                }
        }
        __syncthreads();
        if (t + 1 < ntiles) { storeS(); __syncthreads(); }
    }

    // epilogue
    #pragma unroll
    for (int mt = 0; mt < 4; mt++) {
        int r0 = bm + wm + mt * 16 + gid;
        #pragma unroll
        for (int nt = 0; nt < 4; nt++) {
            int c = bn + wn + nt * 8 + tg * 2;
            float b0 = HASBIAS ? __ldg(&bias[c])     : 0.f;
            float b1 = HASBIAS ? __ldg(&bias[c + 1]) : 0.f;
            if (r0 < M) {
                float v0 = acc[mt][nt][0] + b0, v1 = acc[mt][nt][1] + b1;
                if (ELU) { v0 = (v0 > 0.f) ? v0 : expm1f(v0); v1 = (v1 > 0.f) ? v1 : expm1f(v1); }
                *(float2*)&C[(size_t)r0 * N + c] = make_float2(v0, v1);
            }
            if (r0 + 8 < M) {
                float v2 = acc[mt][nt][2] + b0, v3 = acc[mt][nt][3] + b1;
                if (ELU) { v2 = (v2 > 0.f) ? v2 : expm1f(v2); v3 = (v3 > 0.f) ? v3 : expm1f(v3); }
                *(float2*)&C[(size_t)(r0 + 8) * N + c] = make_float2(v2, v3);
            }
        }
    }
}

// ===== GEMM3 fused with sel: sel[e] = elu(A2@Wc + bc) . Wp2[:,lbl] + bp2 =====
// A = A2 (EA x 256), B = Wc (256x128); grid = (1, EA/128); N=128, K=256.
__global__ void __launch_bounds__(256)
gemm3_sel(const float* __restrict__ A, const float* __restrict__ B,
          const float* __restrict__ bcp, const float* __restrict__ Wp2,
          const float* __restrict__ bp2) {
    __shared__ float Ah[128][APAD], Al[128][APAD];
    __shared__ float Bh[16][BPAD],  Bl[16][BPAD];
    __shared__ float sW[128 * 10];
    __shared__ float sbc[128];
    __shared__ float red[128][5];

    const int tid = threadIdx.x;
    const int bm = blockIdx.y * 128;
    const int K = 256, N = 128;

    const int wid = tid >> 5, lane = tid & 31;
    const int gid = lane >> 2, tg = lane & 3;
    const int wm = (wid >> 2) * 64, wn = (wid & 3) * 32;

    for (int i = tid; i < 128 * 10; i += 256) sW[i] = Wp2[i];
    if (tid < 128) sbc[tid] = bcp[tid];

    const int arow = tid >> 1,  acq = (tid & 1) * 8;
    const int brow = tid >> 4,  bcq = (tid & 15) * 8;

    float4 pa0, pa1, pb0, pb1;
    auto loadG = [&](int k0) {
        int gr = bm + arow;
        pa0 = *(const float4*)&A[(size_t)gr * K + k0 + acq];
        pa1 = *(const float4*)&A[(size_t)gr * K + k0 + acq + 4];
        pb0 = *(const float4*)&B[(size_t)(k0 + brow) * N + bcq];
        pb1 = *(const float4*)&B[(size_t)(k0 + brow) * N + bcq + 4];
    };
    auto storeS = [&]() {
        float h, l;
        split_tf32(pa0.x, h, l); Ah[arow][acq+0] = h; Al[arow][acq+0] = l;
        split_tf32(pa0.y, h, l); Ah[arow][acq+1] = h; Al[arow][acq+1] = l;
        split_tf32(pa0.z, h, l); Ah[arow][acq+2] = h; Al[arow][acq+2] = l;
        split_tf32(pa0.w, h, l); Ah[arow][acq+3] = h; Al[arow][acq+3] = l;
        split_tf32(pa1.x, h, l); Ah[arow][acq+4] = h; Al[arow][acq+4] = l;
        split_tf32(pa1.y, h, l); Ah[arow][acq+5] = h; Al[arow][acq+5] = l;
        split_tf32(pa1.z, h, l); Ah[arow][acq+6] = h; Al[arow][acq+6] = l;
        split_tf32(pa1.w, h, l); Ah[arow][acq+7] = h; Al[arow][acq+7] = l;
        split_tf32(pb0.x, h, l); Bh[brow][bcq+0] = h; Bl[brow][bcq+0] = l;
        split_tf32(pb0.y, h, l); Bh[brow][bcq+1] = h; Bl[brow][bcq+1] = l;
        split_tf32(pb0.z, h, l); Bh[brow][bcq+2] = h; Bl[brow][bcq+2] = l;
        split_tf32(pb0.w, h, l); Bh[brow][bcq+3] = h; Bl[brow][bcq+3] = l;
        split_tf32(pb1.x, h, l); Bh[brow][bcq+4] = h; Bl[brow][bcq+4] = l;
        split_tf32(pb1.y, h, l); Bh[brow][bcq+5] = h; Bl[brow][bcq+5] = l;
        split_tf32(pb1.z, h, l); Bh[brow][bcq+6] = h; Bl[brow][bcq+6] = l;
        split_tf32(pb1.w, h, l); Bh[brow][bcq+7] = h; Bl[brow][bcq+7] = l;
    };

    float acc[4][4][4];
    #pragma unroll
    for (int i = 0; i < 4; i++)
        #pragma unroll
        for (int j = 0; j < 4; j++)
            #pragma unroll
            for (int r = 0; r < 4; r++) acc[i][j][r] = 0.f;

    loadG(0); storeS(); __syncthreads();

    const int ntiles = K >> 4;   // 16
    for (int t = 0; t < ntiles; t++) {
        if (t + 1 < ntiles) loadG((t + 1) << 4);
        #pragma unroll
        for (int ks = 0; ks < 2; ks++) {
            uint32_t ahf[4][4], alf[4][4], bhf[4][2], blf[4][2];
            #pragma unroll
            for (int mt = 0; mt < 4; mt++) {
                int r0 = wm + mt * 16 + gid;
                int c0 = ks * 8 + tg;
                ahf[mt][0] = __float_as_uint(Ah[r0    ][c0    ]);
                ahf[mt][1] = __float_as_uint(Ah[r0 + 8][c0    ]);
                ahf[mt][2] = __float_as_uint(Ah[r0    ][c0 + 4]);
                ahf[mt][3] = __float_as_uint(Ah[r0 + 8][c0 + 4]);
                alf[mt][0] = __float_as_uint(Al[r0    ][c0    ]);
                alf[mt][1] = __float_as_uint(Al[r0 + 8][c0    ]);
                alf[mt][2] = __float_as_uint(Al[r0    ][c0 + 4]);
                alf[mt][3] = __float_as_uint(Al[r0 + 8][c0 + 4]);
            }
            #pragma unroll
            for (int nt = 0; nt < 4; nt++) {
                int c = wn + nt * 8 + gid;
                bhf[nt][0] = __float_as_uint(Bh[ks * 8 + tg    ][c]);
                bhf[nt][1] = __float_as_uint(Bh[ks * 8 + tg + 4][c]);
                blf[nt][0] = __float_as_uint(Bl[ks * 8 + tg    ][c]);
                blf[nt][1] = __float_as_uint(Bl[ks * 8 + tg + 4][c]);
            }
            #pragma unroll
            for (int mt = 0; mt < 4; mt++)
                #pragma unroll
                for (int nt = 0; nt < 4; nt++) {
                    MMA_TF32(acc[mt][nt], ahf[mt], bhf[nt]);
                    MMA_TF32(acc[mt][nt], ahf[mt], blf[nt]);
                    MMA_TF32(acc[mt][nt], alf[mt], bhf[nt]);
                }
        }
        __syncthreads();
        if (t + 1 < ntiles) { storeS(); __syncthreads(); }
    }

    // fused epilogue: per-row elu + dot with Wp2[:, lbl(row)]
    #pragma unroll
    for (int mt = 0; mt < 4; mt++) {
        #pragma unroll
        for (int half = 0; half < 2; half++) {
            int row = wm + mt * 16 + gid + half * 8;
            int lbl = g_lbl[bm + row];
            float p = 0.f;
            #pragma unroll
            for (int nt = 0; nt < 4; nt++) {
                int c = wn + nt * 8 + tg * 2;
                float v0 = acc[mt][nt][half * 2 + 0] + sbc[c];
                float v1 = acc[mt][nt][half * 2 + 1] + sbc[c + 1];
                float h0 = (v0 > 0.f) ? v0 : expm1f(v0);
                float h1 = (v1 > 0.f) ? v1 : expm1f(v1);
                p += h0 * sW[c * 10 + lbl] + h1 * sW[(c + 1) * 10 + lbl];
            }
            p += __shfl_xor_sync(0xffffffffu, p, 1);
            p += __shfl_xor_sync(0xffffffffu, p, 2);
            if (tg == 0) red[row][wid & 3] = p;
        }
    }
    __syncthreads();
    if (tid < 128) {
        float s = red[tid][0] + red[tid][1] + red[tid][2] + red[tid][3];
        g_sel[bm + tid] = s + __ldg(&bp2[g_lbl[bm + tid]]);
    }
}

// ---------------- edge scatter-add -------------------------------------------
__global__ void k_scatter(const int* __restrict__ ei) {
    long long t = (long long)blockIdx.x * blockDim.x + threadIdx.x;
    if (t >= (long long)NE * HD) return;
    int e = (int)(t >> 7), f = (int)(t & 127);
    int s = __ldg(&ei[e]);
    int d = __ldg(&ei[NE + e]);
    float v = g_Mm[(size_t)s * HD + f];
    atomicAdd(&g_aggF[(size_t)d * HD + f], v);
    if (e < NOCP) atomicAdd(&g_aggO[(size_t)d * HD + f], v);
}

// ---------------- D = elu(S+aggF+b) - elu(S+aggO+b) --------------------------
__global__ void k_D(const float* __restrict__ bg) {
    size_t i = (size_t)blockIdx.x * blockDim.x + threadIdx.x;
    if (i >= (size_t)NN * HD) return;
    int f = (int)(i & 127);
    float base = g_S[i] + bg[f];
    float xf = base + g_aggF[i];
    float xo = base + g_aggO[i];
    float rf = (xf > 0.f) ? xf : expm1f(xf);
    float ro = (xo > 0.f) ? xo : expm1f(xo);
    g_D[i] = rf - ro;
}

// ---------------- A1 = elu(P[src] + Q[dst] + br1) ----------------------------
__global__ void k_A1(const int* __restrict__ ei, const float* __restrict__ br1) {
    size_t t = (size_t)blockIdx.x * blockDim.x + threadIdx.x;
    if (t >= (size_t)EA * 128) return;
    int e  = (int)(t >> 7), kq = (int)(t & 127);
    int src = __ldg(&ei[NOCP + e]);
    int dst = __ldg(&ei[NE + NOCP + e]);
    float4 p = *(const float4*)&g_P[(size_t)src * 512 + kq * 4];
    float4 q = *(const float4*)&g_Q[(size_t)dst * 512 + kq * 4];
    float4 b = *(const float4*)&br1[kq * 4];
    float4 r;
    float vx = p.x + q.x + b.x; r.x = (vx > 0.f) ? vx : expm1f(vx);
    float vy = p.y + q.y + b.y; r.y = (vy > 0.f) ? vy : expm1f(vy);
    float vz = p.z + q.z + b.z; r.z = (vz > 0.f) ? vz : expm1f(vz);
    float vw = p.w + q.w + b.w; r.w = (vw > 0.f) ? vw : expm1f(vw);
    *(float4*)&g_A1[t * 4] = r;
}

// ---------------- segment reductions -----------------------------------------
__device__ __forceinline__ void atomMaxF(int* a, float v) {
    int iv = __float_as_int(v);
    if (iv >= 0) atomicMax(a, iv);
    else         atomicMin((unsigned int*)a, (unsigned int)iv);
}

__global__ void k_mx() {
    __shared__ int sm[NG];
    int tid = threadIdx.x;
    if (tid < NG) sm[tid] = (int)0xFF800000;
    __syncthreads();
    int e = blockIdx.x * blockDim.x + tid;
    if (e < EA) atomMaxF(&sm[g_seg[e]], g_sel[e]);
    __syncthreads();
    if (tid < NG) atomMaxF(&g_mx[tid], __int_as_float(sm[tid]));
}

__global__ void k_ex() {
    __shared__ float ss[NG];
    int tid = threadIdx.x;
    if (tid < NG) ss[tid] = 0.f;
    __syncthreads();
    int e = blockIdx.x * blockDim.x + tid;
    if (e < EA) {
        int g = g_seg[e];
        float v = expf(g_sel[e] - __int_as_float(g_mx[g]));
        g_ex[e] = v;
        atomicAdd(&ss[g], v);
    }
    __syncthreads();
    if (tid < NG && ss[tid] != 0.f) atomicAdd(&g_sum[tid], ss[tid]);
}

__global__ void k_probs(float* __restrict__ out) {
    __shared__ int sp[NG];
    int tid = threadIdx.x;
    if (tid < NG) sp[tid] = 0;
    __syncthreads();
    int e = blockIdx.x * blockDim.x + tid;
    if (e < EA) {
        int g = g_seg[e];
        float p = g_ex[e] / g_sum[g];
        out[e] = p;
        atomicMax(&sp[g], __float_as_int(p));
    }
    __syncthreads();
    if (tid < NG) atomicMax(&g_pm[tid], sp[tid]);
}

__global__ void k_added(const float* __restrict__ out) {
    int e = blockIdx.x * blockDim.x + threadIdx.x;
    if (e >= EA) return;
    int g = g_seg[e];
    if (__float_as_int(out[e]) == g_pm[g]) atomicMin(&g_added[g], e);
}

__global__ void k_tail(float* __restrict__ out) {
    int t = threadIdx.x;
    if (t < NG) {
        out[EA + t]      = __int_as_float(g_pm[t]);
        out[EA + NG + t] = (float)g_added[t];
    }
}

// ---------------- launch ------------------------------------------------------
extern "C" void kernel_launch(void* const* d_in, const int* in_sizes, int n_in,
                              void* d_out, int out_size) {
    const int pb = n_in - 13;
    const float* x      = (const float*)d_in[0];
    const int*   ei     = (const int*)  d_in[1];
    const int*   bv     = (const int*)  d_in[2];
    const int*   y      = (const int*)  d_in[3];
    const float* W_self = (const float*)d_in[pb + 0];
    const float* W_nbr  = (const float*)d_in[pb + 1];
    const float* b_gnn  = (const float*)d_in[pb + 2];
    const float* Wr1    = (const float*)d_in[pb + 3];
    const float* br1    = (const float*)d_in[pb + 4];
    const float* Wr2    = (const float*)d_in[pb + 5];
    const float* br2    = (const float*)d_in[pb + 6];
    const float* Wr3    = (const float*)d_in[pb + 7];
    const float* br3    = (const float*)d_in[pb + 8];
    const float* Wp1    = (const float*)d_in[pb + 9];
    const float* bp1    = (const float*)d_in[pb + 10];
    const float* Wp2    = (const float*)d_in[pb + 11];
    const float* bp2    = (const float*)d_in[pb + 12];
    float* out = (float*)d_out;

    void *pS, *pM, *pP, *pQ, *pA1, *pA2, *pD, *pWc, *pbc;
    cudaGetSymbolAddress(&pS,  g_S);
    cudaGetSymbolAddress(&pM,  g_Mm);
    cudaGetSymbolAddress(&pP,  g_P);
    cudaGetSymbolAddress(&pQ,  g_Q);
    cudaGetSymbolAddress(&pA1, g_A1);
    cudaGetSymbolAddress(&pA2, g_A2);
    cudaGetSymbolAddress(&pD,  g_D);
    cudaGetSymbolAddress(&pWc, g_Wc);
    cudaGetSymbolAddress(&pbc, g_bc);

    const int T = 256;

    k_init<<<(NN * HD + T - 1) / T, T>>>();
    k_wc  <<<(256 * 128 + T - 1) / T, T>>>(Wr3, br3, Wp1, bp1);
    k_seg <<<(EA + T - 1) / T, T>>>(ei, bv, y);

    // node transform GEMMs: S = x@W_self, M = x@W_nbr (tensor cores)
    {
        dim3 grid(1, (NN + 127) / 128);
        tgemm<false, false><<<grid, T>>>(x, W_self, nullptr, (float*)pS, NN, HD, HD);
        tgemm<false, false><<<grid, T>>>(x, W_nbr,  nullptr, (float*)pM, NN, HD, HD);
    }
    k_scatter<<<(int)(((long long)NE * HD + T - 1) / T), T>>>(ei);
    k_D<<<(NN * HD + T - 1) / T, T>>>(b_gnn);

    // node-space hoist of GEMM1: P = D@Wr1[0:128,:], Q = D@Wr1[128:256,:]
    {
        dim3 grid(4, (NN + 127) / 128);
        tgemm<false, false><<<grid, T>>>((const float*)pD, Wr1,             nullptr, (float*)pP, NN, 512, HD);
        tgemm<false, false><<<grid, T>>>((const float*)pD, Wr1 + 128 * 512, nullptr, (float*)pQ, NN, 512, HD);
    }
    // A1 = elu(P[src] + Q[dst] + br1)
    k_A1<<<(int)(((size_t)EA * 128 + T - 1) / T), T>>>(ei, br1);

    // A2 = elu(A1 @ Wr2 + br2)   (tensor cores)
    tgemm<true, true><<<dim3(2, EA / 128), T>>>((const float*)pA1, Wr2, br2, (float*)pA2, EA, 256, 512);

    // fused GEMM3 + sel (tensor cores)
    gemm3_sel<<<dim3(1, EA / 128), T>>>((const float*)pA2, (const float*)pWc,
                                        (const float*)pbc, Wp2, bp2);

    // segment softmax + argmax
    const int segBlocks = (EA + T - 1) / T;
    k_mx   <<<segBlocks, T>>>();
    k_ex   <<<segBlocks, T>>>();
    k_probs<<<segBlocks, T>>>(out);
    k_added<<<segBlocks, T>>>(out);
    k_tail <<<1, 64>>>(out);
}

// round 4
// speedup vs baseline: 1.1067x; 1.1067x over previous
#include <cuda_runtime.h>
#include <math.h>
#include <stdint.h>

#define NN   50000
#define NE   262144
#define NOCP 32768
#define EA   (NE - NOCP)      // 229376
#define NG   64
#define HD   128

// ---------------- scratch (device globals; allocation-free kernel_launch) ----
__device__ float g_S   [NN * HD];
__device__ float g_Mm  [NN * HD];
__device__ float g_aggF[NN * HD];
__device__ float g_aggO[NN * HD];
__device__ float g_D   [NN * HD];
__device__ float g_P   [(size_t)NN * 512];
__device__ float g_Q   [(size_t)NN * 512];
__device__ float g_A2  [(size_t)EA * 256];
__device__ float g_sel [EA];
__device__ float g_ex  [EA];
__device__ int   g_seg [EA];
__device__ int   g_lbl [EA];
__device__ float g_Wc  [256 * 128];
__device__ float g_bc  [128];
__device__ int   g_mx  [NG];
__device__ float g_sum [NG];
__device__ int   g_pm  [NG];
__device__ int   g_added[NG];

// ---------------- init ------------------------------------------------------
__global__ void k_init() {
    size_t i = (size_t)blockIdx.x * blockDim.x + threadIdx.x;
    if (i < (size_t)NN * HD) { g_aggF[i] = 0.f; g_aggO[i] = 0.f; }
    if (blockIdx.x == 0 && threadIdx.x < NG) {
        g_mx[threadIdx.x]    = (int)0xFF800000;
        g_sum[threadIdx.x]   = 0.f;
        g_pm[threadIdx.x]    = 0;
        g_added[threadIdx.x] = EA;
    }
}

// ---------------- Wc = Wr3 @ Wp1, bc = br3 @ Wp1 + bp1 -----------------------
__global__ void k_wc(const float* __restrict__ Wr3, const float* __restrict__ br3,
                     const float* __restrict__ Wp1, const float* __restrict__ bp1) {
    int t = blockIdx.x * blockDim.x + threadIdx.x;
    if (t >= 256 * 128) return;
    int k = t >> 7, c = t & 127;
    float s = 0.f;
    #pragma unroll 8
    for (int m = 0; m < 128; m++) s += Wr3[k * 128 + m] * Wp1[m * 128 + c];
    g_Wc[t] = s;
    if (t < 128) {
        float b = bp1[t];
        #pragma unroll 8
        for (int m = 0; m < 128; m++) b += br3[m] * Wp1[m * 128 + t];
        g_bc[t] = b;
    }
}

// ---------------- per-edge segment / label precompute ------------------------
__global__ void k_seg(const int* __restrict__ ei, const int* __restrict__ bv,
                      const int* __restrict__ y) {
    int e = blockIdx.x * blockDim.x + threadIdx.x;
    if (e >= EA) return;
    int s = __ldg(&ei[NOCP + e]);
    int g = __ldg(&bv[s]);
    g_seg[e] = g;
    g_lbl[e] = __ldg(&y[g]);
}

// =============================================================================
//      TF32x3 tensor-core GEMM — raw-fp32 smem, double buffer, 1 sync/tile
// C = op(A@B + bias); 128x128 block tile, K-step 16, 256 thr, 8 warps (64x32).
// FUSEA: A row e is built on the fly as elu(P[src[e]] + Q[dst[e]] + bext).
// =============================================================================
#define MMA_TF32(d, a, b)                                                     \
    asm volatile(                                                             \
        "mma.sync.aligned.m16n8k8.row.col.f32.tf32.tf32.f32 "                 \
        "{%0,%1,%2,%3}, {%4,%5,%6,%7}, {%8,%9}, {%0,%1,%2,%3};\n"             \
        : "+f"((d)[0]), "+f"((d)[1]), "+f"((d)[2]), "+f"((d)[3])              \
        : "r"((a)[0]), "r"((a)[1]), "r"((a)[2]), "r"((a)[3]),                 \
          "r"((b)[0]), "r"((b)[1]))

__device__ __forceinline__ void split_u(float v, uint32_t& h, uint32_t& l) {
    uint32_t hb = __float_as_uint(v) & 0xFFFFE000u;
    h = hb;
    l = __float_as_uint(v - __uint_as_float(hb));
}

__device__ __forceinline__ float elu1(float v) { return (v > 0.f) ? v : expm1f(v); }

#define APAD 20
#define BPAD 136

template <bool ELU, bool HASBIAS, bool FUSEA>
__global__ void __launch_bounds__(256)
tgemm(const float* __restrict__ A, const float* __restrict__ B,
      const float* __restrict__ bias, float* __restrict__ C,
      int M, int N, int K,
      const int* __restrict__ esrc, const int* __restrict__ edst,
      const float* __restrict__ Pm, const float* __restrict__ Qm,
      const float* __restrict__ bext) {
    __shared__ float As[2][128][APAD];
    __shared__ float Bs[2][16][BPAD];

    const int tid = threadIdx.x;
    const int bm = blockIdx.y * 128;
    const int bn = blockIdx.x * 128;

    const int wid = tid >> 5, lane = tid & 31;
    const int gid = lane >> 2, tg = lane & 3;
    const int wm = (wid >> 2) * 64, wn = (wid & 3) * 32;

    const int arow = tid >> 1,  acq = (tid & 1) * 8;
    const int brow = tid >> 4,  bcq = (tid & 15) * 8;

    int src = 0, dst = 0;
    if (FUSEA) {
        src = __ldg(&esrc[bm + arow]);
        dst = __ldg(&edst[bm + arow]);
    }

    float4 pa0, pa1, pb0, pb1;
    auto loadG = [&](int k0) {
        if (FUSEA) {
            float4 p0 = *(const float4*)&Pm[(size_t)src * 512 + k0 + acq];
            float4 p1 = *(const float4*)&Pm[(size_t)src * 512 + k0 + acq + 4];
            float4 q0 = *(const float4*)&Qm[(size_t)dst * 512 + k0 + acq];
            float4 q1 = *(const float4*)&Qm[(size_t)dst * 512 + k0 + acq + 4];
            float4 b0 = *(const float4*)&bext[k0 + acq];
            float4 b1 = *(const float4*)&bext[k0 + acq + 4];
            pa0.x = elu1(p0.x + q0.x + b0.x); pa0.y = elu1(p0.y + q0.y + b0.y);
            pa0.z = elu1(p0.z + q0.z + b0.z); pa0.w = elu1(p0.w + q0.w + b0.w);
            pa1.x = elu1(p1.x + q1.x + b1.x); pa1.y = elu1(p1.y + q1.y + b1.y);
            pa1.z = elu1(p1.z + q1.z + b1.z); pa1.w = elu1(p1.w + q1.w + b1.w);
        } else {
            int gr = bm + arow;
            if (gr < M) {
                pa0 = *(const float4*)&A[(size_t)gr * K + k0 + acq];
                pa1 = *(const float4*)&A[(size_t)gr * K + k0 + acq + 4];
            } else {
                pa0 = make_float4(0.f, 0.f, 0.f, 0.f); pa1 = pa0;
            }
        }
        pb0 = *(const float4*)&B[(size_t)(k0 + brow) * N + bn + bcq];
        pb1 = *(const float4*)&B[(size_t)(k0 + brow) * N + bn + bcq + 4];
    };
    auto storeS = [&](int buf) {
        *(float4*)&As[buf][arow][acq]     = pa0;
        *(float4*)&As[buf][arow][acq + 4] = pa1;
        *(float4*)&Bs[buf][brow][bcq]     = pb0;
        *(float4*)&Bs[buf][brow][bcq + 4] = pb1;
    };

    float acc[4][4][4];
    #pragma unroll
    for (int i = 0; i < 4; i++)
        #pragma unroll
        for (int j = 0; j < 4; j++)
            #pragma unroll
            for (int r = 0; r < 4; r++) acc[i][j][r] = 0.f;

    loadG(0); storeS(0); __syncthreads();

    const int ntiles = K >> 4;
    for (int t = 0; t < ntiles; t++) {
        const int cur = t & 1;
        if (t + 1 < ntiles) loadG((t + 1) << 4);

        #pragma unroll
        for (int ks = 0; ks < 2; ks++) {
            uint32_t ahf[4][4], alf[4][4], bhf[4][2], blf[4][2];
            #pragma unroll
            for (int mt = 0; mt < 4; mt++) {
                int r0 = wm + mt * 16 + gid;
                int c0 = ks * 8 + tg;
                split_u(As[cur][r0    ][c0    ], ahf[mt][0], alf[mt][0]);
                split_u(As[cur][r0 + 8][c0    ], ahf[mt][1], alf[mt][1]);
                split_u(As[cur][r0    ][c0 + 4], ahf[mt][2], alf[mt][2]);
                split_u(As[cur][r0 + 8][c0 + 4], ahf[mt][3], alf[mt][3]);
            }
            #pragma unroll
            for (int nt = 0; nt < 4; nt++) {
                int c = wn + nt * 8 + gid;
                split_u(Bs[cur][ks * 8 + tg    ][c], bhf[nt][0], blf[nt][0]);
                split_u(Bs[cur][ks * 8 + tg + 4][c], bhf[nt][1], blf[nt][1]);
            }
            #pragma unroll
            for (int mt = 0; mt < 4; mt++)
                #pragma unroll
                for (int nt = 0; nt < 4; nt++) {
                    MMA_TF32(acc[mt][nt], ahf[mt], bhf[nt]);
                    MMA_TF32(acc[mt][nt], ahf[mt], blf[nt]);
                    MMA_TF32(acc[mt][nt], alf[mt], bhf[nt]);
                }
        }
        if (t + 1 < ntiles) { storeS(cur ^ 1); __syncthreads(); }
    }

    #pragma unroll
    for (int mt = 0; mt < 4; mt++) {
        int r0 = bm + wm + mt * 16 + gid;
        #pragma unroll
        for (int nt = 0; nt < 4; nt++) {
            int c = bn + wn + nt * 8 + tg * 2;
            float b0 = HASBIAS ? __ldg(&bias[c])     : 0.f;
            float b1 = HASBIAS ? __ldg(&bias[c + 1]) : 0.f;
            if (r0 < M) {
                float v0 = acc[mt][nt][0] + b0, v1 = acc[mt][nt][1] + b1;
                if (ELU) { v0 = elu1(v0); v1 = elu1(v1); }
                *(float2*)&C[(size_t)r0 * N + c] = make_float2(v0, v1);
            }
            if (r0 + 8 < M) {
                float v2 = acc[mt][nt][2] + b0, v3 = acc[mt][nt][3] + b1;
                if (ELU) { v2 = elu1(v2); v3 = elu1(v3); }
                *(float2*)&C[(size_t)(r0 + 8) * N + c] = make_float2(v2, v3);
            }
        }
    }
}

// ===== GEMM3 fused with sel: sel[e] = elu(A2@Wc + bc) . Wp2[:,lbl] + bp2 =====
__global__ void __launch_bounds__(256)
gemm3_sel(const float* __restrict__ A, const float* __restrict__ B,
          const float* __restrict__ bcp, const float* __restrict__ Wp2,
          const float* __restrict__ bp2) {
    __shared__ float As[2][128][APAD];
    __shared__ float Bs[2][16][BPAD];
    __shared__ float sW[128 * 10];
    __shared__ float sbc[128];
    __shared__ float red[128][5];

    const int tid = threadIdx.x;
    const int bm = blockIdx.y * 128;
    const int K = 256, N = 128;

    const int wid = tid >> 5, lane = tid & 31;
    const int gid = lane >> 2, tg = lane & 3;
    const int wm = (wid >> 2) * 64, wn = (wid & 3) * 32;

    for (int i = tid; i < 128 * 10; i += 256) sW[i] = Wp2[i];
    if (tid < 128) sbc[tid] = bcp[tid];

    const int arow = tid >> 1,  acq = (tid & 1) * 8;
    const int brow = tid >> 4,  bcq = (tid & 15) * 8;

    float4 pa0, pa1, pb0, pb1;
    auto loadG = [&](int k0) {
        int gr = bm + arow;
        pa0 = *(const float4*)&A[(size_t)gr * K + k0 + acq];
        pa1 = *(const float4*)&A[(size_t)gr * K + k0 + acq + 4];
        pb0 = *(const float4*)&B[(size_t)(k0 + brow) * N + bcq];
        pb1 = *(const float4*)&B[(size_t)(k0 + brow) * N + bcq + 4];
    };
    auto storeS = [&](int buf) {
        *(float4*)&As[buf][arow][acq]     = pa0;
        *(float4*)&As[buf][arow][acq + 4] = pa1;
        *(float4*)&Bs[buf][brow][bcq]     = pb0;
        *(float4*)&Bs[buf][brow][bcq + 4] = pb1;
    };

    float acc[4][4][4];
    #pragma unroll
    for (int i = 0; i < 4; i++)
        #pragma unroll
        for (int j = 0; j < 4; j++)
            #pragma unroll
            for (int r = 0; r < 4; r++) acc[i][j][r] = 0.f;

    loadG(0); storeS(0); __syncthreads();

    const int ntiles = K >> 4;   // 16
    for (int t = 0; t < ntiles; t++) {
        const int cur = t & 1;
        if (t + 1 < ntiles) loadG((t + 1) << 4);
        #pragma unroll
        for (int ks = 0; ks < 2; ks++) {
            uint32_t ahf[4][4], alf[4][4], bhf[4][2], blf[4][2];
            #pragma unroll
            for (int mt = 0; mt < 4; mt++) {
                int r0 = wm + mt * 16 + gid;
                int c0 = ks * 8 + tg;
                split_u(As[cur][r0    ][c0    ], ahf[mt][0], alf[mt][0]);
                split_u(As[cur][r0 + 8][c0    ], ahf[mt][1], alf[mt][1]);
                split_u(As[cur][r0    ][c0 + 4], ahf[mt][2], alf[mt][2]);
                split_u(As[cur][r0 + 8][c0 + 4], ahf[mt][3], alf[mt][3]);
            }
            #pragma unroll
            for (int nt = 0; nt < 4; nt++) {
                int c = wn + nt * 8 + gid;
                split_u(Bs[cur][ks * 8 + tg    ][c], bhf[nt][0], blf[nt][0]);
                split_u(Bs[cur][ks * 8 + tg + 4][c], bhf[nt][1], blf[nt][1]);
            }
            #pragma unroll
            for (int mt = 0; mt < 4; mt++)
                #pragma unroll
                for (int nt = 0; nt < 4; nt++) {
                    MMA_TF32(acc[mt][nt], ahf[mt], bhf[nt]);
                    MMA_TF32(acc[mt][nt], ahf[mt], blf[nt]);
                    MMA_TF32(acc[mt][nt], alf[mt], bhf[nt]);
                }
        }
        if (t + 1 < ntiles) { storeS(cur ^ 1); __syncthreads(); }
    }

    // fused epilogue: per-row elu + dot with Wp2[:, lbl(row)]
    #pragma unroll
    for (int mt = 0; mt < 4; mt++) {
        #pragma unroll
        for (int half = 0; half < 2; half++) {
            int row = wm + mt * 16 + gid + half * 8;
            int lbl = g_lbl[bm + row];
            float p = 0.f;
            #pragma unroll
            for (int nt = 0; nt < 4; nt++) {
                int c = wn + nt * 8 + tg * 2;
                float v0 = acc[mt][nt][half * 2 + 0] + sbc[c];
                float v1 = acc[mt][nt][half * 2 + 1] + sbc[c + 1];
                float h0 = elu1(v0), h1 = elu1(v1);
                p += h0 * sW[c * 10 + lbl] + h1 * sW[(c + 1) * 10 + lbl];
            }
            p += __shfl_xor_sync(0xffffffffu, p, 1);
            p += __shfl_xor_sync(0xffffffffu, p, 2);
            if (tg == 0) red[row][wid & 3] = p;
        }
    }
    __syncthreads();
    if (tid < 128) {
        float s = red[tid][0] + red[tid][1] + red[tid][2] + red[tid][3];
        g_sel[bm + tid] = s + __ldg(&bp2[g_lbl[bm + tid]]);
    }
}

// ---------------- edge scatter-add -------------------------------------------
__global__ void k_scatter(const int* __restrict__ ei) {
    long long t = (long long)blockIdx.x * blockDim.x + threadIdx.x;
    if (t >= (long long)NE * HD) return;
    int e = (int)(t >> 7), f = (int)(t & 127);
    int s = __ldg(&ei[e]);
    int d = __ldg(&ei[NE + e]);
    float v = g_Mm[(size_t)s * HD + f];
    atomicAdd(&g_aggF[(size_t)d * HD + f], v);
    if (e < NOCP) atomicAdd(&g_aggO[(size_t)d * HD + f], v);
}

// ---------------- D = elu(S+aggF+b) - elu(S+aggO+b) --------------------------
__global__ void k_D(const float* __restrict__ bg) {
    size_t i = (size_t)blockIdx.x * blockDim.x + threadIdx.x;
    if (i >= (size_t)NN * HD) return;
    int f = (int)(i & 127);
    float base = g_S[i] + bg[f];
    float xf = base + g_aggF[i];
    float xo = base + g_aggO[i];
    g_D[i] = elu1(xf) - elu1(xo);
}

// ---------------- segment reductions -----------------------------------------
__device__ __forceinline__ void atomMaxF(int* a, float v) {
    int iv = __float_as_int(v);
    if (iv >= 0) atomicMax(a, iv);
    else         atomicMin((unsigned int*)a, (unsigned int)iv);
}

__global__ void k_mx() {
    __shared__ int sm[NG];
    int tid = threadIdx.x;
    if (tid < NG) sm[tid] = (int)0xFF800000;
    __syncthreads();
    int e = blockIdx.x * blockDim.x + tid;
    if (e < EA) atomMaxF(&sm[g_seg[e]], g_sel[e]);
    __syncthreads();
    if (tid < NG) atomMaxF(&g_mx[tid], __int_as_float(sm[tid]));
}

__global__ void k_ex() {
    __shared__ float ss[NG];
    int tid = threadIdx.x;
    if (tid < NG) ss[tid] = 0.f;
    __syncthreads();
    int e = blockIdx.x * blockDim.x + tid;
    if (e < EA) {
        int g = g_seg[e];
        float v = expf(g_sel[e] - __int_as_float(g_mx[g]));
        g_ex[e] = v;
        atomicAdd(&ss[g], v);
    }
    __syncthreads();
    if (tid < NG && ss[tid] != 0.f) atomicAdd(&g_sum[tid], ss[tid]);
}

__global__ void k_probs(float* __restrict__ out) {
    __shared__ int sp[NG];
    int tid = threadIdx.x;
    if (tid < NG) sp[tid] = 0;
    __syncthreads();
    int e = blockIdx.x * blockDim.x + tid;
    if (e < EA) {
        int g = g_seg[e];
        float p = g_ex[e] / g_sum[g];
        out[e] = p;
        atomicMax(&sp[g], __float_as_int(p));
    }
    __syncthreads();
    if (tid < NG) atomicMax(&g_pm[tid], sp[tid]);
}

__global__ void k_added(const float* __restrict__ out) {
    int e = blockIdx.x * blockDim.x + threadIdx.x;
    if (e >= EA) return;
    int g = g_seg[e];
    if (__float_as_int(out[e]) == g_pm[g]) atomicMin(&g_added[g], e);
}

__global__ void k_tail(float* __restrict__ out) {
    int t = threadIdx.x;
    if (t < NG) {
        out[EA + t]      = __int_as_float(g_pm[t]);
        out[EA + NG + t] = (float)g_added[t];
    }
}

// ---------------- launch ------------------------------------------------------
extern "C" void kernel_launch(void* const* d_in, const int* in_sizes, int n_in,
                              void* d_out, int out_size) {
    const int pb = n_in - 13;
    const float* x      = (const float*)d_in[0];
    const int*   ei     = (const int*)  d_in[1];
    const int*   bv     = (const int*)  d_in[2];
    const int*   y      = (const int*)  d_in[3];
    const float* W_self = (const float*)d_in[pb + 0];
    const float* W_nbr  = (const float*)d_in[pb + 1];
    const float* b_gnn  = (const float*)d_in[pb + 2];
    const float* Wr1    = (const float*)d_in[pb + 3];
    const float* br1    = (const float*)d_in[pb + 4];
    const float* Wr2    = (const float*)d_in[pb + 5];
    const float* br2    = (const float*)d_in[pb + 6];
    const float* Wr3    = (const float*)d_in[pb + 7];
    const float* br3    = (const float*)d_in[pb + 8];
    const float* Wp1    = (const float*)d_in[pb + 9];
    const float* bp1    = (const float*)d_in[pb + 10];
    const float* Wp2    = (const float*)d_in[pb + 11];
    const float* bp2    = (const float*)d_in[pb + 12];
    float* out = (float*)d_out;

    void *pS, *pM, *pP, *pQ, *pA2, *pD, *pWc, *pbc;
    cudaGetSymbolAddress(&pS,  g_S);
    cudaGetSymbolAddress(&pM,  g_Mm);
    cudaGetSymbolAddress(&pP,  g_P);
    cudaGetSymbolAddress(&pQ,  g_Q);
    cudaGetSymbolAddress(&pA2, g_A2);
    cudaGetSymbolAddress(&pD,  g_D);
    cudaGetSymbolAddress(&pWc, g_Wc);
    cudaGetSymbolAddress(&pbc, g_bc);

    const int T = 256;

    k_init<<<(NN * HD + T - 1) / T, T>>>();
    k_wc  <<<(256 * 128 + T - 1) / T, T>>>(Wr3, br3, Wp1, bp1);
    k_seg <<<(EA + T - 1) / T, T>>>(ei, bv, y);

    // node transform GEMMs: S = x@W_self, M = x@W_nbr
    {
        dim3 grid(1, (NN + 127) / 128);
        tgemm<false, false, false><<<grid, T>>>(x, W_self, nullptr, (float*)pS, NN, HD, HD,
                                                nullptr, nullptr, nullptr, nullptr, nullptr);
        tgemm<false, false, false><<<grid, T>>>(x, W_nbr,  nullptr, (float*)pM, NN, HD, HD,
                                                nullptr, nullptr, nullptr, nullptr, nullptr);
    }
    k_scatter<<<(int)(((long long)NE * HD + T - 1) / T), T>>>(ei);
    k_D<<<(NN * HD + T - 1) / T, T>>>(b_gnn);

    // node-space hoist of GEMM1: P = D@Wr1[0:128,:], Q = D@Wr1[128:256,:]
    {
        dim3 grid(4, (NN + 127) / 128);
        tgemm<false, false, false><<<grid, T>>>((const float*)pD, Wr1,             nullptr, (float*)pP, NN, 512, HD,
                                                nullptr, nullptr, nullptr, nullptr, nullptr);
        tgemm<false, false, false><<<grid, T>>>((const float*)pD, Wr1 + 128 * 512, nullptr, (float*)pQ, NN, 512, HD,
                                                nullptr, nullptr, nullptr, nullptr, nullptr);
    }

    // GEMM2 fused with A1 construction:
    // A2 = elu( elu(P[src]+Q[dst]+br1) @ Wr2 + br2 )
    tgemm<true, true, true><<<dim3(2, EA / 128), T>>>(
        nullptr, Wr2, br2, (float*)pA2, EA, 256, 512,
        ei + NOCP, ei + NE + NOCP, (const float*)pP, (const float*)pQ, br1);

    // fused GEMM3 + sel
    gemm3_sel<<<dim3(1, EA / 128), T>>>((const float*)pA2, (const float*)pWc,
                                        (const float*)pbc, Wp2, bp2);

    // segment softmax + argmax
    const int segBlocks = (EA + T - 1) / T;
    k_mx   <<<segBlocks, T>>>();
    k_ex   <<<segBlocks, T>>>();
    k_probs<<<segBlocks, T>>>(out);
    k_added<<<segBlocks, T>>>(out);
    k_tail <<<1, 64>>>(out);
}

// round 5
// speedup vs baseline: 1.3377x; 1.2088x over previous
#include <cuda_runtime.h>
#include <cuda_bf16.h>
#include <math.h>
#include <stdint.h>

#define NN   50000
#define NE   262144
#define NOCP 32768
#define EA   (NE - NOCP)      // 229376
#define NG   64
#define HD   128

// ---------------- scratch (device globals; allocation-free kernel_launch) ----
__device__ float g_S   [NN * HD];
__device__ float g_Mm  [NN * HD];
__device__ float g_aggF[NN * HD];
__device__ float g_aggO[NN * HD];
__device__ float g_D   [NN * HD];
__device__ float g_P   [(size_t)NN * 512];
__device__ float g_Q   [(size_t)NN * 512];
__device__ float g_A2  [(size_t)EA * 256];
__device__ float g_sel [EA];
__device__ float g_ex  [EA];
__device__ int   g_seg [EA];
__device__ int   g_lbl [EA];
__device__ float g_Wc  [256 * 128];
__device__ float g_bc  [128];
__device__ int   g_mx  [NG];
__device__ float g_sum [NG];
__device__ int   g_pm  [NG];
__device__ int   g_added[NG];

// ---------------- init ------------------------------------------------------
__global__ void k_init() {
    size_t i = (size_t)blockIdx.x * blockDim.x + threadIdx.x;
    if (i < (size_t)NN * HD) { g_aggF[i] = 0.f; g_aggO[i] = 0.f; }
    if (blockIdx.x == 0 && threadIdx.x < NG) {
        g_mx[threadIdx.x]    = (int)0xFF800000;
        g_sum[threadIdx.x]   = 0.f;
        g_pm[threadIdx.x]    = 0;
        g_added[threadIdx.x] = EA;
    }
}

// ---------------- Wc = Wr3 @ Wp1, bc = br3 @ Wp1 + bp1 -----------------------
__global__ void k_wc(const float* __restrict__ Wr3, const float* __restrict__ br3,
                     const float* __restrict__ Wp1, const float* __restrict__ bp1) {
    int t = blockIdx.x * blockDim.x + threadIdx.x;
    if (t >= 256 * 128) return;
    int k = t >> 7, c = t & 127;
    float s = 0.f;
    #pragma unroll 8
    for (int m = 0; m < 128; m++) s += Wr3[k * 128 + m] * Wp1[m * 128 + c];
    g_Wc[t] = s;
    if (t < 128) {
        float b = bp1[t];
        #pragma unroll 8
        for (int m = 0; m < 128; m++) b += br3[m] * Wp1[m * 128 + t];
        g_bc[t] = b;
    }
}

// ---------------- per-edge segment / label precompute ------------------------
__global__ void k_seg(const int* __restrict__ ei, const int* __restrict__ bv,
                      const int* __restrict__ y) {
    int e = blockIdx.x * blockDim.x + threadIdx.x;
    if (e >= EA) return;
    int s = __ldg(&ei[NOCP + e]);
    int g = __ldg(&bv[s]);
    g_seg[e] = g;
    g_lbl[e] = __ldg(&y[g]);
}

// =============================================================================
//   BF16x3 tensor-core GEMM (mma m16n8k16): pre-split packed bf16 pairs in smem
// C = op(A@B + bias); 128x128 block tile, K-step 16, 256 thr, 8 warps (64x32).
// FUSEA: A row e built on the fly as elu(P[src[e]] + Q[dst[e]] + bext).
// =============================================================================
#define MMA_BF16(d, a, b)                                                     \
    asm volatile(                                                             \
        "mma.sync.aligned.m16n8k16.row.col.f32.bf16.bf16.f32 "                \
        "{%0,%1,%2,%3}, {%4,%5,%6,%7}, {%8,%9}, {%0,%1,%2,%3};\n"             \
        : "+f"((d)[0]), "+f"((d)[1]), "+f"((d)[2]), "+f"((d)[3])              \
        : "r"((a)[0]), "r"((a)[1]), "r"((a)[2]), "r"((a)[3]),                 \
          "r"((b)[0]), "r"((b)[1]))

// pack (f0 -> low half, f1 -> high half) as bf16 hi plane + bf16 lo plane
__device__ __forceinline__ void cvt_pair(float f0, float f1, uint32_t& h, uint32_t& l) {
    __nv_bfloat162 H = __floats2bfloat162_rn(f0, f1);
    float2 Hf = __bfloat1622float2(H);
    __nv_bfloat162 L = __floats2bfloat162_rn(f0 - Hf.x, f1 - Hf.y);
    h = *(uint32_t*)&H;
    l = *(uint32_t*)&L;
}

__device__ __forceinline__ float elu1(float v) { return (v > 0.f) ? v : expm1f(v); }

#define ASTR 12      // A smem row stride (words); conflict-free fragment LDS
#define BSTR 132     // B smem row stride (words)

template <bool ELU, bool HASBIAS, bool FUSEA>
__global__ void __launch_bounds__(256)
tgemm(const float* __restrict__ A, const float* __restrict__ B,
      const float* __restrict__ bias, float* __restrict__ C,
      int M, int N, int K,
      const int* __restrict__ esrc, const int* __restrict__ edst,
      const float* __restrict__ Pm, const float* __restrict__ Qm,
      const float* __restrict__ bext) {
    __shared__ uint32_t Ah[2][128][ASTR], Al[2][128][ASTR];
    __shared__ uint32_t Bh[2][8][BSTR],  Bl[2][8][BSTR];

    const int tid = threadIdx.x;
    const int bm = blockIdx.y * 128;
    const int bn = blockIdx.x * 128;

    const int wid = tid >> 5, lane = tid & 31;
    const int gid = lane >> 2, tg = lane & 3;
    const int wm = (wid >> 2) * 64, wn = (wid & 3) * 32;

    // loaders: A by (row, 8-k half); B by (k-pair, 4-col chunk)
    const int arow = tid >> 1,  acq = (tid & 1) * 8;
    const int bkp  = tid >> 5,  bnq = (tid & 31) * 4;

    int src = 0, dst = 0;
    if (FUSEA) {
        src = __ldg(&esrc[bm + arow]);
        dst = __ldg(&edst[bm + arow]);
    }

    float4 pa0, pa1, pb0, pb1;
    auto loadG = [&](int k0) {
        if (FUSEA) {
            float4 p0 = *(const float4*)&Pm[(size_t)src * 512 + k0 + acq];
            float4 p1 = *(const float4*)&Pm[(size_t)src * 512 + k0 + acq + 4];
            float4 q0 = *(const float4*)&Qm[(size_t)dst * 512 + k0 + acq];
            float4 q1 = *(const float4*)&Qm[(size_t)dst * 512 + k0 + acq + 4];
            float4 b0 = *(const float4*)&bext[k0 + acq];
            float4 b1 = *(const float4*)&bext[k0 + acq + 4];
            pa0.x = elu1(p0.x + q0.x + b0.x); pa0.y = elu1(p0.y + q0.y + b0.y);
            pa0.z = elu1(p0.z + q0.z + b0.z); pa0.w = elu1(p0.w + q0.w + b0.w);
            pa1.x = elu1(p1.x + q1.x + b1.x); pa1.y = elu1(p1.y + q1.y + b1.y);
            pa1.z = elu1(p1.z + q1.z + b1.z); pa1.w = elu1(p1.w + q1.w + b1.w);
        } else {
            int gr = bm + arow;
            if (gr < M) {
                pa0 = *(const float4*)&A[(size_t)gr * K + k0 + acq];
                pa1 = *(const float4*)&A[(size_t)gr * K + k0 + acq + 4];
            } else {
                pa0 = make_float4(0.f, 0.f, 0.f, 0.f); pa1 = pa0;
            }
        }
        pb0 = *(const float4*)&B[(size_t)(k0 + 2 * bkp)     * N + bn + bnq];
        pb1 = *(const float4*)&B[(size_t)(k0 + 2 * bkp + 1) * N + bn + bnq];
    };
    auto storeS = [&](int buf) {
        uint32_t h0, h1, h2, h3, l0, l1, l2, l3;
        // A: pairs along k
        cvt_pair(pa0.x, pa0.y, h0, l0);
        cvt_pair(pa0.z, pa0.w, h1, l1);
        cvt_pair(pa1.x, pa1.y, h2, l2);
        cvt_pair(pa1.z, pa1.w, h3, l3);
        int kp = acq >> 1;  // 0 or 4
        *(uint4*)&Ah[buf][arow][kp] = make_uint4(h0, h1, h2, h3);
        *(uint4*)&Al[buf][arow][kp] = make_uint4(l0, l1, l2, l3);
        // B: pairs across the two k rows (low half = even k)
        cvt_pair(pb0.x, pb1.x, h0, l0);
        cvt_pair(pb0.y, pb1.y, h1, l1);
        cvt_pair(pb0.z, pb1.z, h2, l2);
        cvt_pair(pb0.w, pb1.w, h3, l3);
        *(uint4*)&Bh[buf][bkp][bnq] = make_uint4(h0, h1, h2, h3);
        *(uint4*)&Bl[buf][bkp][bnq] = make_uint4(l0, l1, l2, l3);
    };

    float acc[4][4][4];
    #pragma unroll
    for (int i = 0; i < 4; i++)
        #pragma unroll
        for (int j = 0; j < 4; j++)
            #pragma unroll
            for (int r = 0; r < 4; r++) acc[i][j][r] = 0.f;

    loadG(0); storeS(0); __syncthreads();

    const int ntiles = K >> 4;
    for (int t = 0; t < ntiles; t++) {
        const int cur = t & 1;
        if (t + 1 < ntiles) loadG((t + 1) << 4);

        uint32_t ahf[4][4], alf[4][4], bhf[4][2], blf[4][2];
        #pragma unroll
        for (int mt = 0; mt < 4; mt++) {
            int r0 = wm + mt * 16 + gid;
            ahf[mt][0] = Ah[cur][r0    ][tg    ]; alf[mt][0] = Al[cur][r0    ][tg    ];
            ahf[mt][1] = Ah[cur][r0 + 8][tg    ]; alf[mt][1] = Al[cur][r0 + 8][tg    ];
            ahf[mt][2] = Ah[cur][r0    ][tg + 4]; alf[mt][2] = Al[cur][r0    ][tg + 4];
            ahf[mt][3] = Ah[cur][r0 + 8][tg + 4]; alf[mt][3] = Al[cur][r0 + 8][tg + 4];
        }
        #pragma unroll
        for (int nt = 0; nt < 4; nt++) {
            int c = wn + nt * 8 + gid;
            bhf[nt][0] = Bh[cur][tg    ][c]; blf[nt][0] = Bl[cur][tg    ][c];
            bhf[nt][1] = Bh[cur][tg + 4][c]; blf[nt][1] = Bl[cur][tg + 4][c];
        }
        #pragma unroll
        for (int mt = 0; mt < 4; mt++)
            #pragma unroll
            for (int nt = 0; nt < 4; nt++) {
                MMA_BF16(acc[mt][nt], ahf[mt], bhf[nt]);
                MMA_BF16(acc[mt][nt], ahf[mt], blf[nt]);
                MMA_BF16(acc[mt][nt], alf[mt], bhf[nt]);
            }

        if (t + 1 < ntiles) { storeS(cur ^ 1); __syncthreads(); }
    }

    #pragma unroll
    for (int mt = 0; mt < 4; mt++) {
        int r0 = bm + wm + mt * 16 + gid;
        #pragma unroll
        for (int nt = 0; nt < 4; nt++) {
            int c = bn + wn + nt * 8 + tg * 2;
            float b0 = HASBIAS ? __ldg(&bias[c])     : 0.f;
            float b1 = HASBIAS ? __ldg(&bias[c + 1]) : 0.f;
            if (r0 < M) {
                float v0 = acc[mt][nt][0] + b0, v1 = acc[mt][nt][1] + b1;
                if (ELU) { v0 = elu1(v0); v1 = elu1(v1); }
                *(float2*)&C[(size_t)r0 * N + c] = make_float2(v0, v1);
            }
            if (r0 + 8 < M) {
                float v2 = acc[mt][nt][2] + b0, v3 = acc[mt][nt][3] + b1;
                if (ELU) { v2 = elu1(v2); v3 = elu1(v3); }
                *(float2*)&C[(size_t)(r0 + 8) * N + c] = make_float2(v2, v3);
            }
        }
    }
}

// ===== GEMM3 fused with sel: sel[e] = elu(A2@Wc + bc) . Wp2[:,lbl] + bp2 =====
__global__ void __launch_bounds__(256)
gemm3_sel(const float* __restrict__ A, const float* __restrict__ B,
          const float* __restrict__ bcp, const float* __restrict__ Wp2,
          const float* __restrict__ bp2) {
    __shared__ uint32_t Ah[2][128][ASTR], Al[2][128][ASTR];
    __shared__ uint32_t Bh[2][8][BSTR],  Bl[2][8][BSTR];
    __shared__ float sW[128 * 10];
    __shared__ float sbc[128];
    __shared__ float red[128][5];

    const int tid = threadIdx.x;
    const int bm = blockIdx.y * 128;
    const int K = 256, N = 128;

    const int wid = tid >> 5, lane = tid & 31;
    const int gid = lane >> 2, tg = lane & 3;
    const int wm = (wid >> 2) * 64, wn = (wid & 3) * 32;

    for (int i = tid; i < 128 * 10; i += 256) sW[i] = Wp2[i];
    if (tid < 128) sbc[tid] = bcp[tid];

    const int arow = tid >> 1,  acq = (tid & 1) * 8;
    const int bkp  = tid >> 5,  bnq = (tid & 31) * 4;

    float4 pa0, pa1, pb0, pb1;
    auto loadG = [&](int k0) {
        int gr = bm + arow;
        pa0 = *(const float4*)&A[(size_t)gr * K + k0 + acq];
        pa1 = *(const float4*)&A[(size_t)gr * K + k0 + acq + 4];
        pb0 = *(const float4*)&B[(size_t)(k0 + 2 * bkp)     * N + bnq];
        pb1 = *(const float4*)&B[(size_t)(k0 + 2 * bkp + 1) * N + bnq];
    };
    auto storeS = [&](int buf) {
        uint32_t h0, h1, h2, h3, l0, l1, l2, l3;
        cvt_pair(pa0.x, pa0.y, h0, l0);
        cvt_pair(pa0.z, pa0.w, h1, l1);
        cvt_pair(pa1.x, pa1.y, h2, l2);
        cvt_pair(pa1.z, pa1.w, h3, l3);
        int kp = acq >> 1;
        *(uint4*)&Ah[buf][arow][kp] = make_uint4(h0, h1, h2, h3);
        *(uint4*)&Al[buf][arow][kp] = make_uint4(l0, l1, l2, l3);
        cvt_pair(pb0.x, pb1.x, h0, l0);
        cvt_pair(pb0.y, pb1.y, h1, l1);
        cvt_pair(pb0.z, pb1.z, h2, l2);
        cvt_pair(pb0.w, pb1.w, h3, l3);
        *(uint4*)&Bh[buf][bkp][bnq] = make_uint4(h0, h1, h2, h3);
        *(uint4*)&Bl[buf][bkp][bnq] = make_uint4(l0, l1, l2, l3);
    };

    float acc[4][4][4];
    #pragma unroll
    for (int i = 0; i < 4; i++)
        #pragma unroll
        for (int j = 0; j < 4; j++)
            #pragma unroll
            for (int r = 0; r < 4; r++) acc[i][j][r] = 0.f;

    loadG(0); storeS(0); __syncthreads();

    const int ntiles = K >> 4;   // 16
    for (int t = 0; t < ntiles; t++) {
        const int cur = t & 1;
        if (t + 1 < ntiles) loadG((t + 1) << 4);

        uint32_t ahf[4][4], alf[4][4], bhf[4][2], blf[4][2];
        #pragma unroll
        for (int mt = 0; mt < 4; mt++) {
            int r0 = wm + mt * 16 + gid;
            ahf[mt][0] = Ah[cur][r0    ][tg    ]; alf[mt][0] = Al[cur][r0    ][tg    ];
            ahf[mt][1] = Ah[cur][r0 + 8][tg    ]; alf[mt][1] = Al[cur][r0 + 8][tg    ];
            ahf[mt][2] = Ah[cur][r0    ][tg + 4]; alf[mt][2] = Al[cur][r0    ][tg + 4];
            ahf[mt][3] = Ah[cur][r0 + 8][tg + 4]; alf[mt][3] = Al[cur][r0 + 8][tg + 4];
        }
        #pragma unroll
        for (int nt = 0; nt < 4; nt++) {
            int c = wn + nt * 8 + gid;
            bhf[nt][0] = Bh[cur][tg    ][c]; blf[nt][0] = Bl[cur][tg    ][c];
            bhf[nt][1] = Bh[cur][tg + 4][c]; blf[nt][1] = Bl[cur][tg + 4][c];
        }
        #pragma unroll
        for (int mt = 0; mt < 4; mt++)
            #pragma unroll
            for (int nt = 0; nt < 4; nt++) {
                MMA_BF16(acc[mt][nt], ahf[mt], bhf[nt]);
                MMA_BF16(acc[mt][nt], ahf[mt], blf[nt]);
                MMA_BF16(acc[mt][nt], alf[mt], bhf[nt]);
            }

        if (t + 1 < ntiles) { storeS(cur ^ 1); __syncthreads(); }
    }

    // fused epilogue: per-row elu + dot with Wp2[:, lbl(row)]
    #pragma unroll
    for (int mt = 0; mt < 4; mt++) {
        #pragma unroll
        for (int half = 0; half < 2; half++) {
            int row = wm + mt * 16 + gid + half * 8;
            int lbl = g_lbl[bm + row];
            float p = 0.f;
            #pragma unroll
            for (int nt = 0; nt < 4; nt++) {
                int c = wn + nt * 8 + tg * 2;
                float v0 = acc[mt][nt][half * 2 + 0] + sbc[c];
                float v1 = acc[mt][nt][half * 2 + 1] + sbc[c + 1];
                float h0 = elu1(v0), h1 = elu1(v1);
                p += h0 * sW[c * 10 + lbl] + h1 * sW[(c + 1) * 10 + lbl];
            }
            p += __shfl_xor_sync(0xffffffffu, p, 1);
            p += __shfl_xor_sync(0xffffffffu, p, 2);
            if (tg == 0) red[row][wid & 3] = p;
        }
    }
    __syncthreads();
    if (tid < 128) {
        float s = red[tid][0] + red[tid][1] + red[tid][2] + red[tid][3];
        g_sel[bm + tid] = s + __ldg(&bp2[g_lbl[bm + tid]]);
    }
}

// ---------------- edge scatter-add -------------------------------------------
__global__ void k_scatter(const int* __restrict__ ei) {
    long long t = (long long)blockIdx.x * blockDim.x + threadIdx.x;
    if (t >= (long long)NE * HD) return;
    int e = (int)(t >> 7), f = (int)(t & 127);
    int s = __ldg(&ei[e]);
    int d = __ldg(&ei[NE + e]);
    float v = g_Mm[(size_t)s * HD + f];
    atomicAdd(&g_aggF[(size_t)d * HD + f], v);
    if (e < NOCP) atomicAdd(&g_aggO[(size_t)d * HD + f], v);
}

// ---------------- D = elu(S+aggF+b) - elu(S+aggO+b) --------------------------
__global__ void k_D(const float* __restrict__ bg) {
    size_t i = (size_t)blockIdx.x * blockDim.x + threadIdx.x;
    if (i >= (size_t)NN * HD) return;
    int f = (int)(i & 127);
    float base = g_S[i] + bg[f];
    float xf = base + g_aggF[i];
    float xo = base + g_aggO[i];
    g_D[i] = elu1(xf) - elu1(xo);
}

// ---------------- segment reductions -----------------------------------------
__device__ __forceinline__ void atomMaxF(int* a, float v) {
    int iv = __float_as_int(v);
    if (iv >= 0) atomicMax(a, iv);
    else         atomicMin((unsigned int*)a, (unsigned int)iv);
}

__global__ void k_mx() {
    __shared__ int sm[NG];
    int tid = threadIdx.x;
    if (tid < NG) sm[tid] = (int)0xFF800000;
    __syncthreads();
    int e = blockIdx.x * blockDim.x + tid;
    if (e < EA) atomMaxF(&sm[g_seg[e]], g_sel[e]);
    __syncthreads();
    if (tid < NG) atomMaxF(&g_mx[tid], __int_as_float(sm[tid]));
}

__global__ void k_ex() {
    __shared__ float ss[NG];
    int tid = threadIdx.x;
    if (tid < NG) ss[tid] = 0.f;
    __syncthreads();
    int e = blockIdx.x * blockDim.x + tid;
    if (e < EA) {
        int g = g_seg[e];
        float v = expf(g_sel[e] - __int_as_float(g_mx[g]));
        g_ex[e] = v;
        atomicAdd(&ss[g], v);
    }
    __syncthreads();
    if (tid < NG && ss[tid] != 0.f) atomicAdd(&g_sum[tid], ss[tid]);
}

__global__ void k_probs(float* __restrict__ out) {
    __shared__ int sp[NG];
    int tid = threadIdx.x;
    if (tid < NG) sp[tid] = 0;
    __syncthreads();
    int e = blockIdx.x * blockDim.x + tid;
    if (e < EA) {
        int g = g_seg[e];
        float p = g_ex[e] / g_sum[g];
        out[e] = p;
        atomicMax(&sp[g], __float_as_int(p));
    }
    __syncthreads();
    if (tid < NG) atomicMax(&g_pm[tid], sp[tid]);
}

__global__ void k_added(const float* __restrict__ out) {
    int e = blockIdx.x * blockDim.x + threadIdx.x;
    if (e >= EA) return;
    int g = g_seg[e];
    if (__float_as_int(out[e]) == g_pm[g]) atomicMin(&g_added[g], e);
}

__global__ void k_tail(float* __restrict__ out) {
    int t = threadIdx.x;
    if (t < NG) {
        out[EA + t]      = __int_as_float(g_pm[t]);
        out[EA + NG + t] = (float)g_added[t];
    }
}

// ---------------- launch ------------------------------------------------------
extern "C" void kernel_launch(void* const* d_in, const int* in_sizes, int n_in,
                              void* d_out, int out_size) {
    const int pb = n_in - 13;
    const float* x      = (const float*)d_in[0];
    const int*   ei     = (const int*)  d_in[1];
    const int*   bv     = (const int*)  d_in[2];
    const int*   y      = (const int*)  d_in[3];
    const float* W_self = (const float*)d_in[pb + 0];
    const float* W_nbr  = (const float*)d_in[pb + 1];
    const float* b_gnn  = (const float*)d_in[pb + 2];
    const float* Wr1    = (const float*)d_in[pb + 3];
    const float* br1    = (const float*)d_in[pb + 4];
    const float* Wr2    = (const float*)d_in[pb + 5];
    const float* br2    = (const float*)d_in[pb + 6];
    const float* Wr3    = (const float*)d_in[pb + 7];
    const float* br3    = (const float*)d_in[pb + 8];
    const float* Wp1    = (const float*)d_in[pb + 9];
    const float* bp1    = (const float*)d_in[pb + 10];
    const float* Wp2    = (const float*)d_in[pb + 11];
    const float* bp2    = (const float*)d_in[pb + 12];
    float* out = (float*)d_out;

    void *pS, *pM, *pP, *pQ, *pA2, *pD, *pWc, *pbc;
    cudaGetSymbolAddress(&pS,  g_S);
    cudaGetSymbolAddress(&pM,  g_Mm);
    cudaGetSymbolAddress(&pP,  g_P);
    cudaGetSymbolAddress(&pQ,  g_Q);
    cudaGetSymbolAddress(&pA2, g_A2);
    cudaGetSymbolAddress(&pD,  g_D);
    cudaGetSymbolAddress(&pWc, g_Wc);
    cudaGetSymbolAddress(&pbc, g_bc);

    const int T = 256;

    k_init<<<(NN * HD + T - 1) / T, T>>>();
    k_wc  <<<(256 * 128 + T - 1) / T, T>>>(Wr3, br3, Wp1, bp1);
    k_seg <<<(EA + T - 1) / T, T>>>(ei, bv, y);

    // node transform GEMMs: S = x@W_self, M = x@W_nbr
    {
        dim3 grid(1, (NN + 127) / 128);
        tgemm<false, false, false><<<grid, T>>>(x, W_self, nullptr, (float*)pS, NN, HD, HD,
                                                nullptr, nullptr, nullptr, nullptr, nullptr);
        tgemm<false, false, false><<<grid, T>>>(x, W_nbr,  nullptr, (float*)pM, NN, HD, HD,
                                                nullptr, nullptr, nullptr, nullptr, nullptr);
    }
    k_scatter<<<(int)(((long long)NE * HD + T - 1) / T), T>>>(ei);
    k_D<<<(NN * HD + T - 1) / T, T>>>(b_gnn);

    // node-space hoist of GEMM1: P = D@Wr1[0:128,:], Q = D@Wr1[128:256,:]
    {
        dim3 grid(4, (NN + 127) / 128);
        tgemm<false, false, false><<<grid, T>>>((const float*)pD, Wr1,             nullptr, (float*)pP, NN, 512, HD,
                                                nullptr, nullptr, nullptr, nullptr, nullptr);
        tgemm<false, false, false><<<grid, T>>>((const float*)pD, Wr1 + 128 * 512, nullptr, (float*)pQ, NN, 512, HD,
                                                nullptr, nullptr, nullptr, nullptr, nullptr);
    }

    // GEMM2 fused with A1 construction:
    // A2 = elu( elu(P[src]+Q[dst]+br1) @ Wr2 + br2 )
    tgemm<true, true, true><<<dim3(2, EA / 128), T>>>(
        nullptr, Wr2, br2, (float*)pA2, EA, 256, 512,
        ei + NOCP, ei + NE + NOCP, (const float*)pP, (const float*)pQ, br1);

    // fused GEMM3 + sel
    gemm3_sel<<<dim3(1, EA / 128), T>>>((const float*)pA2, (const float*)pWc,
                                        (const float*)pbc, Wp2, bp2);

    // segment softmax + argmax
    const int segBlocks = (EA + T - 1) / T;
    k_mx   <<<segBlocks, T>>>();
    k_ex   <<<segBlocks, T>>>();
    k_probs<<<segBlocks, T>>>(out);
    k_added<<<segBlocks, T>>>(out);
    k_tail <<<1, 64>>>(out);
}

// round 6
// speedup vs baseline: 1.9105x; 1.4282x over previous
#include <cuda_runtime.h>
#include <cuda_bf16.h>
#include <math.h>
#include <stdint.h>

#define NN   50000
#define NE   262144
#define NOCP 32768
#define EA   (NE - NOCP)      // 229376
#define NG   64
#define HD   128

// ---------------- scratch (device globals; allocation-free kernel_launch) ----
__device__ float g_S   [NN * HD];
__device__ float g_Mm  [NN * HD];
__device__ float g_aggF[NN * HD];
__device__ float g_aggO[NN * HD];
__device__ float g_D   [NN * HD];
__device__ float g_P   [(size_t)NN * 512];
__device__ float g_Q   [(size_t)NN * 512];
__device__ float g_sel [EA];
__device__ float g_ex  [EA];
__device__ int   g_seg [EA];
__device__ int   g_lbl [EA];
__device__ float g_Wc  [256 * 128];
__device__ float g_bc  [128];
__device__ uint32_t g_W2h[256 * 256];   // packed bf16 hi plane of Wr2 (k-pairs x 256)
__device__ uint32_t g_W2l[256 * 256];
__device__ uint32_t g_Wch[128 * 128];   // packed planes of Wc
__device__ uint32_t g_Wcl[128 * 128];
__device__ int   g_mx  [NG];
__device__ float g_sum [NG];
__device__ int   g_pm  [NG];
__device__ int   g_added[NG];

// ---------------- helpers ------------------------------------------------------
__device__ __forceinline__ void cvt_pair(float f0, float f1, uint32_t& h, uint32_t& l) {
    __nv_bfloat162 H = __floats2bfloat162_rn(f0, f1);
    float2 Hf = __bfloat1622float2(H);
    __nv_bfloat162 L = __floats2bfloat162_rn(f0 - Hf.x, f1 - Hf.y);
    h = *(uint32_t*)&H;
    l = *(uint32_t*)&L;
}
__device__ __forceinline__ float elu1(float v) { return (v > 0.f) ? v : expm1f(v); }

#define MMA_BF16(d, a, b)                                                     \
    asm volatile(                                                             \
        "mma.sync.aligned.m16n8k16.row.col.f32.bf16.bf16.f32 "                \
        "{%0,%1,%2,%3}, {%4,%5,%6,%7}, {%8,%9}, {%0,%1,%2,%3};\n"             \
        : "+f"((d)[0]), "+f"((d)[1]), "+f"((d)[2]), "+f"((d)[3])              \
        : "r"((a)[0]), "r"((a)[1]), "r"((a)[2]), "r"((a)[3]),                 \
          "r"((b)[0]), "r"((b)[1]))

// ---------------- init ------------------------------------------------------
__global__ void k_init() {
    size_t i = (size_t)blockIdx.x * blockDim.x + threadIdx.x;
    if (i < (size_t)NN * HD) { g_aggF[i] = 0.f; g_aggO[i] = 0.f; }
    if (blockIdx.x == 0 && threadIdx.x < NG) {
        g_mx[threadIdx.x]    = (int)0xFF800000;
        g_sum[threadIdx.x]   = 0.f;
        g_pm[threadIdx.x]    = 0;
        g_added[threadIdx.x] = EA;
    }
}

// ---------------- Wc = Wr3 @ Wp1, bc = br3 @ Wp1 + bp1 -----------------------
__global__ void k_wc(const float* __restrict__ Wr3, const float* __restrict__ br3,
                     const float* __restrict__ Wp1, const float* __restrict__ bp1) {
    int t = blockIdx.x * blockDim.x + threadIdx.x;
    if (t >= 256 * 128) return;
    int k = t >> 7, c = t & 127;
    float s = 0.f;
    #pragma unroll 8
    for (int m = 0; m < 128; m++) s += Wr3[k * 128 + m] * Wp1[m * 128 + c];
    g_Wc[t] = s;
    if (t < 128) {
        float b = bp1[t];
        #pragma unroll 8
        for (int m = 0; m < 128; m++) b += br3[m] * Wp1[m * 128 + t];
        g_bc[t] = b;
    }
}

// ---------------- pack static B matrices into bf16 hi/lo planes ---------------
__global__ void k_pack2(const float* __restrict__ Wr2) {
    int t = blockIdx.x * blockDim.x + threadIdx.x;
    if (t >= 256 * 256) return;
    int kp = t >> 8, c = t & 255;
    uint32_t h, l;
    cvt_pair(Wr2[(2 * kp) * 256 + c], Wr2[(2 * kp + 1) * 256 + c], h, l);
    g_W2h[t] = h; g_W2l[t] = l;
}
__global__ void k_packc() {
    int t = blockIdx.x * blockDim.x + threadIdx.x;
    if (t >= 128 * 128) return;
    int kp = t >> 7, c = t & 127;
    uint32_t h, l;
    cvt_pair(g_Wc[(2 * kp) * 128 + c], g_Wc[(2 * kp + 1) * 128 + c], h, l);
    g_Wch[t] = h; g_Wcl[t] = l;
}

// ---------------- per-edge segment / label precompute ------------------------
__global__ void k_seg(const int* __restrict__ ei, const int* __restrict__ bv,
                      const int* __restrict__ y) {
    int e = blockIdx.x * blockDim.x + threadIdx.x;
    if (e >= EA) return;
    int s = __ldg(&ei[NOCP + e]);
    int g = __ldg(&bv[s]);
    g_seg[e] = g;
    g_lbl[e] = __ldg(&y[g]);
}

// =============================================================================
//   BF16x3 tensor-core GEMM (dense; used for S/M and P/Q)
// =============================================================================
#define ASTR 12
#define BSTR 132

template <bool ELU, bool HASBIAS>
__global__ void __launch_bounds__(256)
tgemm(const float* __restrict__ A, const float* __restrict__ B,
      const float* __restrict__ bias, float* __restrict__ C,
      int M, int N, int K) {
    __shared__ uint32_t Ah[2][128][ASTR], Al[2][128][ASTR];
    __shared__ uint32_t Bh[2][8][BSTR],  Bl[2][8][BSTR];

    const int tid = threadIdx.x;
    const int bm = blockIdx.y * 128;
    const int bn = blockIdx.x * 128;

    const int wid = tid >> 5, lane = tid & 31;
    const int gid = lane >> 2, tg = lane & 3;
    const int wm = (wid >> 2) * 64, wn = (wid & 3) * 32;

    const int arow = tid >> 1,  acq = (tid & 1) * 8;
    const int bkp  = tid >> 5,  bnq = (tid & 31) * 4;

    float4 pa0, pa1, pb0, pb1;
    auto loadG = [&](int k0) {
        int gr = bm + arow;
        if (gr < M) {
            pa0 = *(const float4*)&A[(size_t)gr * K + k0 + acq];
            pa1 = *(const float4*)&A[(size_t)gr * K + k0 + acq + 4];
        } else {
            pa0 = make_float4(0.f, 0.f, 0.f, 0.f); pa1 = pa0;
        }
        pb0 = *(const float4*)&B[(size_t)(k0 + 2 * bkp)     * N + bn + bnq];
        pb1 = *(const float4*)&B[(size_t)(k0 + 2 * bkp + 1) * N + bn + bnq];
    };
    auto storeS = [&](int buf) {
        uint32_t h0, h1, h2, h3, l0, l1, l2, l3;
        cvt_pair(pa0.x, pa0.y, h0, l0);
        cvt_pair(pa0.z, pa0.w, h1, l1);
        cvt_pair(pa1.x, pa1.y, h2, l2);
        cvt_pair(pa1.z, pa1.w, h3, l3);
        int kp = acq >> 1;
        *(uint4*)&Ah[buf][arow][kp] = make_uint4(h0, h1, h2, h3);
        *(uint4*)&Al[buf][arow][kp] = make_uint4(l0, l1, l2, l3);
        cvt_pair(pb0.x, pb1.x, h0, l0);
        cvt_pair(pb0.y, pb1.y, h1, l1);
        cvt_pair(pb0.z, pb1.z, h2, l2);
        cvt_pair(pb0.w, pb1.w, h3, l3);
        *(uint4*)&Bh[buf][bkp][bnq] = make_uint4(h0, h1, h2, h3);
        *(uint4*)&Bl[buf][bkp][bnq] = make_uint4(l0, l1, l2, l3);
    };

    float acc[4][4][4];
    #pragma unroll
    for (int i = 0; i < 4; i++)
        #pragma unroll
        for (int j = 0; j < 4; j++)
            #pragma unroll
            for (int r = 0; r < 4; r++) acc[i][j][r] = 0.f;

    loadG(0); storeS(0); __syncthreads();

    const int ntiles = K >> 4;
    for (int t = 0; t < ntiles; t++) {
        const int cur = t & 1;
        if (t + 1 < ntiles) loadG((t + 1) << 4);

        uint32_t ahf[4][4], alf[4][4], bhf[4][2], blf[4][2];
        #pragma unroll
        for (int mt = 0; mt < 4; mt++) {
            int r0 = wm + mt * 16 + gid;
            ahf[mt][0] = Ah[cur][r0    ][tg    ]; alf[mt][0] = Al[cur][r0    ][tg    ];
            ahf[mt][1] = Ah[cur][r0 + 8][tg    ]; alf[mt][1] = Al[cur][r0 + 8][tg    ];
            ahf[mt][2] = Ah[cur][r0    ][tg + 4]; alf[mt][2] = Al[cur][r0    ][tg + 4];
            ahf[mt][3] = Ah[cur][r0 + 8][tg + 4]; alf[mt][3] = Al[cur][r0 + 8][tg + 4];
        }
        #pragma unroll
        for (int nt = 0; nt < 4; nt++) {
            int c = wn + nt * 8 + gid;
            bhf[nt][0] = Bh[cur][tg    ][c]; blf[nt][0] = Bl[cur][tg    ][c];
            bhf[nt][1] = Bh[cur][tg + 4][c]; blf[nt][1] = Bl[cur][tg + 4][c];
        }
        #pragma unroll
        for (int mt = 0; mt < 4; mt++)
            #pragma unroll
            for (int nt = 0; nt < 4; nt++) {
                MMA_BF16(acc[mt][nt], ahf[mt], bhf[nt]);
                MMA_BF16(acc[mt][nt], ahf[mt], blf[nt]);
                MMA_BF16(acc[mt][nt], alf[mt], bhf[nt]);
            }

        if (t + 1 < ntiles) { storeS(cur ^ 1); __syncthreads(); }
    }

    #pragma unroll
    for (int mt = 0; mt < 4; mt++) {
        int r0 = bm + wm + mt * 16 + gid;
        #pragma unroll
        for (int nt = 0; nt < 4; nt++) {
            int c = bn + wn + nt * 8 + tg * 2;
            float b0 = HASBIAS ? __ldg(&bias[c])     : 0.f;
            float b1 = HASBIAS ? __ldg(&bias[c + 1]) : 0.f;
            if (r0 < M) {
                float v0 = acc[mt][nt][0] + b0, v1 = acc[mt][nt][1] + b1;
                if (ELU) { v0 = elu1(v0); v1 = elu1(v1); }
                *(float2*)&C[(size_t)r0 * N + c] = make_float2(v0, v1);
            }
            if (r0 + 8 < M) {
                float v2 = acc[mt][nt][2] + b0, v3 = acc[mt][nt][3] + b1;
                if (ELU) { v2 = elu1(v2); v3 = elu1(v3); }
                *(float2*)&C[(size_t)(r0 + 8) * N + c] = make_float2(v2, v3);
            }
        }
    }
}

// =============================================================================
//  gemm23_sel: fused  T = elu(elu(P[src]+Q[dst]+br1) @ Wr2 + br2)  (128x256)
//              then   sel = elu(T @ Wc + bc) . Wp2[:,lbl] + bp2
//  512 threads, dynamic smem; A2 never leaves the SM.
// =============================================================================
#define DSMEM_G23 193024

__global__ void __launch_bounds__(512)
gemm23_sel(const int* __restrict__ esrc, const int* __restrict__ edst,
           const float* __restrict__ Pm, const float* __restrict__ Qm,
           const float* __restrict__ br1, const float* __restrict__ br2,
           const float* __restrict__ Wp2, const float* __restrict__ bp2) {
    extern __shared__ char dsm[];
    uint32_t (*Th)[132] = (uint32_t(*)[132])(dsm);
    uint32_t (*Tl)[132] = (uint32_t(*)[132])(dsm + 67584);
    char* s1 = dsm + 135168;
    uint32_t (*Ah)[128][12] = (uint32_t(*)[128][12])(s1);
    uint32_t (*Al)[128][12] = (uint32_t(*)[128][12])(s1 + 12288);
    uint32_t (*Bh)[8][260]  = (uint32_t(*)[8][260]) (s1 + 24576);
    uint32_t (*Bl)[8][260]  = (uint32_t(*)[8][260]) (s1 + 41216);
    uint32_t (*B2h)[8][132] = (uint32_t(*)[8][132]) (s1);          // reuses stage-1 region
    uint32_t (*B2l)[8][132] = (uint32_t(*)[8][132]) (s1 + 8448);

    __shared__ float sW[1280];
    __shared__ float sbc[128];
    __shared__ float sbr2[256];
    __shared__ float red[128][2];

    const int tid = threadIdx.x;
    const int bm = blockIdx.x * 128;
    const int wid = tid >> 5, lane = tid & 31;
    const int gid = lane >> 2, tg = lane & 3;

    if (tid < 128) sbc[tid] = g_bc[tid];
    if (tid < 256) sbr2[tid] = br2[tid];
    for (int i = tid; i < 1280; i += 512) sW[i] = Wp2[i];

    // ---------------- stage 1 ----------------
    const int wm1 = (wid >> 1) * 16;
    const int wn1 = (wid & 1) * 128;

    const int arow = tid >> 2;
    const int af   = (tid & 3) * 4;
    const int akp  = (tid & 3) * 2;
    const int bkp  = tid >> 6;
    const int bc4  = (tid & 63) * 4;

    const int src = __ldg(&esrc[bm + arow]);
    const int dst = __ldg(&edst[bm + arow]);

    uint32_t ah0, ah1, al0, al1;
    uint4 pbh, pbl;
    auto loadG1 = [&](int k0) {
        float4 p = *(const float4*)&Pm[(size_t)src * 512 + k0 + af];
        float4 q = *(const float4*)&Qm[(size_t)dst * 512 + k0 + af];
        float4 b = *(const float4*)&br1[k0 + af];
        float e0 = elu1(p.x + q.x + b.x), e1 = elu1(p.y + q.y + b.y);
        float e2 = elu1(p.z + q.z + b.z), e3 = elu1(p.w + q.w + b.w);
        cvt_pair(e0, e1, ah0, al0);
        cvt_pair(e2, e3, ah1, al1);
        int kpg = (k0 >> 1) + bkp;
        pbh = *(const uint4*)&g_W2h[kpg * 256 + bc4];
        pbl = *(const uint4*)&g_W2l[kpg * 256 + bc4];
    };
    auto storeS1 = [&](int buf) {
        Ah[buf][arow][akp]     = ah0;
        Ah[buf][arow][akp + 1] = ah1;
        Al[buf][arow][akp]     = al0;
        Al[buf][arow][akp + 1] = al1;
        *(uint4*)&Bh[buf][bkp][bc4] = pbh;
        *(uint4*)&Bl[buf][bkp][bc4] = pbl;
    };

    float acc[16][4];
    #pragma unroll
    for (int i = 0; i < 16; i++)
        #pragma unroll
        for (int r = 0; r < 4; r++) acc[i][r] = 0.f;

    loadG1(0); storeS1(0); __syncthreads();

    for (int t = 0; t < 32; t++) {
        const int cur = t & 1;
        if (t + 1 < 32) loadG1((t + 1) << 4);

        uint32_t Af[4], Afl[4];
        {
            int r0 = wm1 + gid;
            Af[0]  = Ah[cur][r0    ][tg];     Af[1]  = Ah[cur][r0 + 8][tg];
            Af[2]  = Ah[cur][r0    ][tg + 4]; Af[3]  = Ah[cur][r0 + 8][tg + 4];
            Afl[0] = Al[cur][r0    ][tg];     Afl[1] = Al[cur][r0 + 8][tg];
            Afl[2] = Al[cur][r0    ][tg + 4]; Afl[3] = Al[cur][r0 + 8][tg + 4];
        }
        #pragma unroll
        for (int nt = 0; nt < 16; nt++) {
            int c = wn1 + nt * 8 + gid;
            uint32_t bh[2], bl[2];
            bh[0] = Bh[cur][tg][c]; bh[1] = Bh[cur][tg + 4][c];
            bl[0] = Bl[cur][tg][c]; bl[1] = Bl[cur][tg + 4][c];
            MMA_BF16(acc[nt], Af, bh);
            MMA_BF16(acc[nt], Af, bl);
            MMA_BF16(acc[nt], Afl, bh);
        }
        if (t + 1 < 32) { storeS1(cur ^ 1); __syncthreads(); }
    }

    // pack T = elu(acc + br2) into Th/Tl (bf16 hi/lo, k-pairs)
    {
        int r0 = wm1 + gid, r1 = r0 + 8;
        #pragma unroll
        for (int nt = 0; nt < 16; nt++) {
            int c = wn1 + nt * 8 + tg * 2;
            float e0 = elu1(acc[nt][0] + sbr2[c]);
            float e1 = elu1(acc[nt][1] + sbr2[c + 1]);
            float e2 = elu1(acc[nt][2] + sbr2[c]);
            float e3 = elu1(acc[nt][3] + sbr2[c + 1]);
            uint32_t h, l;
            cvt_pair(e0, e1, h, l); Th[r0][c >> 1] = h; Tl[r0][c >> 1] = l;
            cvt_pair(e2, e3, h, l); Th[r1][c >> 1] = h; Tl[r1][c >> 1] = l;
        }
    }
    __syncthreads();   // T complete; stage-1 buffers may now be overwritten

    // ---------------- stage 2 ----------------
    const int wm2 = (wid >> 1) * 16;
    const int wn2 = (wid & 1) * 64;
    const int b2kp = tid >> 6;
    const int b2c  = (tid & 63) * 2;

    uint2 qbh, qbl;
    auto loadG2 = [&](int s) {
        int kpg = s * 8 + b2kp;
        qbh = *(const uint2*)&g_Wch[kpg * 128 + b2c];
        qbl = *(const uint2*)&g_Wcl[kpg * 128 + b2c];
    };
    auto storeS2 = [&](int buf) {
        *(uint2*)&B2h[buf][b2kp][b2c] = qbh;
        *(uint2*)&B2l[buf][b2kp][b2c] = qbl;
    };

    float acc2[8][4];
    #pragma unroll
    for (int i = 0; i < 8; i++)
        #pragma unroll
        for (int r = 0; r < 4; r++) acc2[i][r] = 0.f;

    loadG2(0); storeS2(0); __syncthreads();

    for (int s = 0; s < 16; s++) {
        const int cur = s & 1;
        if (s + 1 < 16) loadG2(s + 1);

        uint32_t Af[4], Afl[4];
        {
            int r0 = wm2 + gid, kb = s * 8;
            Af[0]  = Th[r0    ][kb + tg];     Af[1]  = Th[r0 + 8][kb + tg];
            Af[2]  = Th[r0    ][kb + tg + 4]; Af[3]  = Th[r0 + 8][kb + tg + 4];
            Afl[0] = Tl[r0    ][kb + tg];     Afl[1] = Tl[r0 + 8][kb + tg];
            Afl[2] = Tl[r0    ][kb + tg + 4]; Afl[3] = Tl[r0 + 8][kb + tg + 4];
        }
        #pragma unroll
        for (int nt = 0; nt < 8; nt++) {
            int c = wn2 + nt * 8 + gid;
            uint32_t bh[2], bl[2];
            bh[0] = B2h[cur][tg][c]; bh[1] = B2h[cur][tg + 4][c];
            bl[0] = B2l[cur][tg][c]; bl[1] = B2l[cur][tg + 4][c];
            MMA_BF16(acc2[nt], Af, bh);
            MMA_BF16(acc2[nt], Af, bl);
            MMA_BF16(acc2[nt], Afl, bh);
        }
        if (s + 1 < 16) { storeS2(cur ^ 1); __syncthreads(); }
    }

    // epilogue: h = elu(acc2 + bc); per-row dot with Wp2[:, lbl]
    {
        int r0 = wm2 + gid, r1 = r0 + 8;
        int lbl0 = g_lbl[bm + r0], lbl1 = g_lbl[bm + r1];
        float p0 = 0.f, p1 = 0.f;
        #pragma unroll
        for (int nt = 0; nt < 8; nt++) {
            int c = wn2 + nt * 8 + tg * 2;
            float h;
            h = elu1(acc2[nt][0] + sbc[c]);     p0 += h * sW[c * 10 + lbl0];
            h = elu1(acc2[nt][1] + sbc[c + 1]); p0 += h * sW[(c + 1) * 10 + lbl0];
            h = elu1(acc2[nt][2] + sbc[c]);     p1 += h * sW[c * 10 + lbl1];
            h = elu1(acc2[nt][3] + sbc[c + 1]); p1 += h * sW[(c + 1) * 10 + lbl1];
        }
        p0 += __shfl_xor_sync(0xffffffffu, p0, 1);
        p0 += __shfl_xor_sync(0xffffffffu, p0, 2);
        p1 += __shfl_xor_sync(0xffffffffu, p1, 1);
        p1 += __shfl_xor_sync(0xffffffffu, p1, 2);
        if (tg == 0) { red[r0][wid & 1] = p0; red[r1][wid & 1] = p1; }
    }
    __syncthreads();
    if (tid < 128)
        g_sel[bm + tid] = red[tid][0] + red[tid][1] + __ldg(&bp2[g_lbl[bm + tid]]);
}

// ---------------- edge scatter-add -------------------------------------------
__global__ void k_scatter(const int* __restrict__ ei) {
    long long t = (long long)blockIdx.x * blockDim.x + threadIdx.x;
    if (t >= (long long)NE * HD) return;
    int e = (int)(t >> 7), f = (int)(t & 127);
    int s = __ldg(&ei[e]);
    int d = __ldg(&ei[NE + e]);
    float v = g_Mm[(size_t)s * HD + f];
    atomicAdd(&g_aggF[(size_t)d * HD + f], v);
    if (e < NOCP) atomicAdd(&g_aggO[(size_t)d * HD + f], v);
}

// ---------------- D = elu(S+aggF+b) - elu(S+aggO+b) --------------------------
__global__ void k_D(const float* __restrict__ bg) {
    size_t i = (size_t)blockIdx.x * blockDim.x + threadIdx.x;
    if (i >= (size_t)NN * HD) return;
    int f = (int)(i & 127);
    float base = g_S[i] + bg[f];
    float xf = base + g_aggF[i];
    float xo = base + g_aggO[i];
    g_D[i] = elu1(xf) - elu1(xo);
}

// ---------------- segment reductions -----------------------------------------
__device__ __forceinline__ void atomMaxF(int* a, float v) {
    int iv = __float_as_int(v);
    if (iv >= 0) atomicMax(a, iv);
    else         atomicMin((unsigned int*)a, (unsigned int)iv);
}

__global__ void k_mx() {
    __shared__ int sm[NG];
    int tid = threadIdx.x;
    if (tid < NG) sm[tid] = (int)0xFF800000;
    __syncthreads();
    int e = blockIdx.x * blockDim.x + tid;
    if (e < EA) atomMaxF(&sm[g_seg[e]], g_sel[e]);
    __syncthreads();
    if (tid < NG) atomMaxF(&g_mx[tid], __int_as_float(sm[tid]));
}

__global__ void k_ex() {
    __shared__ float ss[NG];
    int tid = threadIdx.x;
    if (tid < NG) ss[tid] = 0.f;
    __syncthreads();
    int e = blockIdx.x * blockDim.x + tid;
    if (e < EA) {
        int g = g_seg[e];
        float v = expf(g_sel[e] - __int_as_float(g_mx[g]));
        g_ex[e] = v;
        atomicAdd(&ss[g], v);
    }
    __syncthreads();
    if (tid < NG && ss[tid] != 0.f) atomicAdd(&g_sum[tid], ss[tid]);
}

__global__ void k_probs(float* __restrict__ out) {
    __shared__ int sp[NG];
    int tid = threadIdx.x;
    if (tid < NG) sp[tid] = 0;
    __syncthreads();
    int e = blockIdx.x * blockDim.x + tid;
    if (e < EA) {
        int g = g_seg[e];
        float p = g_ex[e] / g_sum[g];
        out[e] = p;
        atomicMax(&sp[g], __float_as_int(p));
    }
    __syncthreads();
    if (tid < NG) atomicMax(&g_pm[tid], sp[tid]);
}

__global__ void k_added(const float* __restrict__ out) {
    int e = blockIdx.x * blockDim.x + threadIdx.x;
    if (e >= EA) return;
    int g = g_seg[e];
    if (__float_as_int(out[e]) == g_pm[g]) atomicMin(&g_added[g], e);
}

__global__ void k_tail(float* __restrict__ out) {
    int t = threadIdx.x;
    if (t < NG) {
        out[EA + t]      = __int_as_float(g_pm[t]);
        out[EA + NG + t] = (float)g_added[t];
    }
}

// ---------------- launch ------------------------------------------------------
extern "C" void kernel_launch(void* const* d_in, const int* in_sizes, int n_in,
                              void* d_out, int out_size) {
    const int pb = n_in - 13;
    const float* x      = (const float*)d_in[0];
    const int*   ei     = (const int*)  d_in[1];
    const int*   bv     = (const int*)  d_in[2];
    const int*   y      = (const int*)  d_in[3];
    const float* W_self = (const float*)d_in[pb + 0];
    const float* W_nbr  = (const float*)d_in[pb + 1];
    const float* b_gnn  = (const float*)d_in[pb + 2];
    const float* Wr1    = (const float*)d_in[pb + 3];
    const float* br1    = (const float*)d_in[pb + 4];
    const float* Wr2    = (const float*)d_in[pb + 5];
    const float* br2    = (const float*)d_in[pb + 6];
    const float* Wr3    = (const float*)d_in[pb + 7];
    const float* br3    = (const float*)d_in[pb + 8];
    const float* Wp1    = (const float*)d_in[pb + 9];
    const float* bp1    = (const float*)d_in[pb + 10];
    const float* Wp2    = (const float*)d_in[pb + 11];
    const float* bp2    = (const float*)d_in[pb + 12];
    float* out = (float*)d_out;

    void *pS, *pM, *pP, *pQ, *pD;
    cudaGetSymbolAddress(&pS, g_S);
    cudaGetSymbolAddress(&pM, g_Mm);
    cudaGetSymbolAddress(&pP, g_P);
    cudaGetSymbolAddress(&pQ, g_Q);
    cudaGetSymbolAddress(&pD, g_D);

    static int smem_set = 0;
    if (!smem_set) {
        cudaFuncSetAttribute(gemm23_sel, cudaFuncAttributeMaxDynamicSharedMemorySize, DSMEM_G23);
        smem_set = 1;
    }

    const int T = 256;

    k_init <<<(NN * HD + T - 1) / T, T>>>();
    k_wc   <<<(256 * 128 + T - 1) / T, T>>>(Wr3, br3, Wp1, bp1);
    k_packc<<<(128 * 128 + T - 1) / T, T>>>();
    k_pack2<<<(256 * 256 + T - 1) / T, T>>>(Wr2);
    k_seg  <<<(EA + T - 1) / T, T>>>(ei, bv, y);

    // node transform GEMMs: S = x@W_self, M = x@W_nbr
    {
        dim3 grid(1, (NN + 127) / 128);
        tgemm<false, false><<<grid, T>>>(x, W_self, nullptr, (float*)pS, NN, HD, HD);
        tgemm<false, false><<<grid, T>>>(x, W_nbr,  nullptr, (float*)pM, NN, HD, HD);
    }
    k_scatter<<<(int)(((long long)NE * HD + T - 1) / T), T>>>(ei);
    k_D<<<(NN * HD + T - 1) / T, T>>>(b_gnn);

    // node-space hoist of GEMM1: P = D@Wr1[0:128,:], Q = D@Wr1[128:256,:]
    {
        dim3 grid(4, (NN + 127) / 128);
        tgemm<false, false><<<grid, T>>>((const float*)pD, Wr1,             nullptr, (float*)pP, NN, 512, HD);
        tgemm<false, false><<<grid, T>>>((const float*)pD, Wr1 + 128 * 512, nullptr, (float*)pQ, NN, 512, HD);
    }

    // fused GEMM2 + GEMM3 + sel (A2 stays on-chip)
    gemm23_sel<<<EA / 128, 512, DSMEM_G23>>>(
        ei + NOCP, ei + NE + NOCP, (const float*)pP, (const float*)pQ,
        br1, br2, Wp2, bp2);

    // segment softmax + argmax
    const int segBlocks = (EA + T - 1) / T;
    k_mx   <<<segBlocks, T>>>();
    k_ex   <<<segBlocks, T>>>();
    k_probs<<<segBlocks, T>>>(out);
    k_added<<<segBlocks, T>>>(out);
    k_tail <<<1, 64>>>(out);
}

// round 7
// speedup vs baseline: 1.9904x; 1.0418x over previous
#include <cuda_runtime.h>
#include <cuda_bf16.h>
#include <math.h>
#include <stdint.h>

#define NN   50000
#define NE   262144
#define NOCP 32768
#define EA   (NE - NOCP)      // 229376
#define NG   64
#define HD   128

// ---------------- scratch ----------------------------------------------------
__device__ float g_S   [NN * HD];
__device__ float g_Mm  [NN * HD];
__device__ float g_aggF[NN * HD];
__device__ float g_aggO[NN * HD];
__device__ float g_D   [NN * HD];
__device__ float g_P   [(size_t)NN * 512];
__device__ float g_Q   [(size_t)NN * 512];
__device__ float g_sel [EA];
__device__ float g_ex  [EA];
__device__ int   g_seg [EA];
__device__ int   g_lbl [EA];
__device__ float g_Wc  [256 * 128];
__device__ float g_bc  [128];
__device__ uint32_t g_W2h[256 * 256];   // Wr2 packed bf16 hi/lo planes (kp x 256)
__device__ uint32_t g_W2l[256 * 256];
__device__ uint32_t g_Wch[128 * 128];   // Wc planes (kp x 128)
__device__ uint32_t g_Wcl[128 * 128];
__device__ uint32_t g_W1h[128 * 512];   // Wr1 planes (kp x 512); kp<64 top, kp>=64 bottom
__device__ uint32_t g_W1l[128 * 512];
__device__ int   g_mx  [NG];
__device__ float g_sum [NG];
__device__ int   g_pm  [NG];
__device__ int   g_added[NG];

// ---------------- helpers -----------------------------------------------------
__device__ __forceinline__ void cvt_pair(float f0, float f1, uint32_t& h, uint32_t& l) {
    __nv_bfloat162 H = __floats2bfloat162_rn(f0, f1);
    float2 Hf = __bfloat1622float2(H);
    __nv_bfloat162 L = __floats2bfloat162_rn(f0 - Hf.x, f1 - Hf.y);
    h = *(uint32_t*)&H;
    l = *(uint32_t*)&L;
}
__device__ __forceinline__ float elu1(float v) { return (v > 0.f) ? v : expm1f(v); }

#define MMA_BF16(d, a, b)                                                     \
    asm volatile(                                                             \
        "mma.sync.aligned.m16n8k16.row.col.f32.bf16.bf16.f32 "                \
        "{%0,%1,%2,%3}, {%4,%5,%6,%7}, {%8,%9}, {%0,%1,%2,%3};\n"             \
        : "+f"((d)[0]), "+f"((d)[1]), "+f"((d)[2]), "+f"((d)[3])              \
        : "r"((a)[0]), "r"((a)[1]), "r"((a)[2]), "r"((a)[3]),                 \
          "r"((b)[0]), "r"((b)[1]))

__device__ __forceinline__ void atomMaxF(int* a, float v) {
    int iv = __float_as_int(v);
    if (iv >= 0) atomicMax(a, iv);
    else         atomicMin((unsigned int*)a, (unsigned int)iv);
}

// ---------------- init --------------------------------------------------------
__global__ void k_init() {
    size_t i = (size_t)blockIdx.x * blockDim.x + threadIdx.x;
    if (i < (size_t)NN * HD) { g_aggF[i] = 0.f; g_aggO[i] = 0.f; }
    if (blockIdx.x == 0 && threadIdx.x < NG) {
        g_mx[threadIdx.x]    = (int)0xFF800000;
        g_sum[threadIdx.x]   = 0.f;
        g_pm[threadIdx.x]    = 0;
        g_added[threadIdx.x] = EA;
    }
}

// ---------------- Wc = Wr3 @ Wp1, bc = br3 @ Wp1 + bp1 -------------------------
__global__ void k_wc(const float* __restrict__ Wr3, const float* __restrict__ br3,
                     const float* __restrict__ Wp1, const float* __restrict__ bp1) {
    int t = blockIdx.x * blockDim.x + threadIdx.x;
    if (t >= 256 * 128) return;
    int k = t >> 7, c = t & 127;
    float s = 0.f;
    #pragma unroll 8
    for (int m = 0; m < 128; m++) s += Wr3[k * 128 + m] * Wp1[m * 128 + c];
    g_Wc[t] = s;
    if (t < 128) {
        float b = bp1[t];
        #pragma unroll 8
        for (int m = 0; m < 128; m++) b += br3[m] * Wp1[m * 128 + t];
        g_bc[t] = b;
    }
}

// ---------------- pack static B matrices --------------------------------------
__global__ void k_pack2(const float* __restrict__ Wr2) {
    int t = blockIdx.x * blockDim.x + threadIdx.x;
    if (t >= 256 * 256) return;
    int kp = t >> 8, c = t & 255;
    uint32_t h, l;
    cvt_pair(Wr2[(2 * kp) * 256 + c], Wr2[(2 * kp + 1) * 256 + c], h, l);
    g_W2h[t] = h; g_W2l[t] = l;
}
__global__ void k_packc() {
    int t = blockIdx.x * blockDim.x + threadIdx.x;
    if (t >= 128 * 128) return;
    int kp = t >> 7, c = t & 127;
    uint32_t h, l;
    cvt_pair(g_Wc[(2 * kp) * 128 + c], g_Wc[(2 * kp + 1) * 128 + c], h, l);
    g_Wch[t] = h; g_Wcl[t] = l;
}
__global__ void k_pack1(const float* __restrict__ Wr1) {
    int t = blockIdx.x * blockDim.x + threadIdx.x;
    if (t >= 128 * 512) return;
    int kp = t >> 9, c = t & 511;
    uint32_t h, l;
    cvt_pair(Wr1[(2 * kp) * 512 + c], Wr1[(2 * kp + 1) * 512 + c], h, l);
    g_W1h[t] = h; g_W1l[t] = l;
}

// ---------------- per-edge segment / label precompute --------------------------
__global__ void k_seg(const int* __restrict__ ei, const int* __restrict__ bv,
                      const int* __restrict__ y) {
    int e = blockIdx.x * blockDim.x + threadIdx.x;
    if (e >= EA) return;
    int s = __ldg(&ei[NOCP + e]);
    int g = __ldg(&bv[s]);
    g_seg[e] = g;
    g_lbl[e] = __ldg(&y[g]);
}

// =============================================================================
//   BF16x3 dense GEMM (128x128 tile, 256 thr) — used for S/M node transforms
// =============================================================================
#define ASTR 12
#define BSTR 132

template <bool ELU, bool HASBIAS>
__global__ void __launch_bounds__(256)
tgemm(const float* __restrict__ A, const float* __restrict__ B,
      const float* __restrict__ bias, float* __restrict__ C,
      int M, int N, int K) {
    __shared__ uint32_t Ah[2][128][ASTR], Al[2][128][ASTR];
    __shared__ uint32_t Bh[2][8][BSTR],  Bl[2][8][BSTR];

    const int tid = threadIdx.x;
    const int bm = blockIdx.y * 128;
    const int bn = blockIdx.x * 128;

    const int wid = tid >> 5, lane = tid & 31;
    const int gid = lane >> 2, tg = lane & 3;
    const int wm = (wid >> 2) * 64, wn = (wid & 3) * 32;

    const int arow = tid >> 1,  acq = (tid & 1) * 8;
    const int bkp  = tid >> 5,  bnq = (tid & 31) * 4;

    float4 pa0, pa1, pb0, pb1;
    auto loadG = [&](int k0) {
        int gr = bm + arow;
        if (gr < M) {
            pa0 = *(const float4*)&A[(size_t)gr * K + k0 + acq];
            pa1 = *(const float4*)&A[(size_t)gr * K + k0 + acq + 4];
        } else {
            pa0 = make_float4(0.f, 0.f, 0.f, 0.f); pa1 = pa0;
        }
        pb0 = *(const float4*)&B[(size_t)(k0 + 2 * bkp)     * N + bn + bnq];
        pb1 = *(const float4*)&B[(size_t)(k0 + 2 * bkp + 1) * N + bn + bnq];
    };
    auto storeS = [&](int buf) {
        uint32_t h0, h1, h2, h3, l0, l1, l2, l3;
        cvt_pair(pa0.x, pa0.y, h0, l0);
        cvt_pair(pa0.z, pa0.w, h1, l1);
        cvt_pair(pa1.x, pa1.y, h2, l2);
        cvt_pair(pa1.z, pa1.w, h3, l3);
        int kp = acq >> 1;
        *(uint4*)&Ah[buf][arow][kp] = make_uint4(h0, h1, h2, h3);
        *(uint4*)&Al[buf][arow][kp] = make_uint4(l0, l1, l2, l3);
        cvt_pair(pb0.x, pb1.x, h0, l0);
        cvt_pair(pb0.y, pb1.y, h1, l1);
        cvt_pair(pb0.z, pb1.z, h2, l2);
        cvt_pair(pb0.w, pb1.w, h3, l3);
        *(uint4*)&Bh[buf][bkp][bnq] = make_uint4(h0, h1, h2, h3);
        *(uint4*)&Bl[buf][bkp][bnq] = make_uint4(l0, l1, l2, l3);
    };

    float acc[4][4][4];
    #pragma unroll
    for (int i = 0; i < 4; i++)
        #pragma unroll
        for (int j = 0; j < 4; j++)
            #pragma unroll
            for (int r = 0; r < 4; r++) acc[i][j][r] = 0.f;

    loadG(0); storeS(0); __syncthreads();

    const int ntiles = K >> 4;
    for (int t = 0; t < ntiles; t++) {
        const int cur = t & 1;
        if (t + 1 < ntiles) loadG((t + 1) << 4);

        uint32_t ahf[4][4], alf[4][4], bhf[4][2], blf[4][2];
        #pragma unroll
        for (int mt = 0; mt < 4; mt++) {
            int r0 = wm + mt * 16 + gid;
            ahf[mt][0] = Ah[cur][r0    ][tg    ]; alf[mt][0] = Al[cur][r0    ][tg    ];
            ahf[mt][1] = Ah[cur][r0 + 8][tg    ]; alf[mt][1] = Al[cur][r0 + 8][tg    ];
            ahf[mt][2] = Ah[cur][r0    ][tg + 4]; alf[mt][2] = Al[cur][r0    ][tg + 4];
            ahf[mt][3] = Ah[cur][r0 + 8][tg + 4]; alf[mt][3] = Al[cur][r0 + 8][tg + 4];
        }
        #pragma unroll
        for (int nt = 0; nt < 4; nt++) {
            int c = wn + nt * 8 + gid;
            bhf[nt][0] = Bh[cur][tg    ][c]; blf[nt][0] = Bl[cur][tg    ][c];
            bhf[nt][1] = Bh[cur][tg + 4][c]; blf[nt][1] = Bl[cur][tg + 4][c];
        }
        #pragma unroll
        for (int mt = 0; mt < 4; mt++)
            #pragma unroll
            for (int nt = 0; nt < 4; nt++) {
                MMA_BF16(acc[mt][nt], ahf[mt], bhf[nt]);
                MMA_BF16(acc[mt][nt], ahf[mt], blf[nt]);
                MMA_BF16(acc[mt][nt], alf[mt], bhf[nt]);
            }

        if (t + 1 < ntiles) { storeS(cur ^ 1); __syncthreads(); }
    }

    #pragma unroll
    for (int mt = 0; mt < 4; mt++) {
        int r0 = bm + wm + mt * 16 + gid;
        #pragma unroll
        for (int nt = 0; nt < 4; nt++) {
            int c = bn + wn + nt * 8 + tg * 2;
            float b0 = HASBIAS ? __ldg(&bias[c])     : 0.f;
            float b1 = HASBIAS ? __ldg(&bias[c + 1]) : 0.f;
            if (r0 < M) {
                float v0 = acc[mt][nt][0] + b0, v1 = acc[mt][nt][1] + b1;
                if (ELU) { v0 = elu1(v0); v1 = elu1(v1); }
                *(float2*)&C[(size_t)r0 * N + c] = make_float2(v0, v1);
            }
            if (r0 + 8 < M) {
                float v2 = acc[mt][nt][2] + b0, v3 = acc[mt][nt][3] + b1;
                if (ELU) { v2 = elu1(v2); v3 = elu1(v3); }
                *(float2*)&C[(size_t)(r0 + 8) * N + c] = make_float2(v2, v3);
            }
        }
    }
}

// =============================================================================
//  tgemm_wide: dense 128x256 tile, 512 threads, K=128; A=D (fp32), B=packed Wr1
//  blockIdx.z: 0 -> P (kp offset 0), 1 -> Q (kp offset 64)
// =============================================================================
#define DSMEM_WIDE 57856

__global__ void __launch_bounds__(512)
tgemm_wide(const float* __restrict__ A, float* __restrict__ P, float* __restrict__ Q,
           int M) {
    extern __shared__ char dsm[];
    uint32_t (*Ah)[128][12]  = (uint32_t(*)[128][12])(dsm);
    uint32_t (*Al)[128][12]  = (uint32_t(*)[128][12])(dsm + 12288);
    uint32_t (*Bh)[8][260]   = (uint32_t(*)[8][260]) (dsm + 24576);
    uint32_t (*Bl)[8][260]   = (uint32_t(*)[8][260]) (dsm + 41216);

    const int tid = threadIdx.x;
    const int bm = blockIdx.y * 128;
    const int bn = blockIdx.x * 256;
    const int kpoff = blockIdx.z * 64;
    float* C = blockIdx.z ? Q : P;

    const int wid = tid >> 5, lane = tid & 31;
    const int gid = lane >> 2, tg = lane & 3;
    const int wr = wid >> 2, wc = wid & 3;

    const int arow = tid >> 2;
    const int af   = (tid & 3) * 4;
    const int akp  = (tid & 3) * 2;
    const int bkp  = tid >> 6;
    const int bc4  = (tid & 63) * 4;

    uint32_t ah0, ah1, al0, al1;
    uint4 pbh, pbl;
    auto loadG = [&](int k0) {
        int gr = bm + arow;
        float4 a = (gr < M) ? *(const float4*)&A[(size_t)gr * 128 + k0 + af]
                            : make_float4(0.f, 0.f, 0.f, 0.f);
        cvt_pair(a.x, a.y, ah0, al0);
        cvt_pair(a.z, a.w, ah1, al1);
        int kpg = kpoff + (k0 >> 1) + bkp;
        pbh = *(const uint4*)&g_W1h[kpg * 512 + bn + bc4];
        pbl = *(const uint4*)&g_W1l[kpg * 512 + bn + bc4];
    };
    auto storeS = [&](int buf) {
        Ah[buf][arow][akp]     = ah0;
        Ah[buf][arow][akp + 1] = ah1;
        Al[buf][arow][akp]     = al0;
        Al[buf][arow][akp + 1] = al1;
        *(uint4*)&Bh[buf][bkp][bc4] = pbh;
        *(uint4*)&Bl[buf][bkp][bc4] = pbl;
    };

    float acc[2][8][4];
    #pragma unroll
    for (int i = 0; i < 2; i++)
        #pragma unroll
        for (int j = 0; j < 8; j++)
            #pragma unroll
            for (int r = 0; r < 4; r++) acc[i][j][r] = 0.f;

    loadG(0); storeS(0); __syncthreads();

    for (int t = 0; t < 8; t++) {
        const int cur = t & 1;
        if (t + 1 < 8) loadG((t + 1) << 4);

        uint32_t ahf[2][4], alf[2][4];
        #pragma unroll
        for (int mt = 0; mt < 2; mt++) {
            int r0 = wr * 32 + mt * 16 + gid;
            ahf[mt][0] = Ah[cur][r0    ][tg];     alf[mt][0] = Al[cur][r0    ][tg];
            ahf[mt][1] = Ah[cur][r0 + 8][tg];     alf[mt][1] = Al[cur][r0 + 8][tg];
            ahf[mt][2] = Ah[cur][r0    ][tg + 4]; alf[mt][2] = Al[cur][r0    ][tg + 4];
            ahf[mt][3] = Ah[cur][r0 + 8][tg + 4]; alf[mt][3] = Al[cur][r0 + 8][tg + 4];
        }
        #pragma unroll
        for (int nt = 0; nt < 8; nt++) {
            int c = wc * 64 + nt * 8 + gid;
            uint32_t bh[2], bl[2];
            bh[0] = Bh[cur][tg][c]; bh[1] = Bh[cur][tg + 4][c];
            bl[0] = Bl[cur][tg][c]; bl[1] = Bl[cur][tg + 4][c];
            #pragma unroll
            for (int mt = 0; mt < 2; mt++) {
                MMA_BF16(acc[mt][nt], ahf[mt], bh);
                MMA_BF16(acc[mt][nt], ahf[mt], bl);
                MMA_BF16(acc[mt][nt], alf[mt], bh);
            }
        }
        if (t + 1 < 8) { storeS(cur ^ 1); __syncthreads(); }
    }

    #pragma unroll
    for (int mt = 0; mt < 2; mt++) {
        int ra = bm + wr * 32 + mt * 16 + gid;
        #pragma unroll
        for (int nt = 0; nt < 8; nt++) {
            int c = bn + wc * 64 + nt * 8 + tg * 2;
            if (ra < M)
                *(float2*)&C[(size_t)ra * 512 + c] = make_float2(acc[mt][nt][0], acc[mt][nt][1]);
            if (ra + 8 < M)
                *(float2*)&C[(size_t)(ra + 8) * 512 + c] = make_float2(acc[mt][nt][2], acc[mt][nt][3]);
        }
    }
}

// =============================================================================
//  gemm23_sel: T = elu(elu(P[src]+Q[dst]+br1) @ Wr2 + br2)  (128x256, on-chip)
//              sel = elu(T @ Wc + bc) . Wp2[:,lbl] + bp2; fused segment-max
// =============================================================================
#define DSMEM_G23 193024

__global__ void __launch_bounds__(512)
gemm23_sel(const int* __restrict__ esrc, const int* __restrict__ edst,
           const float* __restrict__ Pm, const float* __restrict__ Qm,
           const float* __restrict__ br1, const float* __restrict__ br2,
           const float* __restrict__ Wp2, const float* __restrict__ bp2) {
    extern __shared__ char dsm[];
    uint32_t (*Th)[132] = (uint32_t(*)[132])(dsm);
    uint32_t (*Tl)[132] = (uint32_t(*)[132])(dsm + 67584);
    char* s1 = dsm + 135168;
    uint32_t (*Ah)[128][12] = (uint32_t(*)[128][12])(s1);
    uint32_t (*Al)[128][12] = (uint32_t(*)[128][12])(s1 + 12288);
    uint32_t (*Bh)[8][260]  = (uint32_t(*)[8][260]) (s1 + 24576);
    uint32_t (*Bl)[8][260]  = (uint32_t(*)[8][260]) (s1 + 41216);
    uint32_t (*B2h)[8][132] = (uint32_t(*)[8][132]) (s1);          // reuses stage-1 region
    uint32_t (*B2l)[8][132] = (uint32_t(*)[8][132]) (s1 + 8448);

    __shared__ float sW[1280];
    __shared__ float sbc[128];
    __shared__ float sbr2[256];
    __shared__ float red[128][4];
    __shared__ int   smx[NG];

    const int tid = threadIdx.x;
    const int bm = blockIdx.x * 128;
    const int wid = tid >> 5, lane = tid & 31;
    const int gid = lane >> 2, tg = lane & 3;
    const int wr = wid >> 2, wc = wid & 3;

    if (tid < 128) sbc[tid] = g_bc[tid];
    if (tid < 256) sbr2[tid] = br2[tid];
    if (tid < NG)  smx[tid] = (int)0xFF800000;
    for (int i = tid; i < 1280; i += 512) sW[i] = Wp2[i];

    // ---------------- stage 1 (K=512, N=256) ----------------
    const int arow = tid >> 2;
    const int af   = (tid & 3) * 4;
    const int akp  = (tid & 3) * 2;
    const int bkp  = tid >> 6;
    const int bc4  = (tid & 63) * 4;

    const int src = __ldg(&esrc[bm + arow]);
    const int dst = __ldg(&edst[bm + arow]);

    uint32_t ah0, ah1, al0, al1;
    uint4 pbh, pbl;
    auto loadG1 = [&](int k0) {
        float4 p = *(const float4*)&Pm[(size_t)src * 512 + k0 + af];
        float4 q = *(const float4*)&Qm[(size_t)dst * 512 + k0 + af];
        float4 b = *(const float4*)&br1[k0 + af];
        float e0 = elu1(p.x + q.x + b.x), e1 = elu1(p.y + q.y + b.y);
        float e2 = elu1(p.z + q.z + b.z), e3 = elu1(p.w + q.w + b.w);
        cvt_pair(e0, e1, ah0, al0);
        cvt_pair(e2, e3, ah1, al1);
        int kpg = (k0 >> 1) + bkp;
        pbh = *(const uint4*)&g_W2h[kpg * 256 + bc4];
        pbl = *(const uint4*)&g_W2l[kpg * 256 + bc4];
    };
    auto storeS1 = [&](int buf) {
        Ah[buf][arow][akp]     = ah0;
        Ah[buf][arow][akp + 1] = ah1;
        Al[buf][arow][akp]     = al0;
        Al[buf][arow][akp + 1] = al1;
        *(uint4*)&Bh[buf][bkp][bc4] = pbh;
        *(uint4*)&Bl[buf][bkp][bc4] = pbl;
    };

    float acc[2][8][4];
    #pragma unroll
    for (int i = 0; i < 2; i++)
        #pragma unroll
        for (int j = 0; j < 8; j++)
            #pragma unroll
            for (int r = 0; r < 4; r++) acc[i][j][r] = 0.f;

    loadG1(0); storeS1(0); __syncthreads();

    for (int t = 0; t < 32; t++) {
        const int cur = t & 1;
        if (t + 1 < 32) loadG1((t + 1) << 4);

        uint32_t ahf[2][4], alf[2][4];
        #pragma unroll
        for (int mt = 0; mt < 2; mt++) {
            int r0 = wr * 32 + mt * 16 + gid;
            ahf[mt][0] = Ah[cur][r0    ][tg];     alf[mt][0] = Al[cur][r0    ][tg];
            ahf[mt][1] = Ah[cur][r0 + 8][tg];     alf[mt][1] = Al[cur][r0 + 8][tg];
            ahf[mt][2] = Ah[cur][r0    ][tg + 4]; alf[mt][2] = Al[cur][r0    ][tg + 4];
            ahf[mt][3] = Ah[cur][r0 + 8][tg + 4]; alf[mt][3] = Al[cur][r0 + 8][tg + 4];
        }
        #pragma unroll
        for (int nt = 0; nt < 8; nt++) {
            int c = wc * 64 + nt * 8 + gid;
            uint32_t bh[2], bl[2];
            bh[0] = Bh[cur][tg][c]; bh[1] = Bh[cur][tg + 4][c];
            bl[0] = Bl[cur][tg][c]; bl[1] = Bl[cur][tg + 4][c];
            #pragma unroll
            for (int mt = 0; mt < 2; mt++) {
                MMA_BF16(acc[mt][nt], ahf[mt], bh);
                MMA_BF16(acc[mt][nt], ahf[mt], bl);
                MMA_BF16(acc[mt][nt], alf[mt], bh);
            }
        }
        if (t + 1 < 32) { storeS1(cur ^ 1); __syncthreads(); }
    }

    // pack T = elu(acc + br2) into Th/Tl
    #pragma unroll
    for (int mt = 0; mt < 2; mt++) {
        int ra = wr * 32 + mt * 16 + gid, rb = ra + 8;
        #pragma unroll
        for (int nt = 0; nt < 8; nt++) {
            int c = wc * 64 + nt * 8 + tg * 2;
            float e0 = elu1(acc[mt][nt][0] + sbr2[c]);
            float e1 = elu1(acc[mt][nt][1] + sbr2[c + 1]);
            float e2 = elu1(acc[mt][nt][2] + sbr2[c]);
            float e3 = elu1(acc[mt][nt][3] + sbr2[c + 1]);
            uint32_t h, l;
            cvt_pair(e0, e1, h, l); Th[ra][c >> 1] = h; Tl[ra][c >> 1] = l;
            cvt_pair(e2, e3, h, l); Th[rb][c >> 1] = h; Tl[rb][c >> 1] = l;
        }
    }
    __syncthreads();   // T complete; stage-1 buffers free

    // ---------------- stage 2 (K=256, N=128) ----------------
    const int b2kp = tid >> 6;
    const int b2c  = (tid & 63) * 2;

    uint2 qbh, qbl;
    auto loadG2 = [&](int s) {
        int kpg = s * 8 + b2kp;
        qbh = *(const uint2*)&g_Wch[kpg * 128 + b2c];
        qbl = *(const uint2*)&g_Wcl[kpg * 128 + b2c];
    };
    auto storeS2 = [&](int buf) {
        *(uint2*)&B2h[buf][b2kp][b2c] = qbh;
        *(uint2*)&B2l[buf][b2kp][b2c] = qbl;
    };

    float acc2[2][4][4];
    #pragma unroll
    for (int i = 0; i < 2; i++)
        #pragma unroll
        for (int j = 0; j < 4; j++)
            #pragma unroll
            for (int r = 0; r < 4; r++) acc2[i][j][r] = 0.f;

    loadG2(0); storeS2(0); __syncthreads();

    for (int s = 0; s < 16; s++) {
        const int cur = s & 1;
        if (s + 1 < 16) loadG2(s + 1);

        uint32_t ahf[2][4], alf[2][4];
        const int kb = s * 8;
        #pragma unroll
        for (int mt = 0; mt < 2; mt++) {
            int r0 = wr * 32 + mt * 16 + gid;
            ahf[mt][0] = Th[r0    ][kb + tg];     alf[mt][0] = Tl[r0    ][kb + tg];
            ahf[mt][1] = Th[r0 + 8][kb + tg];     alf[mt][1] = Tl[r0 + 8][kb + tg];
            ahf[mt][2] = Th[r0    ][kb + tg + 4]; alf[mt][2] = Tl[r0    ][kb + tg + 4];
            ahf[mt][3] = Th[r0 + 8][kb + tg + 4]; alf[mt][3] = Tl[r0 + 8][kb + tg + 4];
        }
        #pragma unroll
        for (int nt = 0; nt < 4; nt++) {
            int c = wc * 32 + nt * 8 + gid;
            uint32_t bh[2], bl[2];
            bh[0] = B2h[cur][tg][c]; bh[1] = B2h[cur][tg + 4][c];
            bl[0] = B2l[cur][tg][c]; bl[1] = B2l[cur][tg + 4][c];
            #pragma unroll
            for (int mt = 0; mt < 2; mt++) {
                MMA_BF16(acc2[mt][nt], ahf[mt], bh);
                MMA_BF16(acc2[mt][nt], ahf[mt], bl);
                MMA_BF16(acc2[mt][nt], alf[mt], bh);
            }
        }
        if (s + 1 < 16) { storeS2(cur ^ 1); __syncthreads(); }
    }

    // epilogue: h = elu(acc2 + bc); per-row dot with Wp2[:, lbl]
    #pragma unroll
    for (int mt = 0; mt < 2; mt++) {
        int ra = wr * 32 + mt * 16 + gid, rb = ra + 8;
        int lbla = g_lbl[bm + ra], lblb = g_lbl[bm + rb];
        float pa = 0.f, pb = 0.f;
        #pragma unroll
        for (int nt = 0; nt < 4; nt++) {
            int c = wc * 32 + nt * 8 + tg * 2;
            float h;
            h = elu1(acc2[mt][nt][0] + sbc[c]);     pa += h * sW[c * 10 + lbla];
            h = elu1(acc2[mt][nt][1] + sbc[c + 1]); pa += h * sW[(c + 1) * 10 + lbla];
            h = elu1(acc2[mt][nt][2] + sbc[c]);     pb += h * sW[c * 10 + lblb];
            h = elu1(acc2[mt][nt][3] + sbc[c + 1]); pb += h * sW[(c + 1) * 10 + lblb];
        }
        pa += __shfl_xor_sync(0xffffffffu, pa, 1);
        pa += __shfl_xor_sync(0xffffffffu, pa, 2);
        pb += __shfl_xor_sync(0xffffffffu, pb, 1);
        pb += __shfl_xor_sync(0xffffffffu, pb, 2);
        if (tg == 0) { red[ra][wc] = pa; red[rb][wc] = pb; }
    }
    __syncthreads();
    if (tid < 128) {
        float s = red[tid][0] + red[tid][1] + red[tid][2] + red[tid][3]
                + __ldg(&bp2[g_lbl[bm + tid]]);
        g_sel[bm + tid] = s;
        atomMaxF(&smx[g_seg[bm + tid]], s);          // fused segment max
    }
    __syncthreads();
    if (tid < NG) {
        float v = __int_as_float(smx[tid]);
        if (v > -1e37f) atomMaxF(&g_mx[tid], v);
    }
}

// ---------------- edge scatter-add ---------------------------------------------
__global__ void k_scatter(const int* __restrict__ ei) {
    long long t = (long long)blockIdx.x * blockDim.x + threadIdx.x;
    if (t >= (long long)NE * HD) return;
    int e = (int)(t >> 7), f = (int)(t & 127);
    int s = __ldg(&ei[e]);
    int d = __ldg(&ei[NE + e]);
    float v = g_Mm[(size_t)s * HD + f];
    atomicAdd(&g_aggF[(size_t)d * HD + f], v);
    if (e < NOCP) atomicAdd(&g_aggO[(size_t)d * HD + f], v);
}

// ---------------- D = elu(S+aggF+b) - elu(S+aggO+b) -----------------------------
__global__ void k_D(const float* __restrict__ bg) {
    size_t i = (size_t)blockIdx.x * blockDim.x + threadIdx.x;
    if (i >= (size_t)NN * HD) return;
    int f = (int)(i & 127);
    float base = g_S[i] + bg[f];
    float xf = base + g_aggF[i];
    float xo = base + g_aggO[i];
    g_D[i] = elu1(xf) - elu1(xo);
}

// ---------------- segment softmax remainder -------------------------------------
__global__ void k_ex() {
    __shared__ float ss[NG];
    int tid = threadIdx.x;
    if (tid < NG) ss[tid] = 0.f;
    __syncthreads();
    int e = blockIdx.x * blockDim.x + tid;
    if (e < EA) {
        int g = g_seg[e];
        float v = expf(g_sel[e] - __int_as_float(g_mx[g]));
        g_ex[e] = v;
        atomicAdd(&ss[g], v);
    }
    __syncthreads();
    if (tid < NG && ss[tid] != 0.f) atomicAdd(&g_sum[tid], ss[tid]);
}

__global__ void k_probs(float* __restrict__ out) {
    __shared__ int sp[NG];
    int tid = threadIdx.x;
    if (tid < NG) sp[tid] = 0;
    __syncthreads();
    int e = blockIdx.x * blockDim.x + tid;
    if (e < EA) {
        int g = g_seg[e];
        float p = g_ex[e] / g_sum[g];
        out[e] = p;
        atomicMax(&sp[g], __float_as_int(p));
    }
    __syncthreads();
    if (tid < NG) atomicMax(&g_pm[tid], sp[tid]);
}

__global__ void k_added(const float* __restrict__ out) {
    int e = blockIdx.x * blockDim.x + threadIdx.x;
    if (e >= EA) return;
    int g = g_seg[e];
    if (__float_as_int(out[e]) == g_pm[g]) atomicMin(&g_added[g], e);
}

__global__ void k_tail(float* __restrict__ out) {
    int t = threadIdx.x;
    if (t < NG) {
        out[EA + t]      = __int_as_float(g_pm[t]);
        out[EA + NG + t] = (float)g_added[t];
    }
}

// ---------------- launch ---------------------------------------------------------
extern "C" void kernel_launch(void* const* d_in, const int* in_sizes, int n_in,
                              void* d_out, int out_size) {
    const int pb = n_in - 13;
    const float* x      = (const float*)d_in[0];
    const int*   ei     = (const int*)  d_in[1];
    const int*   bv     = (const int*)  d_in[2];
    const int*   y      = (const int*)  d_in[3];
    const float* W_self = (const float*)d_in[pb + 0];
    const float* W_nbr  = (const float*)d_in[pb + 1];
    const float* b_gnn  = (const float*)d_in[pb + 2];
    const float* Wr1    = (const float*)d_in[pb + 3];
    const float* br1    = (const float*)d_in[pb + 4];
    const float* Wr2    = (const float*)d_in[pb + 5];
    const float* br2    = (const float*)d_in[pb + 6];
    const float* Wr3    = (const float*)d_in[pb + 7];
    const float* br3    = (const float*)d_in[pb + 8];
    const float* Wp1    = (const float*)d_in[pb + 9];
    const float* bp1    = (const float*)d_in[pb + 10];
    const float* Wp2    = (const float*)d_in[pb + 11];
    const float* bp2    = (const float*)d_in[pb + 12];
    float* out = (float*)d_out;

    void *pS, *pM, *pP, *pQ, *pD;
    cudaGetSymbolAddress(&pS, g_S);
    cudaGetSymbolAddress(&pM, g_Mm);
    cudaGetSymbolAddress(&pP, g_P);
    cudaGetSymbolAddress(&pQ, g_Q);
    cudaGetSymbolAddress(&pD, g_D);

    cudaFuncSetAttribute(gemm23_sel, cudaFuncAttributeMaxDynamicSharedMemorySize, DSMEM_G23);
    cudaFuncSetAttribute(tgemm_wide, cudaFuncAttributeMaxDynamicSharedMemorySize, DSMEM_WIDE);

    const int T = 256;

    k_init <<<(NN * HD + T - 1) / T, T>>>();
    k_wc   <<<(256 * 128 + T - 1) / T, T>>>(Wr3, br3, Wp1, bp1);
    k_packc<<<(128 * 128 + T - 1) / T, T>>>();
    k_pack2<<<(256 * 256 + T - 1) / T, T>>>(Wr2);
    k_pack1<<<(128 * 512 + T - 1) / T, T>>>(Wr1);
    k_seg  <<<(EA + T - 1) / T, T>>>(ei, bv, y);

    // node transform GEMMs: S = x@W_self, M = x@W_nbr
    {
        dim3 grid(1, (NN + 127) / 128);
        tgemm<false, false><<<grid, T>>>(x, W_self, nullptr, (float*)pS, NN, HD, HD);
        tgemm<false, false><<<grid, T>>>(x, W_nbr,  nullptr, (float*)pM, NN, HD, HD);
    }
    k_scatter<<<(int)(((long long)NE * HD + T - 1) / T), T>>>(ei);
    k_D<<<(NN * HD + T - 1) / T, T>>>(b_gnn);

    // P = D@Wr1[0:128,:], Q = D@Wr1[128:256,:] (wide tiles, packed B)
    tgemm_wide<<<dim3(2, (NN + 127) / 128, 2), 512, DSMEM_WIDE>>>(
        (const float*)pD, (float*)pP, (float*)pQ, NN);

    // fused GEMM2 + GEMM3 + sel + segment-max
    gemm23_sel<<<EA / 128, 512, DSMEM_G23>>>(
        ei + NOCP, ei + NE + NOCP, (const float*)pP, (const float*)pQ,
        br1, br2, Wp2, bp2);

    // segment softmax + argmax (mx already done in gemm23_sel)
    const int segBlocks = (EA + T - 1) / T;
    k_ex   <<<segBlocks, T>>>();
    k_probs<<<segBlocks, T>>>(out);
    k_added<<<segBlocks, T>>>(out);
    k_tail <<<1, 64>>>(out);
}

// round 9
// speedup vs baseline: 2.5078x; 1.2599x over previous
#include <cuda_runtime.h>
#include <cuda_bf16.h>
#include <cuda_fp16.h>
#include <math.h>
#include <stdint.h>

#define NN   50000
#define NE   262144
#define NOCP 32768
#define EA   (NE - NOCP)      // 229376
#define NG   64
#define HD   128

// ---------------- scratch ----------------------------------------------------
__device__ float g_S   [NN * HD];
__device__ float g_Mm  [NN * HD];
__device__ float g_aggF[NN * HD];
__device__ float g_aggO[NN * HD];
__device__ float g_D   [NN * HD];
__device__ float g_P   [(size_t)NN * 512];
__device__ float g_Q   [(size_t)NN * 512];
__device__ float g_sel [EA];
__device__ float g_ex  [EA];
__device__ int   g_seg [EA];
__device__ int   g_lbl [EA];
__device__ float g_Wc  [256 * 128];
__device__ float g_bc  [128];
__device__ uint32_t g_W2p[256 * 256];   // Wr2 fp16 pairs (kp x 256)
__device__ uint32_t g_Wcp[128 * 128];   // Wc  fp16 pairs (kp x 128)
__device__ uint32_t g_W1p[128 * 512];   // Wr1 fp16 pairs (kp x 512)
__device__ int   g_mx  [NG];
__device__ float g_sum [NG];
__device__ int   g_pm  [NG];
__device__ int   g_added[NG];

// ---------------- helpers -----------------------------------------------------
// bf16 hi/lo split pair (for the x3 node GEMM)
__device__ __forceinline__ void cvt_pair(float f0, float f1, uint32_t& h, uint32_t& l) {
    __nv_bfloat162 H = __floats2bfloat162_rn(f0, f1);
    float2 Hf = __bfloat1622float2(H);
    __nv_bfloat162 L = __floats2bfloat162_rn(f0 - Hf.x, f1 - Hf.y);
    h = *(uint32_t*)&H;
    l = *(uint32_t*)&L;
}
// fp16 single pair
__device__ __forceinline__ uint32_t cvt_h2(float f0, float f1) {
    __half2 H = __floats2half2_rn(f0, f1);
    return *(uint32_t*)&H;
}
// fp16 hi/lo split pair (A-side exact to 22 bits)
__device__ __forceinline__ void cvt_splith(float f0, float f1, uint32_t& h, uint32_t& l) {
    __half2 H = __floats2half2_rn(f0, f1);
    float2 Hf = __half22float2(H);
    __half2 L = __floats2half2_rn(f0 - Hf.x, f1 - Hf.y);
    h = *(uint32_t*)&H;
    l = *(uint32_t*)&L;
}
__device__ __forceinline__ float elu1(float v) { return (v > 0.f) ? v : expm1f(v); }

#define MMA_BF16(d, a, b)                                                     \
    asm volatile(                                                             \
        "mma.sync.aligned.m16n8k16.row.col.f32.bf16.bf16.f32 "                \
        "{%0,%1,%2,%3}, {%4,%5,%6,%7}, {%8,%9}, {%0,%1,%2,%3};\n"             \
        : "+f"((d)[0]), "+f"((d)[1]), "+f"((d)[2]), "+f"((d)[3])              \
        : "r"((a)[0]), "r"((a)[1]), "r"((a)[2]), "r"((a)[3]),                 \
          "r"((b)[0]), "r"((b)[1]))

#define MMA_F16(d, a, b)                                                      \
    asm volatile(                                                             \
        "mma.sync.aligned.m16n8k16.row.col.f32.f16.f16.f32 "                  \
        "{%0,%1,%2,%3}, {%4,%5,%6,%7}, {%8,%9}, {%0,%1,%2,%3};\n"             \
        : "+f"((d)[0]), "+f"((d)[1]), "+f"((d)[2]), "+f"((d)[3])              \
        : "r"((a)[0]), "r"((a)[1]), "r"((a)[2]), "r"((a)[3]),                 \
          "r"((b)[0]), "r"((b)[1]))

__device__ __forceinline__ void atomMaxF(int* a, float v) {
    int iv = __float_as_int(v);
    if (iv >= 0) atomicMax(a, iv);
    else         atomicMin((unsigned int*)a, (unsigned int)iv);
}

// ---------------- init --------------------------------------------------------
__global__ void k_init() {
    size_t i = (size_t)blockIdx.x * blockDim.x + threadIdx.x;
    if (i < (size_t)NN * HD) { g_aggF[i] = 0.f; g_aggO[i] = 0.f; }
    if (blockIdx.x == 0 && threadIdx.x < NG) {
        g_mx[threadIdx.x]    = (int)0xFF800000;
        g_sum[threadIdx.x]   = 0.f;
        g_pm[threadIdx.x]    = 0;
        g_added[threadIdx.x] = EA;
    }
}

// ---------------- Wc = Wr3 @ Wp1, bc = br3 @ Wp1 + bp1 -------------------------
__global__ void k_wc(const float* __restrict__ Wr3, const float* __restrict__ br3,
                     const float* __restrict__ Wp1, const float* __restrict__ bp1) {
    int t = blockIdx.x * blockDim.x + threadIdx.x;
    if (t >= 256 * 128) return;
    int k = t >> 7, c = t & 127;
    float s = 0.f;
    #pragma unroll 8
    for (int m = 0; m < 128; m++) s += Wr3[k * 128 + m] * Wp1[m * 128 + c];
    g_Wc[t] = s;
    if (t < 128) {
        float b = bp1[t];
        #pragma unroll 8
        for (int m = 0; m < 128; m++) b += br3[m] * Wp1[m * 128 + t];
        g_bc[t] = b;
    }
}

// ---------------- pack static B matrices (single fp16 plane) -------------------
__global__ void k_pack2(const float* __restrict__ Wr2) {
    int t = blockIdx.x * blockDim.x + threadIdx.x;
    if (t >= 256 * 256) return;
    int kp = t >> 8, c = t & 255;
    g_W2p[t] = cvt_h2(Wr2[(2 * kp) * 256 + c], Wr2[(2 * kp + 1) * 256 + c]);
}
__global__ void k_packc() {
    int t = blockIdx.x * blockDim.x + threadIdx.x;
    if (t >= 128 * 128) return;
    int kp = t >> 7, c = t & 127;
    g_Wcp[t] = cvt_h2(g_Wc[(2 * kp) * 128 + c], g_Wc[(2 * kp + 1) * 128 + c]);
}
__global__ void k_pack1(const float* __restrict__ Wr1) {
    int t = blockIdx.x * blockDim.x + threadIdx.x;
    if (t >= 128 * 512) return;
    int kp = t >> 9, c = t & 511;
    g_W1p[t] = cvt_h2(Wr1[(2 * kp) * 512 + c], Wr1[(2 * kp + 1) * 512 + c]);
}

// ---------------- per-edge segment / label precompute --------------------------
__global__ void k_seg(const int* __restrict__ ei, const int* __restrict__ bv,
                      const int* __restrict__ y) {
    int e = blockIdx.x * blockDim.x + threadIdx.x;
    if (e >= EA) return;
    int s = __ldg(&ei[NOCP + e]);
    int g = __ldg(&bv[s]);
    g_seg[e] = g;
    g_lbl[e] = __ldg(&y[g]);
}

// =============================================================================
//   BF16x3 dense GEMM (128x128 tile, 256 thr) — S/M node transforms (accurate)
// =============================================================================
#define ASTR 12
#define BSTR 132

template <bool ELU, bool HASBIAS>
__global__ void __launch_bounds__(256)
tgemm(const float* __restrict__ A, const float* __restrict__ B,
      const float* __restrict__ bias, float* __restrict__ C,
      int M, int N, int K) {
    __shared__ uint32_t Ah[2][128][ASTR], Al[2][128][ASTR];
    __shared__ uint32_t Bh[2][8][BSTR],  Bl[2][8][BSTR];

    const int tid = threadIdx.x;
    const int bm = blockIdx.y * 128;
    const int bn = blockIdx.x * 128;

    const int wid = tid >> 5, lane = tid & 31;
    const int gid = lane >> 2, tg = lane & 3;
    const int wm = (wid >> 2) * 64, wn = (wid & 3) * 32;

    const int arow = tid >> 1,  acq = (tid & 1) * 8;
    const int bkp  = tid >> 5,  bnq = (tid & 31) * 4;

    float4 pa0, pa1, pb0, pb1;
    auto loadG = [&](int k0) {
        int gr = bm + arow;
        if (gr < M) {
            pa0 = *(const float4*)&A[(size_t)gr * K + k0 + acq];
            pa1 = *(const float4*)&A[(size_t)gr * K + k0 + acq + 4];
        } else {
            pa0 = make_float4(0.f, 0.f, 0.f, 0.f); pa1 = pa0;
        }
        pb0 = *(const float4*)&B[(size_t)(k0 + 2 * bkp)     * N + bn + bnq];
        pb1 = *(const float4*)&B[(size_t)(k0 + 2 * bkp + 1) * N + bn + bnq];
    };
    auto storeS = [&](int buf) {
        uint32_t h0, h1, h2, h3, l0, l1, l2, l3;
        cvt_pair(pa0.x, pa0.y, h0, l0);
        cvt_pair(pa0.z, pa0.w, h1, l1);
        cvt_pair(pa1.x, pa1.y, h2, l2);
        cvt_pair(pa1.z, pa1.w, h3, l3);
        int kp = acq >> 1;
        *(uint4*)&Ah[buf][arow][kp] = make_uint4(h0, h1, h2, h3);
        *(uint4*)&Al[buf][arow][kp] = make_uint4(l0, l1, l2, l3);
        cvt_pair(pb0.x, pb1.x, h0, l0);
        cvt_pair(pb0.y, pb1.y, h1, l1);
        cvt_pair(pb0.z, pb1.z, h2, l2);
        cvt_pair(pb0.w, pb1.w, h3, l3);
        *(uint4*)&Bh[buf][bkp][bnq] = make_uint4(h0, h1, h2, h3);
        *(uint4*)&Bl[buf][bkp][bnq] = make_uint4(l0, l1, l2, l3);
    };

    float acc[4][4][4];
    #pragma unroll
    for (int i = 0; i < 4; i++)
        #pragma unroll
        for (int j = 0; j < 4; j++)
            #pragma unroll
            for (int r = 0; r < 4; r++) acc[i][j][r] = 0.f;

    loadG(0); storeS(0); __syncthreads();

    const int ntiles = K >> 4;
    for (int t = 0; t < ntiles; t++) {
        const int cur = t & 1;
        if (t + 1 < ntiles) loadG((t + 1) << 4);

        uint32_t ahf[4][4], alf[4][4], bhf[4][2], blf[4][2];
        #pragma unroll
        for (int mt = 0; mt < 4; mt++) {
            int r0 = wm + mt * 16 + gid;
            ahf[mt][0] = Ah[cur][r0    ][tg    ]; alf[mt][0] = Al[cur][r0    ][tg    ];
            ahf[mt][1] = Ah[cur][r0 + 8][tg    ]; alf[mt][1] = Al[cur][r0 + 8][tg    ];
            ahf[mt][2] = Ah[cur][r0    ][tg + 4]; alf[mt][2] = Al[cur][r0    ][tg + 4];
            ahf[mt][3] = Ah[cur][r0 + 8][tg + 4]; alf[mt][3] = Al[cur][r0 + 8][tg + 4];
        }
        #pragma unroll
        for (int nt = 0; nt < 4; nt++) {
            int c = wn + nt * 8 + gid;
            bhf[nt][0] = Bh[cur][tg    ][c]; blf[nt][0] = Bl[cur][tg    ][c];
            bhf[nt][1] = Bh[cur][tg + 4][c]; blf[nt][1] = Bl[cur][tg + 4][c];
        }
        #pragma unroll
        for (int mt = 0; mt < 4; mt++)
            #pragma unroll
            for (int nt = 0; nt < 4; nt++) {
                MMA_BF16(acc[mt][nt], ahf[mt], bhf[nt]);
                MMA_BF16(acc[mt][nt], ahf[mt], blf[nt]);
                MMA_BF16(acc[mt][nt], alf[mt], bhf[nt]);
            }

        if (t + 1 < ntiles) { storeS(cur ^ 1); __syncthreads(); }
    }

    #pragma unroll
    for (int mt = 0; mt < 4; mt++) {
        int r0 = bm + wm + mt * 16 + gid;
        #pragma unroll
        for (int nt = 0; nt < 4; nt++) {
            int c = bn + wn + nt * 8 + tg * 2;
            float b0 = HASBIAS ? __ldg(&bias[c])     : 0.f;
            float b1 = HASBIAS ? __ldg(&bias[c + 1]) : 0.f;
            if (r0 < M) {
                float v0 = acc[mt][nt][0] + b0, v1 = acc[mt][nt][1] + b1;
                if (ELU) { v0 = elu1(v0); v1 = elu1(v1); }
                *(float2*)&C[(size_t)r0 * N + c] = make_float2(v0, v1);
            }
            if (r0 + 8 < M) {
                float v2 = acc[mt][nt][2] + b0, v3 = acc[mt][nt][3] + b1;
                if (ELU) { v2 = elu1(v2); v3 = elu1(v3); }
                *(float2*)&C[(size_t)(r0 + 8) * N + c] = make_float2(v2, v3);
            }
        }
    }
}

// =============================================================================
//  tgemm_wide (FP16x2): dense 128x256 tile, 512 thr, K=128; A=D, B=g_W1p
// =============================================================================
#define DSMEM_WIDE 41216

__global__ void __launch_bounds__(512)
tgemm_wide(const float* __restrict__ A, float* __restrict__ P, float* __restrict__ Q,
           int M) {
    extern __shared__ char dsmw[];
    uint32_t (*Ah)[128][12]  = (uint32_t(*)[128][12])(dsmw);
    uint32_t (*Al)[128][12]  = (uint32_t(*)[128][12])(dsmw + 12288);
    uint32_t (*Bp)[8][260]   = (uint32_t(*)[8][260]) (dsmw + 24576);

    const int tid = threadIdx.x;
    const int bm = blockIdx.y * 128;
    const int bn = blockIdx.x * 256;
    const int kpoff = blockIdx.z * 64;
    float* C = blockIdx.z ? Q : P;

    const int wid = tid >> 5, lane = tid & 31;
    const int gid = lane >> 2, tg = lane & 3;
    const int wr = wid >> 2, wc = wid & 3;

    const int arow = tid >> 2;
    const int af   = (tid & 3) * 4;
    const int akp  = (tid & 3) * 2;
    const int bkp  = tid >> 6;
    const int bc4  = (tid & 63) * 4;

    uint32_t ah0, ah1, al0, al1;
    uint4 pbh;
    auto loadG = [&](int k0) {
        int gr = bm + arow;
        float4 a = (gr < M) ? *(const float4*)&A[(size_t)gr * 128 + k0 + af]
                            : make_float4(0.f, 0.f, 0.f, 0.f);
        cvt_splith(a.x, a.y, ah0, al0);
        cvt_splith(a.z, a.w, ah1, al1);
        int kpg = kpoff + (k0 >> 1) + bkp;
        pbh = *(const uint4*)&g_W1p[kpg * 512 + bn + bc4];
    };
    auto storeS = [&](int buf) {
        Ah[buf][arow][akp]     = ah0;
        Ah[buf][arow][akp + 1] = ah1;
        Al[buf][arow][akp]     = al0;
        Al[buf][arow][akp + 1] = al1;
        *(uint4*)&Bp[buf][bkp][bc4] = pbh;
    };

    float acc[2][8][4];
    #pragma unroll
    for (int i = 0; i < 2; i++)
        #pragma unroll
        for (int j = 0; j < 8; j++)
            #pragma unroll
            for (int r = 0; r < 4; r++) acc[i][j][r] = 0.f;

    loadG(0); storeS(0); __syncthreads();

    for (int t = 0; t < 8; t++) {
        const int cur = t & 1;
        if (t + 1 < 8) loadG((t + 1) << 4);

        uint32_t ahf[2][4], alf[2][4];
        #pragma unroll
        for (int mt = 0; mt < 2; mt++) {
            int r0 = wr * 32 + mt * 16 + gid;
            ahf[mt][0] = Ah[cur][r0    ][tg];     alf[mt][0] = Al[cur][r0    ][tg];
            ahf[mt][1] = Ah[cur][r0 + 8][tg];     alf[mt][1] = Al[cur][r0 + 8][tg];
            ahf[mt][2] = Ah[cur][r0    ][tg + 4]; alf[mt][2] = Al[cur][r0    ][tg + 4];
            ahf[mt][3] = Ah[cur][r0 + 8][tg + 4]; alf[mt][3] = Al[cur][r0 + 8][tg + 4];
        }
        #pragma unroll
        for (int nt = 0; nt < 8; nt++) {
            int c = wc * 64 + nt * 8 + gid;
            uint32_t bh[2];
            bh[0] = Bp[cur][tg][c]; bh[1] = Bp[cur][tg + 4][c];
            #pragma unroll
            for (int mt = 0; mt < 2; mt++) {
                MMA_F16(acc[mt][nt], ahf[mt], bh);
                MMA_F16(acc[mt][nt], alf[mt], bh);
            }
        }
        if (t + 1 < 8) { storeS(cur ^ 1); __syncthreads(); }
    }

    #pragma unroll
    for (int mt = 0; mt < 2; mt++) {
        int ra = bm + wr * 32 + mt * 16 + gid;
        #pragma unroll
        for (int nt = 0; nt < 8; nt++) {
            int c = bn + wc * 64 + nt * 8 + tg * 2;
            if (ra < M)
                *(float2*)&C[(size_t)ra * 512 + c] = make_float2(acc[mt][nt][0], acc[mt][nt][1]);
            if (ra + 8 < M)
                *(float2*)&C[(size_t)(ra + 8) * 512 + c] = make_float2(acc[mt][nt][2], acc[mt][nt][3]);
        }
    }
}

// =============================================================================
//  gemm23_sel (FP16x2): T = elu(elu(P[src]+Q[dst]+br1) @ Wr2 + br2) on-chip,
//  sel = elu(T @ Wc + bc) . Wp2[:,lbl] + bp2; fused segment-max
// =============================================================================
#define DSMEM_G23 176384

__global__ void __launch_bounds__(512)
gemm23_sel(const int* __restrict__ esrc, const int* __restrict__ edst,
           const float* __restrict__ Pm, const float* __restrict__ Qm,
           const float* __restrict__ br1, const float* __restrict__ br2,
           const float* __restrict__ Wp2, const float* __restrict__ bp2) {
    extern __shared__ char dsm[];
    uint32_t (*Th)[132] = (uint32_t(*)[132])(dsm);
    uint32_t (*Tl)[132] = (uint32_t(*)[132])(dsm + 67584);
    char* s1 = dsm + 135168;
    uint32_t (*Ah)[128][12] = (uint32_t(*)[128][12])(s1);
    uint32_t (*Al)[128][12] = (uint32_t(*)[128][12])(s1 + 12288);
    uint32_t (*Bp)[8][260]  = (uint32_t(*)[8][260]) (s1 + 24576);
    uint32_t (*B2p)[8][132] = (uint32_t(*)[8][132]) (s1);          // reuses stage-1 region

    __shared__ float sW[1280];
    __shared__ float sbc[128];
    __shared__ float sbr2[256];
    __shared__ float red[128][4];
    __shared__ int   smx[NG];

    const int tid = threadIdx.x;
    const int bm = blockIdx.x * 128;
    const int wid = tid >> 5, lane = tid & 31;
    const int gid = lane >> 2, tg = lane & 3;
    const int wr = wid >> 2, wc = wid & 3;

    if (tid < 128) sbc[tid] = g_bc[tid];
    if (tid < 256) sbr2[tid] = br2[tid];
    if (tid < NG)  smx[tid] = (int)0xFF800000;
    for (int i = tid; i < 1280; i += 512) sW[i] = Wp2[i];

    // ---------------- stage 1 (K=512, N=256) ----------------
    const int arow = tid >> 2;
    const int af   = (tid & 3) * 4;
    const int akp  = (tid & 3) * 2;
    const int bkp  = tid >> 6;
    const int bc4  = (tid & 63) * 4;

    const int src = __ldg(&esrc[bm + arow]);
    const int dst = __ldg(&edst[bm + arow]);

    uint32_t ah0, ah1, al0, al1;
    uint4 pbh;
    auto loadG1 = [&](int k0) {
        float4 p = *(const float4*)&Pm[(size_t)src * 512 + k0 + af];
        float4 q = *(const float4*)&Qm[(size_t)dst * 512 + k0 + af];
        float4 b = *(const float4*)&br1[k0 + af];
        float e0 = elu1(p.x + q.x + b.x), e1 = elu1(p.y + q.y + b.y);
        float e2 = elu1(p.z + q.z + b.z), e3 = elu1(p.w + q.w + b.w);
        cvt_splith(e0, e1, ah0, al0);
        cvt_splith(e2, e3, ah1, al1);
        int kpg = (k0 >> 1) + bkp;
        pbh = *(const uint4*)&g_W2p[kpg * 256 + bc4];
    };
    auto storeS1 = [&](int buf) {
        Ah[buf][arow][akp]     = ah0;
        Ah[buf][arow][akp + 1] = ah1;
        Al[buf][arow][akp]     = al0;
        Al[buf][arow][akp + 1] = al1;
        *(uint4*)&Bp[buf][bkp][bc4] = pbh;
    };

    float acc[2][8][4];
    #pragma unroll
    for (int i = 0; i < 2; i++)
        #pragma unroll
        for (int j = 0; j < 8; j++)
            #pragma unroll
            for (int r = 0; r < 4; r++) acc[i][j][r] = 0.f;

    loadG1(0); storeS1(0); __syncthreads();

    for (int t = 0; t < 32; t++) {
        const int cur = t & 1;
        if (t + 1 < 32) loadG1((t + 1) << 4);

        uint32_t ahf[2][4], alf[2][4];
        #pragma unroll
        for (int mt = 0; mt < 2; mt++) {
            int r0 = wr * 32 + mt * 16 + gid;
            ahf[mt][0] = Ah[cur][r0    ][tg];     alf[mt][0] = Al[cur][r0    ][tg];
            ahf[mt][1] = Ah[cur][r0 + 8][tg];     alf[mt][1] = Al[cur][r0 + 8][tg];
            ahf[mt][2] = Ah[cur][r0    ][tg + 4]; alf[mt][2] = Al[cur][r0    ][tg + 4];
            ahf[mt][3] = Ah[cur][r0 + 8][tg + 4]; alf[mt][3] = Al[cur][r0 + 8][tg + 4];
        }
        #pragma unroll
        for (int nt = 0; nt < 8; nt++) {
            int c = wc * 64 + nt * 8 + gid;
            uint32_t bh[2];
            bh[0] = Bp[cur][tg][c]; bh[1] = Bp[cur][tg + 4][c];
            #pragma unroll
            for (int mt = 0; mt < 2; mt++) {
                MMA_F16(acc[mt][nt], ahf[mt], bh);
                MMA_F16(acc[mt][nt], alf[mt], bh);
            }
        }
        if (t + 1 < 32) { storeS1(cur ^ 1); __syncthreads(); }
    }

    // pack T = elu(acc + br2) into Th/Tl (fp16 hi/lo pairs)
    #pragma unroll
    for (int mt = 0; mt < 2; mt++) {
        int ra = wr * 32 + mt * 16 + gid, rb = ra + 8;
        #pragma unroll
        for (int nt = 0; nt < 8; nt++) {
            int c = wc * 64 + nt * 8 + tg * 2;
            float e0 = elu1(acc[mt][nt][0] + sbr2[c]);
            float e1 = elu1(acc[mt][nt][1] + sbr2[c + 1]);
            float e2 = elu1(acc[mt][nt][2] + sbr2[c]);
            float e3 = elu1(acc[mt][nt][3] + sbr2[c + 1]);
            uint32_t h, l;
            cvt_splith(e0, e1, h, l); Th[ra][c >> 1] = h; Tl[ra][c >> 1] = l;
            cvt_splith(e2, e3, h, l); Th[rb][c >> 1] = h; Tl[rb][c >> 1] = l;
        }
    }
    __syncthreads();   // T complete; stage-1 buffers free

    // ---------------- stage 2 (K=256, N=128) ----------------
    const int b2kp = tid >> 6;
    const int b2c  = (tid & 63) * 2;

    uint2 qbh;
    auto loadG2 = [&](int s) {
        int kpg = s * 8 + b2kp;
        qbh = *(const uint2*)&g_Wcp[kpg * 128 + b2c];
    };
    auto storeS2 = [&](int buf) {
        *(uint2*)&B2p[buf][b2kp][b2c] = qbh;
    };

    float acc2[2][4][4];
    #pragma unroll
    for (int i = 0; i < 2; i++)
        #pragma unroll
        for (int j = 0; j < 4; j++)
            #pragma unroll
            for (int r = 0; r < 4; r++) acc2[i][j][r] = 0.f;

    loadG2(0); storeS2(0); __syncthreads();

    for (int s = 0; s < 16; s++) {
        const int cur = s & 1;
        if (s + 1 < 16) loadG2(s + 1);

        uint32_t ahf[2][4], alf[2][4];
        const int kb = s * 8;
        #pragma unroll
        for (int mt = 0; mt < 2; mt++) {
            int r0 = wr * 32 + mt * 16 + gid;
            ahf[mt][0] = Th[r0    ][kb + tg];     alf[mt][0] = Tl[r0    ][kb + tg];
            ahf[mt][1] = Th[r0 + 8][kb + tg];     alf[mt][1] = Tl[r0 + 8][kb + tg];
            ahf[mt][2] = Th[r0    ][kb + tg + 4]; alf[mt][2] = Tl[r0    ][kb + tg + 4];
            ahf[mt][3] = Th[r0 + 8][kb + tg + 4]; alf[mt][3] = Tl[r0 + 8][kb + tg + 4];
        }
        #pragma unroll
        for (int nt = 0; nt < 4; nt++) {
            int c = wc * 32 + nt * 8 + gid;
            uint32_t bh[2];
            bh[0] = B2p[cur][tg][c]; bh[1] = B2p[cur][tg + 4][c];
            #pragma unroll
            for (int mt = 0; mt < 2; mt++) {
                MMA_F16(acc2[mt][nt], ahf[mt], bh);
                MMA_F16(acc2[mt][nt], alf[mt], bh);
            }
        }
        if (s + 1 < 16) { storeS2(cur ^ 1); __syncthreads(); }
    }

    // epilogue: h = elu(acc2 + bc); per-row dot with Wp2[:, lbl]
    #pragma unroll
    for (int mt = 0; mt < 2; mt++) {
        int ra = wr * 32 + mt * 16 + gid, rb = ra + 8;
        int lbla = g_lbl[bm + ra], lblb = g_lbl[bm + rb];
        float pa = 0.f, pb = 0.f;
        #pragma unroll
        for (int nt = 0; nt < 4; nt++) {
            int c = wc * 32 + nt * 8 + tg * 2;
            float h;
            h = elu1(acc2[mt][nt][0] + sbc[c]);     pa += h * sW[c * 10 + lbla];
            h = elu1(acc2[mt][nt][1] + sbc[c + 1]); pa += h * sW[(c + 1) * 10 + lbla];
            h = elu1(acc2[mt][nt][2] + sbc[c]);     pb += h * sW[c * 10 + lblb];
            h = elu1(acc2[mt][nt][3] + sbc[c + 1]); pb += h * sW[(c + 1) * 10 + lblb];
        }
        pa += __shfl_xor_sync(0xffffffffu, pa, 1);
        pa += __shfl_xor_sync(0xffffffffu, pa, 2);
        pb += __shfl_xor_sync(0xffffffffu, pb, 1);
        pb += __shfl_xor_sync(0xffffffffu, pb, 2);
        if (tg == 0) { red[ra][wc] = pa; red[rb][wc] = pb; }
    }
    __syncthreads();
    if (tid < 128) {
        float s = red[tid][0] + red[tid][1] + red[tid][2] + red[tid][3]
                + __ldg(&bp2[g_lbl[bm + tid]]);
        g_sel[bm + tid] = s;
        atomMaxF(&smx[g_seg[bm + tid]], s);          // fused segment max
    }
    __syncthreads();
    if (tid < NG) {
        float v = __int_as_float(smx[tid]);
        if (v > -1e37f) atomMaxF(&g_mx[tid], v);
    }
}

// ---------------- edge scatter-add (vector red atomics) -------------------------
__global__ void k_scatter(const int* __restrict__ ei) {
    int t = blockIdx.x * blockDim.x + threadIdx.x;
    if (t >= NE * 32) return;
    int e = t >> 5, v = t & 31;
    int s = __ldg(&ei[e]);
    int d = __ldg(&ei[NE + e]);
    float4 m = *(const float4*)&g_Mm[(size_t)s * HD + v * 4];
    float* dstF = &g_aggF[(size_t)d * HD + v * 4];
    asm volatile("red.global.add.v4.f32 [%0], {%1,%2,%3,%4};"
                 :: "l"(dstF), "f"(m.x), "f"(m.y), "f"(m.z), "f"(m.w) : "memory");
    if (e < NOCP) {
        float* dstO = &g_aggO[(size_t)d * HD + v * 4];
        asm volatile("red.global.add.v4.f32 [%0], {%1,%2,%3,%4};"
                     :: "l"(dstO), "f"(m.x), "f"(m.y), "f"(m.z), "f"(m.w) : "memory");
    }
}

// ---------------- D = elu(S+aggF+b) - elu(S+aggO+b) -----------------------------
__global__ void k_D(const float* __restrict__ bg) {
    size_t i = (size_t)blockIdx.x * blockDim.x + threadIdx.x;
    if (i >= (size_t)NN * HD) return;
    int f = (int)(i & 127);
    float base = g_S[i] + bg[f];
    float xf = base + g_aggF[i];
    float xo = base + g_aggO[i];
    g_D[i] = elu1(xf) - elu1(xo);
}

// ---------------- segment softmax remainder -------------------------------------
__global__ void k_ex() {
    __shared__ float ss[NG];
    int tid = threadIdx.x;
    if (tid < NG) ss[tid] = 0.f;
    __syncthreads();
    int e = blockIdx.x * blockDim.x + tid;
    if (e < EA) {
        int g = g_seg[e];
        float v = expf(g_sel[e] - __int_as_float(g_mx[g]));
        g_ex[e] = v;
        atomicAdd(&ss[g], v);
    }
    __syncthreads();
    if (tid < NG && ss[tid] != 0.f) atomicAdd(&g_sum[tid], ss[tid]);
}

__global__ void k_probs(float* __restrict__ out) {
    __shared__ int sp[NG];
    int tid = threadIdx.x;
    if (tid < NG) sp[tid] = 0;
    __syncthreads();
    int e = blockIdx.x * blockDim.x + tid;
    if (e < EA) {
        int g = g_seg[e];
        float p = g_ex[e] / g_sum[g];
        out[e] = p;
        atomicMax(&sp[g], __float_as_int(p));
    }
    __syncthreads();
    if (tid < NG) atomicMax(&g_pm[tid], sp[tid]);
}

__global__ void k_added(const float* __restrict__ out) {
    int e = blockIdx.x * blockDim.x + threadIdx.x;
    if (e >= EA) return;
    int g = g_seg[e];
    if (__float_as_int(out[e]) == g_pm[g]) atomicMin(&g_added[g], e);
}

__global__ void k_tail(float* __restrict__ out) {
    int t = threadIdx.x;
    if (t < NG) {
        out[EA + t]      = __int_as_float(g_pm[t]);
        out[EA + NG + t] = (float)g_added[t];
    }
}

// ---------------- launch ---------------------------------------------------------
extern "C" void kernel_launch(void* const* d_in, const int* in_sizes, int n_in,
                              void* d_out, int out_size) {
    const int pb = n_in - 13;
    const float* x      = (const float*)d_in[0];
    const int*   ei     = (const int*)  d_in[1];
    const int*   bv     = (const int*)  d_in[2];
    const int*   y      = (const int*)  d_in[3];
    const float* W_self = (const float*)d_in[pb + 0];
    const float* W_nbr  = (const float*)d_in[pb + 1];
    const float* b_gnn  = (const float*)d_in[pb + 2];
    const float* Wr1    = (const float*)d_in[pb + 3];
    const float* br1    = (const float*)d_in[pb + 4];
    const float* Wr2    = (const float*)d_in[pb + 5];
    const float* br2    = (const float*)d_in[pb + 6];
    const float* Wr3    = (const float*)d_in[pb + 7];
    const float* br3    = (const float*)d_in[pb + 8];
    const float* Wp1    = (const float*)d_in[pb + 9];
    const float* bp1    = (const float*)d_in[pb + 10];
    const float* Wp2    = (const float*)d_in[pb + 11];
    const float* bp2    = (const float*)d_in[pb + 12];
    float* out = (float*)d_out;

    void *pS, *pM, *pP, *pQ, *pD;
    cudaGetSymbolAddress(&pS, g_S);
    cudaGetSymbolAddress(&pM, g_Mm);
    cudaGetSymbolAddress(&pP, g_P);
    cudaGetSymbolAddress(&pQ, g_Q);
    cudaGetSymbolAddress(&pD, g_D);

    cudaFuncSetAttribute(gemm23_sel, cudaFuncAttributeMaxDynamicSharedMemorySize, DSMEM_G23);
    cudaFuncSetAttribute(tgemm_wide, cudaFuncAttributeMaxDynamicSharedMemorySize, DSMEM_WIDE);

    const int T = 256;

    k_init <<<(NN * HD + T - 1) / T, T>>>();
    k_wc   <<<(256 * 128 + T - 1) / T, T>>>(Wr3, br3, Wp1, bp1);
    k_packc<<<(128 * 128 + T - 1) / T, T>>>();
    k_pack2<<<(256 * 256 + T - 1) / T, T>>>(Wr2);
    k_pack1<<<(128 * 512 + T - 1) / T, T>>>(Wr1);
    k_seg  <<<(EA + T - 1) / T, T>>>(ei, bv, y);

    // node transform GEMMs: S = x@W_self, M = x@W_nbr (bf16x3, accurate)
    {
        dim3 grid(1, (NN + 127) / 128);
        tgemm<false, false><<<grid, T>>>(x, W_self, nullptr, (float*)pS, NN, HD, HD);
        tgemm<false, false><<<grid, T>>>(x, W_nbr,  nullptr, (float*)pM, NN, HD, HD);
    }
    k_scatter<<<(NE * 32 + T - 1) / T, T>>>(ei);
    k_D<<<(NN * HD + T - 1) / T, T>>>(b_gnn);

    // P = D@Wr1[0:128,:], Q = D@Wr1[128:256,:] (fp16x2)
    tgemm_wide<<<dim3(2, (NN + 127) / 128, 2), 512, DSMEM_WIDE>>>(
        (const float*)pD, (float*)pP, (float*)pQ, NN);

    // fused GEMM2 + GEMM3 + sel + segment-max (fp16x2)
    gemm23_sel<<<EA / 128, 512, DSMEM_G23>>>(
        ei + NOCP, ei + NE + NOCP, (const float*)pP, (const float*)pQ,
        br1, br2, Wp2, bp2);

    // segment softmax + argmax (mx already fused)
    const int segBlocks = (EA + T - 1) / T;
    k_ex   <<<segBlocks, T>>>();
    k_probs<<<segBlocks, T>>>(out);
    k_added<<<segBlocks, T>>>(out);
    k_tail <<<1, 64>>>(out);
}

// round 10
// speedup vs baseline: 2.9035x; 1.1578x over previous
#include <cuda_runtime.h>
#include <cuda_bf16.h>
#include <cuda_fp16.h>
#include <math.h>
#include <stdint.h>

#define NN   50000
#define NE   262144
#define NOCP 32768
#define EA   (NE - NOCP)      // 229376
#define NG   64
#define HD   128

// ---------------- scratch ----------------------------------------------------
__device__ float g_S   [NN * HD];
__device__ float g_Mm  [NN * HD];
__device__ float g_aggR[NN * HD];       // sum over edges [NOCP, NE)
__device__ float g_aggO[NN * HD];       // sum over edges [0, NOCP)
__device__ float g_D   [NN * HD];
__device__ uint32_t g_P16[(size_t)NN * 256];   // P as fp16 pairs
__device__ uint32_t g_Q16[(size_t)NN * 256];   // Q as fp16 pairs
__device__ float g_sel [EA];
__device__ float g_ex  [EA];
__device__ int   g_seg [EA];
__device__ int   g_lbl [EA];
__device__ float g_bc  [128];
__device__ uint32_t g_W2p[256 * 256];   // Wr2 fp16 pairs (kp x 256)
__device__ uint32_t g_Wcp[128 * 128];   // Wc  fp16 pairs (kp x 128)
__device__ uint32_t g_W1p[128 * 512];   // Wr1 fp16 pairs (kp x 512)
__device__ int   g_mx  [NG];
__device__ float g_sum [NG];
__device__ int   g_pm  [NG];
__device__ int   g_added[NG];

// ---------------- helpers -----------------------------------------------------
__device__ __forceinline__ void cvt_pair(float f0, float f1, uint32_t& h, uint32_t& l) {
    __nv_bfloat162 H = __floats2bfloat162_rn(f0, f1);
    float2 Hf = __bfloat1622float2(H);
    __nv_bfloat162 L = __floats2bfloat162_rn(f0 - Hf.x, f1 - Hf.y);
    h = *(uint32_t*)&H;
    l = *(uint32_t*)&L;
}
__device__ __forceinline__ uint32_t cvt_h2(float f0, float f1) {
    __half2 H = __floats2half2_rn(f0, f1);
    return *(uint32_t*)&H;
}
__device__ __forceinline__ void cvt_splith(float f0, float f1, uint32_t& h, uint32_t& l) {
    __half2 H = __floats2half2_rn(f0, f1);
    float2 Hf = __half22float2(H);
    __half2 L = __floats2half2_rn(f0 - Hf.x, f1 - Hf.y);
    h = *(uint32_t*)&H;
    l = *(uint32_t*)&L;
}
__device__ __forceinline__ float2 h2f2(uint32_t u) {
    return __half22float2(*(__half2*)&u);
}
__device__ __forceinline__ float elu1(float v) { return (v > 0.f) ? v : expm1f(v); }

#define MMA_BF16(d, a, b)                                                     \
    asm volatile(                                                             \
        "mma.sync.aligned.m16n8k16.row.col.f32.bf16.bf16.f32 "                \
        "{%0,%1,%2,%3}, {%4,%5,%6,%7}, {%8,%9}, {%0,%1,%2,%3};\n"             \
        : "+f"((d)[0]), "+f"((d)[1]), "+f"((d)[2]), "+f"((d)[3])              \
        : "r"((a)[0]), "r"((a)[1]), "r"((a)[2]), "r"((a)[3]),                 \
          "r"((b)[0]), "r"((b)[1]))

#define MMA_F16(d, a, b)                                                      \
    asm volatile(                                                             \
        "mma.sync.aligned.m16n8k16.row.col.f32.f16.f16.f32 "                  \
        "{%0,%1,%2,%3}, {%4,%5,%6,%7}, {%8,%9}, {%0,%1,%2,%3};\n"             \
        : "+f"((d)[0]), "+f"((d)[1]), "+f"((d)[2]), "+f"((d)[3])              \
        : "r"((a)[0]), "r"((a)[1]), "r"((a)[2]), "r"((a)[3]),                 \
          "r"((b)[0]), "r"((b)[1]))

__device__ __forceinline__ void atomMaxF(int* a, float v) {
    int iv = __float_as_int(v);
    if (iv >= 0) atomicMax(a, iv);
    else         atomicMin((unsigned int*)a, (unsigned int)iv);
}

// ---------------- init (small arrays only; agg arrays via memsetAsync) ---------
__global__ void k_init0() {
    int t = threadIdx.x;
    if (t < NG) {
        g_mx[t]    = (int)0xFF800000;
        g_sum[t]   = 0.f;
        g_pm[t]    = 0;
        g_added[t] = EA;
    }
}

// ---------------- Wc = Wr3 @ Wp1 (packed fp16 pairs), bc = br3@Wp1+bp1 ---------
__global__ void k_wc(const float* __restrict__ Wr3, const float* __restrict__ br3,
                     const float* __restrict__ Wp1, const float* __restrict__ bp1) {
    int t = blockIdx.x * blockDim.x + threadIdx.x;
    if (t >= 128 * 128) return;
    int kp = t >> 7, c = t & 127;
    float s0 = 0.f, s1 = 0.f;
    #pragma unroll 8
    for (int m = 0; m < 128; m++) {
        float w = Wp1[m * 128 + c];
        s0 += Wr3[(2 * kp) * 128 + m] * w;
        s1 += Wr3[(2 * kp + 1) * 128 + m] * w;
    }
    g_Wcp[kp * 128 + c] = cvt_h2(s0, s1);
    if (t < 128) {
        float b = bp1[t];
        #pragma unroll 8
        for (int m = 0; m < 128; m++) b += br3[m] * Wp1[m * 128 + t];
        g_bc[t] = b;
    }
}

// ---------------- pack Wr2 + Wr1 in one launch ----------------------------------
__global__ void k_pack12(const float* __restrict__ Wr2, const float* __restrict__ Wr1) {
    int t = blockIdx.x * blockDim.x + threadIdx.x;
    if (t < 256 * 256) {
        int kp = t >> 8, c = t & 255;
        g_W2p[t] = cvt_h2(Wr2[(2 * kp) * 256 + c], Wr2[(2 * kp + 1) * 256 + c]);
    } else if (t < 256 * 256 + 128 * 512) {
        int t2 = t - 256 * 256;
        int kp = t2 >> 9, c = t2 & 511;
        g_W1p[t2] = cvt_h2(Wr1[(2 * kp) * 512 + c], Wr1[(2 * kp + 1) * 512 + c]);
    }
}

// ---------------- per-edge segment / label precompute ---------------------------
__global__ void k_seg(const int* __restrict__ ei, const int* __restrict__ bv,
                      const int* __restrict__ y) {
    int e = blockIdx.x * blockDim.x + threadIdx.x;
    if (e >= EA) return;
    int s = __ldg(&ei[NOCP + e]);
    int g = __ldg(&bv[s]);
    g_seg[e] = g;
    g_lbl[e] = __ldg(&y[g]);
}

// =============================================================================
//   BF16x3 dense GEMM (128x128 tile, 256 thr) — S/M node transforms (accurate)
//   blockIdx.z selects (B0->C0) or (B1->C1)
// =============================================================================
#define ASTR 12
#define BSTR 132

__global__ void __launch_bounds__(256)
tgemm_sm(const float* __restrict__ A,
         const float* __restrict__ B0, const float* __restrict__ B1,
         float* __restrict__ C0, float* __restrict__ C1, int M) {
    const int N = HD, K = HD;
    const float* B = blockIdx.z ? B1 : B0;
    float* C = blockIdx.z ? C1 : C0;

    __shared__ uint32_t Ah[2][128][ASTR], Al[2][128][ASTR];
    __shared__ uint32_t Bh[2][8][BSTR],  Bl[2][8][BSTR];

    const int tid = threadIdx.x;
    const int bm = blockIdx.y * 128;

    const int wid = tid >> 5, lane = tid & 31;
    const int gid = lane >> 2, tg = lane & 3;
    const int wm = (wid >> 2) * 64, wn = (wid & 3) * 32;

    const int arow = tid >> 1,  acq = (tid & 1) * 8;
    const int bkp  = tid >> 5,  bnq = (tid & 31) * 4;

    float4 pa0, pa1, pb0, pb1;
    auto loadG = [&](int k0) {
        int gr = bm + arow;
        if (gr < M) {
            pa0 = *(const float4*)&A[(size_t)gr * K + k0 + acq];
            pa1 = *(const float4*)&A[(size_t)gr * K + k0 + acq + 4];
        } else {
            pa0 = make_float4(0.f, 0.f, 0.f, 0.f); pa1 = pa0;
        }
        pb0 = *(const float4*)&B[(size_t)(k0 + 2 * bkp)     * N + bnq];
        pb1 = *(const float4*)&B[(size_t)(k0 + 2 * bkp + 1) * N + bnq];
    };
    auto storeS = [&](int buf) {
        uint32_t h0, h1, h2, h3, l0, l1, l2, l3;
        cvt_pair(pa0.x, pa0.y, h0, l0);
        cvt_pair(pa0.z, pa0.w, h1, l1);
        cvt_pair(pa1.x, pa1.y, h2, l2);
        cvt_pair(pa1.z, pa1.w, h3, l3);
        int kp = acq >> 1;
        *(uint4*)&Ah[buf][arow][kp] = make_uint4(h0, h1, h2, h3);
        *(uint4*)&Al[buf][arow][kp] = make_uint4(l0, l1, l2, l3);
        cvt_pair(pb0.x, pb1.x, h0, l0);
        cvt_pair(pb0.y, pb1.y, h1, l1);
        cvt_pair(pb0.z, pb1.z, h2, l2);
        cvt_pair(pb0.w, pb1.w, h3, l3);
        *(uint4*)&Bh[buf][bkp][bnq] = make_uint4(h0, h1, h2, h3);
        *(uint4*)&Bl[buf][bkp][bnq] = make_uint4(l0, l1, l2, l3);
    };

    float acc[4][4][4];
    #pragma unroll
    for (int i = 0; i < 4; i++)
        #pragma unroll
        for (int j = 0; j < 4; j++)
            #pragma unroll
            for (int r = 0; r < 4; r++) acc[i][j][r] = 0.f;

    loadG(0); storeS(0); __syncthreads();

    const int ntiles = K >> 4;
    for (int t = 0; t < ntiles; t++) {
        const int cur = t & 1;
        if (t + 1 < ntiles) loadG((t + 1) << 4);

        uint32_t ahf[4][4], alf[4][4], bhf[4][2], blf[4][2];
        #pragma unroll
        for (int mt = 0; mt < 4; mt++) {
            int r0 = wm + mt * 16 + gid;
            ahf[mt][0] = Ah[cur][r0    ][tg    ]; alf[mt][0] = Al[cur][r0    ][tg    ];
            ahf[mt][1] = Ah[cur][r0 + 8][tg    ]; alf[mt][1] = Al[cur][r0 + 8][tg    ];
            ahf[mt][2] = Ah[cur][r0    ][tg + 4]; alf[mt][2] = Al[cur][r0    ][tg + 4];
            ahf[mt][3] = Ah[cur][r0 + 8][tg + 4]; alf[mt][3] = Al[cur][r0 + 8][tg + 4];
        }
        #pragma unroll
        for (int nt = 0; nt < 4; nt++) {
            int c = wn + nt * 8 + gid;
            bhf[nt][0] = Bh[cur][tg    ][c]; blf[nt][0] = Bl[cur][tg    ][c];
            bhf[nt][1] = Bh[cur][tg + 4][c]; blf[nt][1] = Bl[cur][tg + 4][c];
        }
        #pragma unroll
        for (int mt = 0; mt < 4; mt++)
            #pragma unroll
            for (int nt = 0; nt < 4; nt++) {
                MMA_BF16(acc[mt][nt], ahf[mt], bhf[nt]);
                MMA_BF16(acc[mt][nt], ahf[mt], blf[nt]);
                MMA_BF16(acc[mt][nt], alf[mt], bhf[nt]);
            }

        if (t + 1 < ntiles) { storeS(cur ^ 1); __syncthreads(); }
    }

    #pragma unroll
    for (int mt = 0; mt < 4; mt++) {
        int r0 = bm + wm + mt * 16 + gid;
        #pragma unroll
        for (int nt = 0; nt < 4; nt++) {
            int c = wn + nt * 8 + tg * 2;
            if (r0 < M)
                *(float2*)&C[(size_t)r0 * N + c] = make_float2(acc[mt][nt][0], acc[mt][nt][1]);
            if (r0 + 8 < M)
                *(float2*)&C[(size_t)(r0 + 8) * N + c] = make_float2(acc[mt][nt][2], acc[mt][nt][3]);
        }
    }
}

// =============================================================================
//  tgemm_wide (FP16x2): 128x256 tile, 512 thr, K=128; writes fp16 pairs P16/Q16
// =============================================================================
#define DSMEM_WIDE 41216

__global__ void __launch_bounds__(512)
tgemm_wide(const float* __restrict__ A, uint32_t* __restrict__ P16,
           uint32_t* __restrict__ Q16, int M) {
    extern __shared__ char dsmw[];
    uint32_t (*Ah)[128][12]  = (uint32_t(*)[128][12])(dsmw);
    uint32_t (*Al)[128][12]  = (uint32_t(*)[128][12])(dsmw + 12288);
    uint32_t (*Bp)[8][260]   = (uint32_t(*)[8][260]) (dsmw + 24576);

    const int tid = threadIdx.x;
    const int bm = blockIdx.y * 128;
    const int bn = blockIdx.x * 256;
    const int kpoff = blockIdx.z * 64;
    uint32_t* C16 = blockIdx.z ? Q16 : P16;

    const int wid = tid >> 5, lane = tid & 31;
    const int gid = lane >> 2, tg = lane & 3;
    const int wr = wid >> 2, wc = wid & 3;

    const int arow = tid >> 2;
    const int af   = (tid & 3) * 4;
    const int akp  = (tid & 3) * 2;
    const int bkp  = tid >> 6;
    const int bc4  = (tid & 63) * 4;

    uint32_t ah0, ah1, al0, al1;
    uint4 pbh;
    auto loadG = [&](int k0) {
        int gr = bm + arow;
        float4 a = (gr < M) ? *(const float4*)&A[(size_t)gr * 128 + k0 + af]
                            : make_float4(0.f, 0.f, 0.f, 0.f);
        cvt_splith(a.x, a.y, ah0, al0);
        cvt_splith(a.z, a.w, ah1, al1);
        int kpg = kpoff + (k0 >> 1) + bkp;
        pbh = *(const uint4*)&g_W1p[kpg * 512 + bn + bc4];
    };
    auto storeS = [&](int buf) {
        Ah[buf][arow][akp]     = ah0;
        Ah[buf][arow][akp + 1] = ah1;
        Al[buf][arow][akp]     = al0;
        Al[buf][arow][akp + 1] = al1;
        *(uint4*)&Bp[buf][bkp][bc4] = pbh;
    };

    float acc[2][8][4];
    #pragma unroll
    for (int i = 0; i < 2; i++)
        #pragma unroll
        for (int j = 0; j < 8; j++)
            #pragma unroll
            for (int r = 0; r < 4; r++) acc[i][j][r] = 0.f;

    loadG(0); storeS(0); __syncthreads();

    for (int t = 0; t < 8; t++) {
        const int cur = t & 1;
        if (t + 1 < 8) loadG((t + 1) << 4);

        uint32_t ahf[2][4], alf[2][4];
        #pragma unroll
        for (int mt = 0; mt < 2; mt++) {
            int r0 = wr * 32 + mt * 16 + gid;
            ahf[mt][0] = Ah[cur][r0    ][tg];     alf[mt][0] = Al[cur][r0    ][tg];
            ahf[mt][1] = Ah[cur][r0 + 8][tg];     alf[mt][1] = Al[cur][r0 + 8][tg];
            ahf[mt][2] = Ah[cur][r0    ][tg + 4]; alf[mt][2] = Al[cur][r0    ][tg + 4];
            ahf[mt][3] = Ah[cur][r0 + 8][tg + 4]; alf[mt][3] = Al[cur][r0 + 8][tg + 4];
        }
        #pragma unroll
        for (int nt = 0; nt < 8; nt++) {
            int c = wc * 64 + nt * 8 + gid;
            uint32_t bh[2];
            bh[0] = Bp[cur][tg][c]; bh[1] = Bp[cur][tg + 4][c];
            #pragma unroll
            for (int mt = 0; mt < 2; mt++) {
                MMA_F16(acc[mt][nt], ahf[mt], bh);
                MMA_F16(acc[mt][nt], alf[mt], bh);
            }
        }
        if (t + 1 < 8) { storeS(cur ^ 1); __syncthreads(); }
    }

    #pragma unroll
    for (int mt = 0; mt < 2; mt++) {
        int ra = bm + wr * 32 + mt * 16 + gid;
        #pragma unroll
        for (int nt = 0; nt < 8; nt++) {
            int c = bn + wc * 64 + nt * 8 + tg * 2;
            if (ra < M)
                C16[(size_t)ra * 256 + (c >> 1)] = cvt_h2(acc[mt][nt][0], acc[mt][nt][1]);
            if (ra + 8 < M)
                C16[(size_t)(ra + 8) * 256 + (c >> 1)] = cvt_h2(acc[mt][nt][2], acc[mt][nt][3]);
        }
    }
}

// =============================================================================
//  gemm23_sel: stage1 A single fp16 plane (P/Q fp16), stage2 T hi/lo split.
// =============================================================================
#define DSMEM_G23 164096

__global__ void __launch_bounds__(512)
gemm23_sel(const int* __restrict__ esrc, const int* __restrict__ edst,
           const uint32_t* __restrict__ Pm, const uint32_t* __restrict__ Qm,
           const float* __restrict__ br1, const float* __restrict__ br2,
           const float* __restrict__ Wp2, const float* __restrict__ bp2) {
    extern __shared__ char dsm[];
    uint32_t (*Th)[132] = (uint32_t(*)[132])(dsm);
    uint32_t (*Tl)[132] = (uint32_t(*)[132])(dsm + 67584);
    char* s1 = dsm + 135168;
    uint32_t (*Ah)[128][12] = (uint32_t(*)[128][12])(s1);
    uint32_t (*Bp)[8][260]  = (uint32_t(*)[8][260]) (s1 + 12288);
    uint32_t (*B2p)[8][132] = (uint32_t(*)[8][132]) (s1);          // reuses stage-1 region

    __shared__ float sW[1280];
    __shared__ float sbc[128];
    __shared__ float sbr1[512];
    __shared__ float sbr2[256];
    __shared__ float red[128][4];
    __shared__ int   smx[NG];

    const int tid = threadIdx.x;
    const int bm = blockIdx.x * 128;
    const int wid = tid >> 5, lane = tid & 31;
    const int gid = lane >> 2, tg = lane & 3;
    const int wr = wid >> 2, wc = wid & 3;

    if (tid < 128) sbc[tid] = g_bc[tid];
    if (tid < 256) sbr2[tid] = br2[tid];
    if (tid < NG)  smx[tid] = (int)0xFF800000;
    sbr1[tid] = br1[tid];
    for (int i = tid; i < 1280; i += 512) sW[i] = Wp2[i];

    // ---------------- stage 1 (K=512, N=256), A single-plane fp16 ----------------
    const int arow = tid >> 2;
    const int akp  = (tid & 3) * 2;
    const int bkp  = tid >> 6;
    const int bc4  = (tid & 63) * 4;

    const int src = __ldg(&esrc[bm + arow]);
    const int dst = __ldg(&edst[bm + arow]);

    uint32_t ah0, ah1;
    uint4 pbh;
    auto loadG1 = [&](int k0) {
        int kp0 = (k0 >> 1) + (tid & 3) * 2;
        uint2 pp = *(const uint2*)&Pm[(size_t)src * 256 + kp0];
        uint2 qq = *(const uint2*)&Qm[(size_t)dst * 256 + kp0];
        float2 p0 = h2f2(pp.x), p1 = h2f2(pp.y);
        float2 q0 = h2f2(qq.x), q1 = h2f2(qq.y);
        int kb = k0 + (tid & 3) * 4;
        float e0 = elu1(p0.x + q0.x + sbr1[kb]);
        float e1 = elu1(p0.y + q0.y + sbr1[kb + 1]);
        float e2 = elu1(p1.x + q1.x + sbr1[kb + 2]);
        float e3 = elu1(p1.y + q1.y + sbr1[kb + 3]);
        ah0 = cvt_h2(e0, e1);
        ah1 = cvt_h2(e2, e3);
        int kpg = (k0 >> 1) + bkp;
        pbh = *(const uint4*)&g_W2p[kpg * 256 + bc4];
    };
    auto storeS1 = [&](int buf) {
        Ah[buf][arow][akp]     = ah0;
        Ah[buf][arow][akp + 1] = ah1;
        *(uint4*)&Bp[buf][bkp][bc4] = pbh;
    };

    float acc[2][8][4];
    #pragma unroll
    for (int i = 0; i < 2; i++)
        #pragma unroll
        for (int j = 0; j < 8; j++)
            #pragma unroll
            for (int r = 0; r < 4; r++) acc[i][j][r] = 0.f;

    loadG1(0); storeS1(0); __syncthreads();

    for (int t = 0; t < 32; t++) {
        const int cur = t & 1;
        if (t + 1 < 32) loadG1((t + 1) << 4);

        uint32_t ahf[2][4];
        #pragma unroll
        for (int mt = 0; mt < 2; mt++) {
            int r0 = wr * 32 + mt * 16 + gid;
            ahf[mt][0] = Ah[cur][r0    ][tg];
            ahf[mt][1] = Ah[cur][r0 + 8][tg];
            ahf[mt][2] = Ah[cur][r0    ][tg + 4];
            ahf[mt][3] = Ah[cur][r0 + 8][tg + 4];
        }
        #pragma unroll
        for (int nt = 0; nt < 8; nt++) {
            int c = wc * 64 + nt * 8 + gid;
            uint32_t bh[2];
            bh[0] = Bp[cur][tg][c]; bh[1] = Bp[cur][tg + 4][c];
            #pragma unroll
            for (int mt = 0; mt < 2; mt++)
                MMA_F16(acc[mt][nt], ahf[mt], bh);
        }
        if (t + 1 < 32) { storeS1(cur ^ 1); __syncthreads(); }
    }

    // pack T = elu(acc + br2) into Th/Tl (fp16 hi/lo pairs)
    #pragma unroll
    for (int mt = 0; mt < 2; mt++) {
        int ra = wr * 32 + mt * 16 + gid, rb = ra + 8;
        #pragma unroll
        for (int nt = 0; nt < 8; nt++) {
            int c = wc * 64 + nt * 8 + tg * 2;
            float e0 = elu1(acc[mt][nt][0] + sbr2[c]);
            float e1 = elu1(acc[mt][nt][1] + sbr2[c + 1]);
            float e2 = elu1(acc[mt][nt][2] + sbr2[c]);
            float e3 = elu1(acc[mt][nt][3] + sbr2[c + 1]);
            uint32_t h, l;
            cvt_splith(e0, e1, h, l); Th[ra][c >> 1] = h; Tl[ra][c >> 1] = l;
            cvt_splith(e2, e3, h, l); Th[rb][c >> 1] = h; Tl[rb][c >> 1] = l;
        }
    }
    __syncthreads();   // T complete; stage-1 buffers free

    // ---------------- stage 2 (K=256, N=128) ----------------
    const int b2kp = tid >> 6;
    const int b2c  = (tid & 63) * 2;

    uint2 qbh;
    auto loadG2 = [&](int s) {
        int kpg = s * 8 + b2kp;
        qbh = *(const uint2*)&g_Wcp[kpg * 128 + b2c];
    };
    auto storeS2 = [&](int buf) {
        *(uint2*)&B2p[buf][b2kp][b2c] = qbh;
    };

    float acc2[2][4][4];
    #pragma unroll
    for (int i = 0; i < 2; i++)
        #pragma unroll
        for (int j = 0; j < 4; j++)
            #pragma unroll
            for (int r = 0; r < 4; r++) acc2[i][j][r] = 0.f;

    loadG2(0); storeS2(0); __syncthreads();

    for (int s = 0; s < 16; s++) {
        const int cur = s & 1;
        if (s + 1 < 16) loadG2(s + 1);

        uint32_t ahf[2][4], alf[2][4];
        const int kb = s * 8;
        #pragma unroll
        for (int mt = 0; mt < 2; mt++) {
            int r0 = wr * 32 + mt * 16 + gid;
            ahf[mt][0] = Th[r0    ][kb + tg];     alf[mt][0] = Tl[r0    ][kb + tg];
            ahf[mt][1] = Th[r0 + 8][kb + tg];     alf[mt][1] = Tl[r0 + 8][kb + tg];
            ahf[mt][2] = Th[r0    ][kb + tg + 4]; alf[mt][2] = Tl[r0    ][kb + tg + 4];
            ahf[mt][3] = Th[r0 + 8][kb + tg + 4]; alf[mt][3] = Tl[r0 + 8][kb + tg + 4];
        }
        #pragma unroll
        for (int nt = 0; nt < 4; nt++) {
            int c = wc * 32 + nt * 8 + gid;
            uint32_t bh[2];
            bh[0] = B2p[cur][tg][c]; bh[1] = B2p[cur][tg + 4][c];
            #pragma unroll
            for (int mt = 0; mt < 2; mt++) {
                MMA_F16(acc2[mt][nt], ahf[mt], bh);
                MMA_F16(acc2[mt][nt], alf[mt], bh);
            }
        }
        if (s + 1 < 16) { storeS2(cur ^ 1); __syncthreads(); }
    }

    // epilogue: h = elu(acc2 + bc); per-row dot with Wp2[:, lbl]
    #pragma unroll
    for (int mt = 0; mt < 2; mt++) {
        int ra = wr * 32 + mt * 16 + gid, rb = ra + 8;
        int lbla = g_lbl[bm + ra], lblb = g_lbl[bm + rb];
        float pa = 0.f, pb = 0.f;
        #pragma unroll
        for (int nt = 0; nt < 4; nt++) {
            int c = wc * 32 + nt * 8 + tg * 2;
            float h;
            h = elu1(acc2[mt][nt][0] + sbc[c]);     pa += h * sW[c * 10 + lbla];
            h = elu1(acc2[mt][nt][1] + sbc[c + 1]); pa += h * sW[(c + 1) * 10 + lbla];
            h = elu1(acc2[mt][nt][2] + sbc[c]);     pb += h * sW[c * 10 + lblb];
            h = elu1(acc2[mt][nt][3] + sbc[c + 1]); pb += h * sW[(c + 1) * 10 + lblb];
        }
        pa += __shfl_xor_sync(0xffffffffu, pa, 1);
        pa += __shfl_xor_sync(0xffffffffu, pa, 2);
        pb += __shfl_xor_sync(0xffffffffu, pb, 1);
        pb += __shfl_xor_sync(0xffffffffu, pb, 2);
        if (tg == 0) { red[ra][wc] = pa; red[rb][wc] = pb; }
    }
    __syncthreads();
    if (tid < 128) {
        float s = red[tid][0] + red[tid][1] + red[tid][2] + red[tid][3]
                + __ldg(&bp2[g_lbl[bm + tid]]);
        g_sel[bm + tid] = s;
        atomMaxF(&smx[g_seg[bm + tid]], s);
    }
    __syncthreads();
    if (tid < NG) {
        float v = __int_as_float(smx[tid]);
        if (v > -1e37f) atomMaxF(&g_mx[tid], v);
    }
}

// ---------------- edge scatter-add (one red.v4 per edge-lane) --------------------
__global__ void k_scatter(const int* __restrict__ ei) {
    int t = blockIdx.x * blockDim.x + threadIdx.x;
    if (t >= NE * 32) return;
    int e = t >> 5, v = t & 31;
    int s = __ldg(&ei[e]);
    int d = __ldg(&ei[NE + e]);
    float4 m = *(const float4*)&g_Mm[(size_t)s * HD + v * 4];
    float* dst4 = (e < NOCP) ? &g_aggO[(size_t)d * HD + v * 4]
                             : &g_aggR[(size_t)d * HD + v * 4];
    asm volatile("red.global.add.v4.f32 [%0], {%1,%2,%3,%4};"
                 :: "l"(dst4), "f"(m.x), "f"(m.y), "f"(m.z), "f"(m.w) : "memory");
}

// ---------------- D = elu(S+aggO+aggR+b) - elu(S+aggO+b) -------------------------
__global__ void k_D(const float* __restrict__ bg) {
    size_t i = (size_t)blockIdx.x * blockDim.x + threadIdx.x;
    if (i >= (size_t)NN * HD) return;
    int f = (int)(i & 127);
    float ao = g_aggO[i], ar = g_aggR[i];
    float base = g_S[i] + bg[f] + ao;
    g_D[i] = elu1(base + ar) - elu1(base);
}

// ---------------- segment softmax remainder --------------------------------------
__global__ void k_ex() {
    __shared__ float ss[NG];
    int tid = threadIdx.x;
    if (tid < NG) ss[tid] = 0.f;
    __syncthreads();
    int e = blockIdx.x * blockDim.x + tid;
    if (e < EA) {
        int g = g_seg[e];
        float v = expf(g_sel[e] - __int_as_float(g_mx[g]));
        g_ex[e] = v;
        atomicAdd(&ss[g], v);
    }
    __syncthreads();
    if (tid < NG && ss[tid] != 0.f) atomicAdd(&g_sum[tid], ss[tid]);
}

__global__ void k_probs(float* __restrict__ out) {
    __shared__ int sp[NG];
    int tid = threadIdx.x;
    if (tid < NG) sp[tid] = 0;
    __syncthreads();
    int e = blockIdx.x * blockDim.x + tid;
    if (e < EA) {
        int g = g_seg[e];
        float p = g_ex[e] / g_sum[g];
        out[e] = p;
        atomicMax(&sp[g], __float_as_int(p));
    }
    __syncthreads();
    if (tid < NG) atomicMax(&g_pm[tid], sp[tid]);
}

__global__ void k_added(const float* __restrict__ out) {
    int e = blockIdx.x * blockDim.x + threadIdx.x;
    if (e >= EA) return;
    int g = g_seg[e];
    if (__float_as_int(out[e]) == g_pm[g]) atomicMin(&g_added[g], e);
}

__global__ void k_tail(float* __restrict__ out) {
    int t = threadIdx.x;
    if (t < NG) {
        out[EA + t]      = __int_as_float(g_pm[t]);
        out[EA + NG + t] = (float)g_added[t];
    }
}

// ---------------- launch ----------------------------------------------------------
extern "C" void kernel_launch(void* const* d_in, const int* in_sizes, int n_in,
                              void* d_out, int out_size) {
    const int pb = n_in - 13;
    const float* x      = (const float*)d_in[0];
    const int*   ei     = (const int*)  d_in[1];
    const int*   bv     = (const int*)  d_in[2];
    const int*   y      = (const int*)  d_in[3];
    const float* W_self = (const float*)d_in[pb + 0];
    const float* W_nbr  = (const float*)d_in[pb + 1];
    const float* b_gnn  = (const float*)d_in[pb + 2];
    const float* Wr1    = (const float*)d_in[pb + 3];
    const float* br1    = (const float*)d_in[pb + 4];
    const float* Wr2    = (const float*)d_in[pb + 5];
    const float* br2    = (const float*)d_in[pb + 6];
    const float* Wr3    = (const float*)d_in[pb + 7];
    const float* br3    = (const float*)d_in[pb + 8];
    const float* Wp1    = (const float*)d_in[pb + 9];
    const float* bp1    = (const float*)d_in[pb + 10];
    const float* Wp2    = (const float*)d_in[pb + 11];
    const float* bp2    = (const float*)d_in[pb + 12];
    float* out = (float*)d_out;

    void *pS, *pM, *pP, *pQ, *pD, *pAR, *pAO;
    cudaGetSymbolAddress(&pS,  g_S);
    cudaGetSymbolAddress(&pM,  g_Mm);
    cudaGetSymbolAddress(&pP,  g_P16);
    cudaGetSymbolAddress(&pQ,  g_Q16);
    cudaGetSymbolAddress(&pD,  g_D);
    cudaGetSymbolAddress(&pAR, g_aggR);
    cudaGetSymbolAddress(&pAO, g_aggO);

    cudaFuncSetAttribute(gemm23_sel, cudaFuncAttributeMaxDynamicSharedMemorySize, DSMEM_G23);
    cudaFuncSetAttribute(tgemm_wide, cudaFuncAttributeMaxDynamicSharedMemorySize, DSMEM_WIDE);

    const int T = 256;

    cudaMemsetAsync(pAR, 0, (size_t)NN * HD * sizeof(float));
    cudaMemsetAsync(pAO, 0, (size_t)NN * HD * sizeof(float));
    k_init0 <<<1, 64>>>();
    k_wc    <<<(128 * 128 + T - 1) / T, T>>>(Wr3, br3, Wp1, bp1);
    k_pack12<<<(256 * 256 + 128 * 512 + T - 1) / T, T>>>(Wr2, Wr1);
    k_seg   <<<(EA + T - 1) / T, T>>>(ei, bv, y);

    // node transform GEMMs: S = x@W_self, M = x@W_nbr (one launch, z-select)
    tgemm_sm<<<dim3(1, (NN + 127) / 128, 2), T>>>(x, W_self, W_nbr,
                                                  (float*)pS, (float*)pM, NN);

    k_scatter<<<(NE * 32 + T - 1) / T, T>>>(ei);
    k_D<<<(NN * HD + T - 1) / T, T>>>(b_gnn);

    // P = D@Wr1[0:128,:], Q = D@Wr1[128:256,:]  (fp16x2, fp16-pair outputs)
    tgemm_wide<<<dim3(2, (NN + 127) / 128, 2), 512, DSMEM_WIDE>>>(
        (const float*)pD, (uint32_t*)pP, (uint32_t*)pQ, NN);

    // fused GEMM2 + GEMM3 + sel + segment-max
    gemm23_sel<<<EA / 128, 512, DSMEM_G23>>>(
        ei + NOCP, ei + NE + NOCP, (const uint32_t*)pP, (const uint32_t*)pQ,
        br1, br2, Wp2, bp2);

    // segment softmax + argmax
    const int segBlocks = (EA + T - 1) / T;
    k_ex   <<<segBlocks, T>>>();
    k_probs<<<segBlocks, T>>>(out);
    k_added<<<segBlocks, T>>>(out);
    k_tail <<<1, 64>>>(out);
}